// round 13
// baseline (speedup 1.0000x reference)
#include <cuda_runtime.h>
#include <cuda_bf16.h>
#include <math.h>

#define BB 8
#define TT 32
#define CC 1024
#define HH 128
#define DST 32
#define FIN 64
#define SS 27            // T - INIT_LENGTH - 1
#define NT 31            // scan steps
#define ROWS (BB*CC)     // 8192

// ================= warp-MMA helpers =================
__device__ __forceinline__ unsigned smem_u32(const void* p){
    unsigned a;
    asm("{ .reg .u64 t; cvta.to.shared.u64 t, %1; cvt.u32.u64 %0, t; }" : "=r"(a) : "l"(p));
    return a;
}

__device__ __forceinline__ void ldsm4(unsigned& r0, unsigned& r1, unsigned& r2, unsigned& r3,
                                      unsigned addr){
    asm volatile("ldmatrix.sync.aligned.m8n8.x4.shared.b16 {%0,%1,%2,%3}, [%4];"
                 : "=r"(r0), "=r"(r1), "=r"(r2), "=r"(r3) : "r"(addr));
}

__device__ __forceinline__ void mma16816(float* c, const unsigned* a, unsigned b0, unsigned b1){
    asm volatile("mma.sync.aligned.m16n8k16.row.col.f32.bf16.bf16.f32 "
                 "{%0,%1,%2,%3}, {%4,%5,%6,%7}, {%8,%9}, {%0,%1,%2,%3};"
                 : "+f"(c[0]), "+f"(c[1]), "+f"(c[2]), "+f"(c[3])
                 : "r"(a[0]), "r"(a[1]), "r"(a[2]), "r"(a[3]), "r"(b0), "r"(b1));
}

__device__ __forceinline__ void cp16(unsigned dst, const void* src){
    asm volatile("cp.async.cg.shared.global [%0], [%1], 16;"
                 :: "r"(dst), "l"(__cvta_generic_to_global(src)));
}
#define CP_COMMIT() asm volatile("cp.async.commit_group;" ::: "memory")
#define CP_WAIT0()  asm volatile("cp.async.wait_group 0;" ::: "memory")

__device__ __forceinline__ unsigned swz(unsigned boff){
    return boff ^ ((boff >> 3) & 0x70);
}

// load rows x K bf16 matrix into k-panel smem layout (panel = 64 k, swizzled 128B rows)
template<int RM, int KD>
__device__ __forceinline__ void load_mat(unsigned dst, const __nv_bfloat16* src, int ld, int tid){
    constexpr int UPR = KD/8;
    constexpr int UNITS = RM*UPR;
    for (int u = tid; u < UNITS; u += 256){
        int row = u / UPR, k8 = u % UPR;
        int kp = k8 >> 3, kc8 = k8 & 7;
        cp16(dst + kp*(RM*128) + swz(row*128 + kc8*16),
             src + (size_t)row*ld + kp*64 + kc8*8);
    }
}

// ---------------- device scratch ----------------
__device__ __nv_bfloat16 g_Lf[(size_t)TT*CC*CC];
__device__ __nv_bfloat16 g_Lb[(size_t)TT*CC*CC];
__device__ __nv_bfloat16 g_BX[(size_t)BB*TT*FIN*CC];   // [b][t][f][c]
__device__ __nv_bfloat16 g_BHWf[(size_t)BB*HH*CC];     // (h@Wfwd)^T [b][f][c]
__device__ __nv_bfloat16 g_BHWb[(size_t)BB*HH*CC];     // (h@Wbwd)^T [b][f][c]

__device__ __nv_bfloat16 g_Zxf[(size_t)NT*ROWS*64];
__device__ __nv_bfloat16 g_Zxb[(size_t)NT*ROWS*64];
__device__ __nv_bfloat16 g_tmp[(size_t)NT*ROWS*64];
__device__ __nv_bfloat16 g_gi_all[(size_t)NT*ROWS*384];
__device__ __nv_bfloat16 g_gcat[(size_t)ROWS*256];
__device__ float         g_hsf[(size_t)ROWS*HH];
__device__ float         g_gh[(size_t)ROWS*384];
__device__ float         g_hist[(size_t)SS*ROWS*HH];
__device__ float         g_h[(size_t)ROWS*HH];
__device__ float         g_dinvf[TT*CC];
__device__ float         g_dinvb[TT*CC];
__device__ int           g_mask[CC];

// weights bf16 [N][K]
__device__ __nv_bfloat16 g_Winit[128*64];
__device__ __nv_bfloat16 g_WfeF[32*64];
__device__ __nv_bfloat16 g_WfeB[32*64];
__device__ __nv_bfloat16 g_Wfb[256*128];     // rows 0..127 = Wfwd^T, 128..255 = Wbwd^T
__device__ __nv_bfloat16 g_Wmerge[128*256];
__device__ __nv_bfloat16 g_Wmh[384*256];     // (Wmerge @ Whh)^T, bf16 [N][K]
__device__ __nv_bfloat16 g_Wih[384*64];
__device__ float         g_bias2[384];       // bm @ Whh + bhh

#define OFF_INIT  0
#define OFF_FEF   128
#define OFF_FEB   160
#define OFF_FWD   192
#define OFF_BWD   320
#define OFF_MERGE 448
#define OFF_BIH   576
__device__ float g_bias[960];

// ---------------- prolog kernels ----------------
__global__ void rowsum_kernel(const float* __restrict__ adj){
    int warp = (blockIdx.x*blockDim.x + threadIdx.x) >> 5;
    int lane = threadIdx.x & 31;
    if (warp >= TT*CC) return;
    const float* row = adj + (size_t)warp*CC;
    float s = 0.f;
    for (int j = lane; j < CC; j += 32) s += row[j];
    #pragma unroll
    for (int o = 16; o; o >>= 1) s += __shfl_xor_sync(0xffffffffu, s, o);
    if (!lane) g_dinvf[warp] = 1.0f / sqrtf(s + 1.0f);
}

__global__ void colsum_kernel(const float* __restrict__ adj){
    int t = blockIdx.y;
    int i = blockIdx.x*blockDim.x + threadIdx.x;
    const float* base = adj + (size_t)t*CC*CC + i;
    float s = 0.f;
    for (int j = 0; j < CC; j++) s += base[(size_t)j*CC];
    g_dinvb[t*CC + i] = 1.0f / sqrtf(s + 1.0f);
}

__global__ void build_L_kernel(const float* __restrict__ adj){
    __shared__ float tile[32][33];
    int t = blockIdx.z;
    int i0 = blockIdx.y*32, j0 = blockIdx.x*32;
    int tx = threadIdx.x, ty = threadIdx.y;
    const float* df = g_dinvf + t*CC;
    const float* db = g_dinvb + t*CC;
    #pragma unroll
    for (int r = 0; r < 4; r++){
        int li = ty + r*8;
        int i = i0 + li, j = j0 + tx;
        float v = adj[((size_t)t*CC + i)*CC + j] + ((i == j) ? 1.f : 0.f);
        g_Lf[((size_t)t*CC + i)*CC + j] = __float2bfloat16(v * df[i] * df[j]);
        tile[li][tx] = v * db[i] * db[j];
    }
    __syncthreads();
    #pragma unroll
    for (int r = 0; r < 4; r++){
        int lj = ty + r*8;
        int p = j0 + lj, q = i0 + tx;
        g_Lb[((size_t)t*CC + p)*CC + q] = __float2bfloat16(tile[tx][lj]);
    }
}

__global__ void build_BX_kernel(const float* __restrict__ in){
    __shared__ float tile[32][33];
    int c0 = blockIdx.x*32, f0 = blockIdx.y*32;
    int bt = blockIdx.z;
    int tx = threadIdx.x, ty = threadIdx.y;
    #pragma unroll
    for (int r = 0; r < 4; r++){
        int c = c0 + ty + r*8;
        int f = f0 + tx;
        int col = (f < 32) ? f : 96 + f;
        tile[ty + r*8][tx] = in[(((size_t)bt*CC) + c)*160 + col];
    }
    __syncthreads();
    #pragma unroll
    for (int r = 0; r < 4; r++){
        int f = f0 + ty + r*8;
        int c = c0 + tx;
        g_BX[(((size_t)bt*FIN) + f)*CC + c] = __float2bfloat16(tile[tx][ty + r*8]);
    }
}

__global__ void mask_init_kernel(){
    int i = blockIdx.x*blockDim.x + threadIdx.x;
    if (i < CC) g_mask[i] = 0;
}
__global__ void mask_set_kernel(const int* __restrict__ cells, int n){
    int i = blockIdx.x*blockDim.x + threadIdx.x;
    if (i < n) g_mask[cells[i]] = 1;
}

__global__ void wconv_kernel(const float* __restrict__ W, __nv_bfloat16* w, int K, int N){
    int idx = blockIdx.x*blockDim.x + threadIdx.x;
    if (idx >= N*K) return;
    int n = idx / K, k = idx - n*K;
    w[idx] = __float2bfloat16(W[(size_t)k*N + n]);
}

// Wmh[n][k] = sum_j Wmerge[k][j] * Whh[j][n]; bias2[n] = sum_j bm[j]*Whh[j][n] + bhh[n]
__global__ void compose_kernel(const float* __restrict__ Wm, const float* __restrict__ Whh,
                               const float* __restrict__ bm, const float* __restrict__ bhh){
    int idx = blockIdx.x*blockDim.x + threadIdx.x;
    if (idx < 384*256){
        int n = idx >> 8, k = idx & 255;
        float s = 0.f;
        #pragma unroll 8
        for (int j = 0; j < 128; j++) s += Wm[k*128 + j]*Whh[(size_t)j*384 + n];
        g_Wmh[(size_t)n*256 + k] = __float2bfloat16(s);
    }
    if (idx < 384){
        float s = bhh[idx];
        for (int j = 0; j < 128; j++) s += bm[j]*Whh[(size_t)j*384 + idx];
        g_bias2[idx] = s;
    }
}

__global__ void bias_copy_kernel(const float* initb, const float* fef, const float* feb,
                                 const float* fwd, const float* bwd, const float* merge,
                                 const float* bih){
    int i = blockIdx.x*blockDim.x + threadIdx.x;
    if (i < 128){
        g_bias[OFF_INIT + i] = initb[i];
        g_bias[OFF_FWD + i]  = fwd[i];
        g_bias[OFF_BWD + i]  = bwd[i];
        g_bias[OFF_MERGE + i]= merge[i];
    }
    if (i < 32){
        g_bias[OFF_FEF + i] = fef[i];
        g_bias[OFF_FEB + i] = feb[i];
    }
    if (i < 384) g_bias[OFF_BIH + i] = bih[i];
}

// ================ x-propagation: Zx = L @ BX  (M=128, N=64) ================
#define PX_BUFSZ (16384 + 64*128)
#define PX_SMEM  (2*PX_BUFSZ)

__global__ void __launch_bounds__(256) propx_kernel(){
    constexpr int NB = 64;
    constexpr int NCC = NB/32;
    constexpr int TOTAL = 1024 + NB*8;
    extern __shared__ char smem[];
    unsigned smem_base = smem_u32(smem);
    int tid = threadIdx.x;
    int b = blockIdx.x;
    int mtile = blockIdx.y;
    int t = blockIdx.z >> 1;
    int dir = blockIdx.z & 1;

    const __nv_bfloat16* L = (dir ? g_Lb : g_Lf) + (size_t)t*CC*CC + (size_t)mtile*128*CC;
    const __nv_bfloat16* Bsrc = g_BX + (size_t)(b*TT + t)*FIN*CC;
    __nv_bfloat16* Zdst = (dir ? g_Zxb : g_Zxf) + ((size_t)t*ROWS + b*CC + mtile*128)*64;

    int wid = tid >> 5, lane = tid & 31;
    int m0 = (wid >> 1)*32;
    int n0 = (wid & 1)*(NB/2);
    int lrow = lane & 7, lq8 = (lane >> 3) & 1, lkhi = lane >> 4;

    float acc[2][NCC][2][4];
    #pragma unroll
    for (int mi = 0; mi < 2; mi++)
        #pragma unroll
        for (int nc = 0; nc < NCC; nc++)
            #pragma unroll
            for (int sb = 0; sb < 2; sb++)
                #pragma unroll
                for (int q = 0; q < 4; q++) acc[mi][nc][sb][q] = 0.f;

    {
        #pragma unroll
        for (int it = 0; it < TOTAL/256; it++){
            int idx = tid + it*256;
            const __nv_bfloat16* src; unsigned sec; int row, col;
            if (idx < 1024){ row = idx >> 3; col = idx & 7; src = L + (size_t)row*CC + col*8; sec = 0; }
            else { int i2 = idx - 1024; row = i2 >> 3; col = i2 & 7; src = Bsrc + (size_t)row*CC + col*8; sec = 16384; }
            cp16(smem_base + sec + swz(row*128 + col*16), src);
        }
        CP_COMMIT();
    }

    for (int s = 0; s < 16; s++){
        int buf = s & 1;
        if (s + 1 < 16){
            int k0 = (s+1)*64;
            unsigned base = smem_base + (buf^1)*PX_BUFSZ;
            #pragma unroll
            for (int it = 0; it < TOTAL/256; it++){
                int idx = tid + it*256;
                const __nv_bfloat16* src; unsigned sec; int row, col;
                if (idx < 1024){ row = idx >> 3; col = idx & 7; src = L + (size_t)row*CC + k0 + col*8; sec = 0; }
                else { int i2 = idx - 1024; row = i2 >> 3; col = i2 & 7; src = Bsrc + (size_t)row*CC + k0 + col*8; sec = 16384; }
                cp16(base + sec + swz(row*128 + col*16), src);
            }
            CP_COMMIT();
            asm volatile("cp.async.wait_group 1;" ::: "memory");
        } else {
            CP_WAIT0();
        }
        __syncthreads();

        unsigned ab = smem_base + buf*PX_BUFSZ;
        #pragma unroll
        for (int kk = 0; kk < 4; kk++){
            unsigned a[2][4];
            #pragma unroll
            for (int mi = 0; mi < 2; mi++){
                unsigned row = m0 + mi*16 + lrow + lq8*8;
                unsigned sw = swz(row*128 + kk*32 + lkhi*16);
                ldsm4(a[mi][0], a[mi][1], a[mi][2], a[mi][3], ab + sw);
            }
            #pragma unroll
            for (int nc = 0; nc < NCC; nc++){
                unsigned row = n0 + nc*16 + lrow + lq8*8;
                unsigned sw = swz(row*128 + kk*32 + lkhi*16);
                unsigned bh[4];
                ldsm4(bh[0], bh[1], bh[2], bh[3], ab + 16384 + sw);
                #pragma unroll
                for (int mi = 0; mi < 2; mi++){
                    mma16816(acc[mi][nc][0], a[mi], bh[0], bh[2]);
                    mma16816(acc[mi][nc][1], a[mi], bh[1], bh[3]);
                }
            }
        }
        __syncthreads();
    }

    int g = lane >> 2, cpair = (lane & 3)*2;
    #pragma unroll
    for (int mi = 0; mi < 2; mi++){
        int row = m0 + mi*16 + g;
        #pragma unroll
        for (int nc = 0; nc < NCC; nc++){
            #pragma unroll
            for (int sb = 0; sb < 2; sb++){
                int col = n0 + nc*16 + sb*8 + cpair;
                float* cc = acc[mi][nc][sb];
                *(__nv_bfloat162*)(Zdst + (size_t)row*64 + col) =
                    __floats2bfloat162_rn(cc[0], cc[1]);
                *(__nv_bfloat162*)(Zdst + (size_t)(row+8)*64 + col) =
                    __floats2bfloat162_rn(cc[2], cc[3]);
            }
        }
    }
}

// ================ h-propagation (fused fwd/bwd GCN): gcat = relu(L @ BHW + b) =========
// grid (b=8, y=dir*16+mtile) = (8,32); CTA = 64 L-rows x 128 cols
#define PH_BUFSZ (8192 + 16384)
#define PH_SMEM  (2*PH_BUFSZ)

__global__ void __launch_bounds__(256) proph_kernel(int t){
    extern __shared__ char smem[];
    unsigned smem_base = smem_u32(smem);
    int tid = threadIdx.x;
    int b = blockIdx.x;
    int mtile = blockIdx.y & 15;
    int dir = blockIdx.y >> 4;

    const __nv_bfloat16* L = (dir ? g_Lb : g_Lf) + (size_t)t*CC*CC + (size_t)mtile*64*CC;
    const __nv_bfloat16* Bsrc = (dir ? g_BHWb : g_BHWf) + (size_t)b*HH*CC;
    const float* bias = g_bias + (dir ? OFF_BWD : OFF_FWD);
    __nv_bfloat16* Gdst = g_gcat + ((size_t)(b*CC + mtile*64))*256 + dir*128;

    int wid = tid >> 5, lane = tid & 31;
    int m0 = (wid & 1)*32;
    int n0 = (wid >> 1)*32;
    int lrow = lane & 7, lq8 = (lane >> 3) & 1, lkhi = lane >> 4;

    float acc[2][2][2][4];
    #pragma unroll
    for (int mi = 0; mi < 2; mi++)
        #pragma unroll
        for (int nc = 0; nc < 2; nc++)
            #pragma unroll
            for (int sb = 0; sb < 2; sb++)
                #pragma unroll
                for (int q = 0; q < 4; q++) acc[mi][nc][sb][q] = 0.f;

    {
        #pragma unroll
        for (int it = 0; it < 6; it++){
            int idx = tid + it*256;
            const __nv_bfloat16* src; unsigned sec; int row, col;
            if (idx < 512){ row = idx >> 3; col = idx & 7; src = L + (size_t)row*CC + col*8; sec = 0; }
            else { int i2 = idx - 512; row = i2 >> 3; col = i2 & 7; src = Bsrc + (size_t)row*CC + col*8; sec = 8192; }
            cp16(smem_base + sec + swz(row*128 + col*16), src);
        }
        CP_COMMIT();
    }

    for (int s = 0; s < 16; s++){
        int buf = s & 1;
        if (s + 1 < 16){
            int k0 = (s+1)*64;
            unsigned base = smem_base + (buf^1)*PH_BUFSZ;
            #pragma unroll
            for (int it = 0; it < 6; it++){
                int idx = tid + it*256;
                const __nv_bfloat16* src; unsigned sec; int row, col;
                if (idx < 512){ row = idx >> 3; col = idx & 7; src = L + (size_t)row*CC + k0 + col*8; sec = 0; }
                else { int i2 = idx - 512; row = i2 >> 3; col = i2 & 7; src = Bsrc + (size_t)row*CC + k0 + col*8; sec = 8192; }
                cp16(base + sec + swz(row*128 + col*16), src);
            }
            CP_COMMIT();
            asm volatile("cp.async.wait_group 1;" ::: "memory");
        } else {
            CP_WAIT0();
        }
        __syncthreads();

        unsigned ab = smem_base + buf*PH_BUFSZ;
        #pragma unroll
        for (int kk = 0; kk < 4; kk++){
            unsigned a[2][4];
            #pragma unroll
            for (int mi = 0; mi < 2; mi++){
                unsigned row = m0 + mi*16 + lrow + lq8*8;
                unsigned sw = swz(row*128 + kk*32 + lkhi*16);
                ldsm4(a[mi][0], a[mi][1], a[mi][2], a[mi][3], ab + sw);
            }
            #pragma unroll
            for (int nc = 0; nc < 2; nc++){
                unsigned row = n0 + nc*16 + lrow + lq8*8;
                unsigned sw = swz(row*128 + kk*32 + lkhi*16);
                unsigned bh[4];
                ldsm4(bh[0], bh[1], bh[2], bh[3], ab + 8192 + sw);
                #pragma unroll
                for (int mi = 0; mi < 2; mi++){
                    mma16816(acc[mi][nc][0], a[mi], bh[0], bh[2]);
                    mma16816(acc[mi][nc][1], a[mi], bh[1], bh[3]);
                }
            }
        }
        __syncthreads();
    }

    int g = lane >> 2, cpair = (lane & 3)*2;
    #pragma unroll
    for (int mi = 0; mi < 2; mi++){
        int row = m0 + mi*16 + g;
        #pragma unroll
        for (int nc = 0; nc < 2; nc++){
            #pragma unroll
            for (int sb = 0; sb < 2; sb++){
                int col = n0 + nc*16 + sb*8 + cpair;
                float b0 = bias[col], b1 = bias[col+1];
                float* cc = acc[mi][nc][sb];
                float v00 = fmaxf(cc[0]+b0, 0.f), v01 = fmaxf(cc[1]+b1, 0.f);
                float v10 = fmaxf(cc[2]+b0, 0.f), v11 = fmaxf(cc[3]+b1, 0.f);
                *(__nv_bfloat162*)(Gdst + (size_t)row*256 + col) =
                    __floats2bfloat162_rn(v00, v01);
                *(__nv_bfloat162*)(Gdst + (size_t)(row+8)*256 + col) =
                    __floats2bfloat162_rn(v10, v11);
            }
        }
    }
}

// ================ generic bf16 HMMA GEMM (task table) ================
// Loop tasks: 2=hs(gcat@Wmerge), 3..5=gh chunks (gcat@Wmh_j)
// Precompute: 10=feF, 11=feB, 12/13=gi, 14=init
#define SG_BUFSZ 40960
#define SG_SMEM  (2*SG_BUFSZ)

__global__ void __launch_bounds__(256) sgemm_kernel(int basecfg){
    int which = basecfg + blockIdx.y;
    const __nv_bfloat16 *A, *W;
    int lda, K, N, ldc, act = 0;
    const float* bias;
    float* Cf = nullptr;
    __nv_bfloat16 *Cbf = nullptr;

    switch (which){
    case 2: A=g_gcat; lda=256; K=256; W=g_Wmerge; N=128; bias=g_bias+OFF_MERGE;
            Cf=g_hsf; ldc=128; break;
    case 3: case 4: case 5: {
        int j = which - 3;
        A=g_gcat; lda=256; K=256; W=g_Wmh + (size_t)j*128*256; N=128;
        bias=g_bias2 + j*128; Cf=g_gh + j*128; ldc=384; break; }
    case 10: A=g_Zxf; lda=64; K=64; W=g_WfeF; N=32; bias=g_bias+OFF_FEF;
            Cbf=g_tmp; ldc=64; act=1; break;
    case 11: A=g_Zxb; lda=64; K=64; W=g_WfeB; N=32; bias=g_bias+OFF_FEB;
            Cbf=g_tmp+32; ldc=64; act=1; break;
    case 12: case 13: {
        int j = which - 12;
        A=g_tmp; lda=64; K=64; W=g_Wih + j*192*64; N=192; bias=g_bias+OFF_BIH+j*192;
        Cbf=g_gi_all + j*192; ldc=384; break; }
    default: // 14: init
        A=g_Zxf; lda=64; K=64; W=g_Winit; N=128; bias=g_bias+OFF_INIT;
        Cf=g_h; ldc=128; act=1; break;
    }

    extern __shared__ char smem[];
    unsigned smem_base = smem_u32(smem);
    int tid = threadIdx.x;
    int mtile = blockIdx.x;
    int wid = tid >> 5, lane = tid & 31;
    int m0 = (wid >> 1)*32;
    int Nw = N >> 1;
    int n0 = (wid & 1)*Nw;
    int ncCount = Nw >> 4; if (ncCount < 1) ncCount = 1;
    int lrow = lane & 7, lq8 = (lane >> 3) & 1, lkhi = lane >> 4;
    int nstages = K >> 6;

    float acc[2][6][2][4];
    #pragma unroll
    for (int mi = 0; mi < 2; mi++)
        #pragma unroll
        for (int nc = 0; nc < 6; nc++)
            #pragma unroll
            for (int sb = 0; sb < 2; sb++)
                #pragma unroll
                for (int q = 0; q < 4; q++) acc[mi][nc][sb][q] = 0.f;

    int total = 1024 + N*8;
    for (int idx = tid; idx < total; idx += 256){
        const __nv_bfloat16* src; unsigned sec; int row, col;
        if (idx < 1024){ row = idx >> 3; col = idx & 7;
            src = A + ((size_t)mtile*128 + row)*lda + col*8; sec = 0; }
        else { int i2 = idx - 1024; row = i2 >> 3; col = i2 & 7;
            src = W + (size_t)row*K + col*8; sec = 16384; }
        cp16(smem_base + sec + swz(row*128 + col*16), src);
    }
    CP_COMMIT();

    for (int s = 0; s < nstages; s++){
        int buf = s & 1;
        if (s + 1 < nstages){
            int k0 = (s+1)*64;
            unsigned base = smem_base + (buf^1)*SG_BUFSZ;
            for (int idx = tid; idx < total; idx += 256){
                const __nv_bfloat16* src; unsigned sec; int row, col;
                if (idx < 1024){ row = idx >> 3; col = idx & 7;
                    src = A + ((size_t)mtile*128 + row)*lda + k0 + col*8; sec = 0; }
                else { int i2 = idx - 1024; row = i2 >> 3; col = i2 & 7;
                    src = W + (size_t)row*K + k0 + col*8; sec = 16384; }
                cp16(base + sec + swz(row*128 + col*16), src);
            }
            CP_COMMIT();
            asm volatile("cp.async.wait_group 1;" ::: "memory");
        } else {
            CP_WAIT0();
        }
        __syncthreads();

        unsigned ab = smem_base + buf*SG_BUFSZ;
        #pragma unroll
        for (int kk = 0; kk < 4; kk++){
            unsigned a[2][4];
            #pragma unroll
            for (int mi = 0; mi < 2; mi++){
                unsigned row = m0 + mi*16 + lrow + lq8*8;
                unsigned sw = swz(row*128 + kk*32 + lkhi*16);
                ldsm4(a[mi][0], a[mi][1], a[mi][2], a[mi][3], ab + sw);
            }
            for (int nc = 0; nc < ncCount; nc++){
                unsigned row = n0 + nc*16 + lrow + lq8*8;
                unsigned sw = swz(row*128 + kk*32 + lkhi*16);
                unsigned bh[4];
                ldsm4(bh[0], bh[1], bh[2], bh[3], ab + 16384 + sw);
                #pragma unroll
                for (int mi = 0; mi < 2; mi++){
                    mma16816(acc[mi][nc][0], a[mi], bh[0], bh[2]);
                    mma16816(acc[mi][nc][1], a[mi], bh[1], bh[3]);
                }
            }
        }
        __syncthreads();
    }

    int g = lane >> 2, cpair = (lane & 3)*2;
    #pragma unroll
    for (int mi = 0; mi < 2; mi++){
        int row = mtile*128 + m0 + mi*16 + g;
        for (int nc = 0; nc < ncCount; nc++){
            #pragma unroll
            for (int sb = 0; sb < 2; sb++){
                int col = n0 + nc*16 + sb*8 + cpair;
                float b0 = bias[col], b1 = bias[col+1];
                float* cc = acc[mi][nc][sb];
                float v00 = cc[0] + b0, v01 = cc[1] + b1;
                float v10 = cc[2] + b0, v11 = cc[3] + b1;
                if (act){
                    v00 = fmaxf(v00, 0.f); v01 = fmaxf(v01, 0.f);
                    v10 = fmaxf(v10, 0.f); v11 = fmaxf(v11, 0.f);
                }
                if (Cf){
                    *(float2*)(Cf + (size_t)row*ldc + col)     = make_float2(v00, v01);
                    *(float2*)(Cf + (size_t)(row+8)*ldc + col) = make_float2(v10, v11);
                }
                if (Cbf){
                    *(__nv_bfloat162*)(Cbf + (size_t)row*ldc + col)     = __floats2bfloat162_rn(v00, v01);
                    *(__nv_bfloat162*)(Cbf + (size_t)(row+8)*ldc + col) = __floats2bfloat162_rn(v10, v11);
                }
            }
        }
    }
}

// ================ gruhw: GRU gates + hist; then BHW = (h@Wfwd | h@Wbwd)^T ============
// grid 256 (32 rows/CTA). smem: H[8K] W[64K] OUT[17K] = 89.3KB -> 2 CTAs/SM.
#define GW_H   0
#define GW_W   8192
#define GW_OUT 73728
#define GW_SMEM 91136

__global__ void __launch_bounds__(256) gruhw_kernel(int t, int mode){
    extern __shared__ char smem[];
    unsigned sb = smem_u32(smem);
    int tid = threadIdx.x;
    int row0 = blockIdx.x*32;
    int b = row0 >> 10, c0 = row0 & 1023;

    load_mat<256,128>(sb + GW_W, g_Wfb, 128, tid);
    CP_COMMIT();

    // gates (or passthrough) -> h into smem k-panel layout
    #pragma unroll
    for (int it = 0; it < 16; it++){
        int item = tid + it*256;
        int f = item & 127, rl = item >> 7;
        int R = row0 + rl;
        float h;
        if (mode == 0){
            h = g_h[(size_t)R*HH + f];
        } else {
            const __nv_bfloat16* gi = g_gi_all + ((size_t)t*ROWS + R)*384;
            const float* gh = g_gh + (size_t)R*384;
            float ir = __bfloat162float(gi[f]);
            float iz = __bfloat162float(gi[128 + f]);
            float inn = __bfloat162float(gi[256 + f]);
            float hr = gh[f], hz = gh[128 + f], hn = gh[256 + f];
            float rg = 1.f / (1.f + expf(-(ir + hr)));
            float zg = 1.f / (1.f + expf(-(iz + hz)));
            float ng = tanhf(inn + rg*hn);
            float hs = g_hsf[(size_t)R*HH + f];
            h = (1.f - zg)*ng + zg*hs;
            if (t >= 4) g_hist[((size_t)(t-4)*ROWS + R)*HH + f] = h;
        }
        int kp = f >> 6, kc = f & 63;
        *(__nv_bfloat16*)(smem + GW_H + kp*4096 + swz(rl*128 + kc*2)) = __float2bfloat16(h);
    }
    CP_WAIT0();
    __syncthreads();

    int wid = tid >> 5, lane = tid & 31;
    int m0 = (wid & 1)*16;          // 32 rows total
    int n0 = (wid >> 1)*64;         // 256 cols total
    int lrow = lane & 7, lq8 = (lane >> 3) & 1, lkhi = lane >> 4;
    int g = lane >> 2, cpair = (lane & 3)*2;

    float acc[4][2][4];
    #pragma unroll
    for (int nc = 0; nc < 4; nc++)
        #pragma unroll
        for (int sbq = 0; sbq < 2; sbq++)
            #pragma unroll
            for (int q = 0; q < 4; q++) acc[nc][sbq][q] = 0.f;

    #pragma unroll
    for (int s = 0; s < 2; s++){
        unsigned aP = sb + GW_H + s*4096;
        unsigned wP = sb + GW_W + s*32768;
        #pragma unroll
        for (int kk = 0; kk < 4; kk++){
            unsigned a[4];
            unsigned row = m0 + lrow + lq8*8;
            ldsm4(a[0], a[1], a[2], a[3], aP + swz(row*128 + kk*32 + lkhi*16));
            #pragma unroll
            for (int nc = 0; nc < 4; nc++){
                unsigned wrow = n0 + nc*16 + lrow + lq8*8;
                unsigned bh[4];
                ldsm4(bh[0], bh[1], bh[2], bh[3], wP + swz(wrow*128 + kk*32 + lkhi*16));
                mma16816(acc[nc][0], a, bh[0], bh[2]);
                mma16816(acc[nc][1], a, bh[1], bh[3]);
            }
        }
    }

    // epilogue: OUT[f][c] tile in smem (pitch 34 bf16)
    __nv_bfloat16* OUT = (__nv_bfloat16*)(smem + GW_OUT);
    int rl = m0 + g;
    #pragma unroll
    for (int nc = 0; nc < 4; nc++){
        #pragma unroll
        for (int sbq = 0; sbq < 2; sbq++){
            int col = n0 + nc*16 + sbq*8 + cpair;
            float* cc = acc[nc][sbq];
            OUT[col*34 + rl]       = __float2bfloat16(cc[0]);
            OUT[(col+1)*34 + rl]   = __float2bfloat16(cc[1]);
            OUT[col*34 + rl+8]     = __float2bfloat16(cc[2]);
            OUT[(col+1)*34 + rl+8] = __float2bfloat16(cc[3]);
        }
    }
    __syncthreads();
    // coalesced write to BHW [b][f][c]
    #pragma unroll
    for (int it = 0; it < 32; it++){
        int item = tid + it*256;
        int cl = item & 31, f = item >> 5;
        __nv_bfloat16 v = OUT[f*34 + cl];
        if (f < 128) g_BHWf[((size_t)b*HH + f)*CC + c0 + cl] = v;
        else         g_BHWb[((size_t)b*HH + (f - 128))*CC + c0 + cl] = v;
    }
}

// ---------------- final: pred = hist @ outW + outb, fused mask-scatter ----------------
__global__ void __launch_bounds__(256) predout_kernel(const float* __restrict__ in,
                                                      const float* __restrict__ outW,
                                                      const float* __restrict__ outb,
                                                      float* __restrict__ out){
    __shared__ float Ws[128*32];
    __shared__ float As[64*128];
    int r0 = blockIdx.x*64;
    int tid = threadIdx.x;
    for (int i = tid; i < 128*32; i += 256) Ws[i] = outW[i];
    {
        const float4* src = (const float4*)(g_hist + (size_t)r0*HH);
        float4* dst = (float4*)As;
        for (int i = tid; i < 64*128/4; i += 256) dst[i] = src[i];
    }
    __syncthreads();

    #pragma unroll
    for (int it = 0; it < 2; it++){
        int item = tid + it*256;
        int rl = item >> 3;
        int cg = (item & 7)*4;
        float a0 = outb[cg], a1 = outb[cg+1], a2 = outb[cg+2], a3 = outb[cg+3];
        const float* Ar = As + rl*128;
        #pragma unroll 8
        for (int k = 0; k < 128; k++){
            float av = Ar[k];
            const float* wr = Ws + k*32 + cg;
            a0 += av*wr[0]; a1 += av*wr[1]; a2 += av*wr[2]; a3 += av*wr[3];
        }
        int r = r0 + rl;
        int t = r >> 13;
        int rb = r & 8191;
        int b = rb >> 10, c = rb & 1023;
        float4 v;
        if (g_mask[c])
            v = *(const float4*)(in + (((size_t)(b*TT + t + 5)*CC + c)*160) + cg);
        else
            v = make_float4(a0, a1, a2, a3);
        *(float4*)(out + (((size_t)(b*SS + t)*CC + c)*DST) + cg) = v;
    }
}

// ---------------- host orchestration ----------------
static __nv_bfloat16* symb(const void* s){ void* p = nullptr; cudaGetSymbolAddress(&p, s); return (__nv_bfloat16*)p; }

extern "C" void kernel_launch(void* const* d_in, const int* in_sizes, int n_in,
                              void* d_out, int out_size)
{
    const float* inputs   = (const float*)d_in[0];
    const float* adj      = (const float*)d_in[1];
    const float* init_W   = (const float*)d_in[2];
    const float* init_b   = (const float*)d_in[3];
    const float* fe_fwd_W = (const float*)d_in[4];
    const float* fe_fwd_b = (const float*)d_in[5];
    const float* fe_bwd_W = (const float*)d_in[6];
    const float* fe_bwd_b = (const float*)d_in[7];
    const float* fwd_W    = (const float*)d_in[8];
    const float* fwd_b    = (const float*)d_in[9];
    const float* bwd_W    = (const float*)d_in[10];
    const float* bwd_b    = (const float*)d_in[11];
    const float* merge_W  = (const float*)d_in[12];
    const float* merge_b  = (const float*)d_in[13];
    const float* gru_Wih  = (const float*)d_in[14];
    const float* gru_bih  = (const float*)d_in[15];
    const float* gru_Whh  = (const float*)d_in[16];
    const float* gru_bhh  = (const float*)d_in[17];
    const float* out_W    = (const float*)d_in[18];
    const float* out_b    = (const float*)d_in[19];
    const int*   cells    = (const int*)  d_in[20];
    float* out = (float*)d_out;

    cudaFuncSetAttribute(propx_kernel, cudaFuncAttributeMaxDynamicSharedMemorySize, PX_SMEM);
    cudaFuncSetAttribute(proph_kernel, cudaFuncAttributeMaxDynamicSharedMemorySize, PH_SMEM);
    cudaFuncSetAttribute(sgemm_kernel, cudaFuncAttributeMaxDynamicSharedMemorySize, SG_SMEM);
    cudaFuncSetAttribute(gruhw_kernel, cudaFuncAttributeMaxDynamicSharedMemorySize, GW_SMEM);

    // ---- prolog ----
    rowsum_kernel<<<TT*CC/8, 256>>>(adj);
    colsum_kernel<<<dim3(4, TT), 256>>>(adj);
    build_L_kernel<<<dim3(CC/32, CC/32, TT), dim3(32, 8)>>>(adj);
    build_BX_kernel<<<dim3(CC/32, FIN/32, BB*TT), dim3(32, 8)>>>(inputs);
    mask_init_kernel<<<4, 256>>>();
    int nic = in_sizes[20];
    mask_set_kernel<<<(nic + 255)/256, 256>>>(cells, nic);

    wconv_kernel<<<(128*64 + 255)/256, 256>>>(init_W,  symb(g_Winit), 64, 128);
    wconv_kernel<<<(32*64 + 255)/256, 256>>>(fe_fwd_W, symb(g_WfeF),  64, 32);
    wconv_kernel<<<(32*64 + 255)/256, 256>>>(fe_bwd_W, symb(g_WfeB),  64, 32);
    wconv_kernel<<<(128*128 + 255)/256, 256>>>(fwd_W,  symb(g_Wfb),         128, 128);
    wconv_kernel<<<(128*128 + 255)/256, 256>>>(bwd_W,  symb(g_Wfb)+128*128, 128, 128);
    wconv_kernel<<<(128*256 + 255)/256, 256>>>(merge_W,symb(g_Wmerge),256, 128);
    wconv_kernel<<<(384*64 + 255)/256, 256>>>(gru_Wih, symb(g_Wih),   64, 384);
    compose_kernel<<<(384*256 + 255)/256, 256>>>(merge_W, gru_Whh, merge_b, gru_bhh);
    bias_copy_kernel<<<2, 256>>>(init_b, fe_fwd_b, fe_bwd_b, fwd_b, bwd_b, merge_b,
                                 gru_bih);

    // ---- x-dependent precompute ----
    propx_kernel<<<dim3(BB, 8, NT*2), 256, PX_SMEM>>>();
    sgemm_kernel<<<dim3(NT*64, 2), 256, SG_SMEM>>>(10);   // fe fwd+bwd -> tmp
    sgemm_kernel<<<dim3(NT*64, 2), 256, SG_SMEM>>>(12);   // gi
    sgemm_kernel<<<dim3(64, 1), 256, SG_SMEM>>>(14);      // hidden0 -> g_h
    gruhw_kernel<<<256, 256, GW_SMEM>>>(0, 0);            // BHW from h0

    // ---- scan: 3 kernels per step ----
    for (int t = 0; t < NT; t++){
        proph_kernel<<<dim3(BB, 32), 256, PH_SMEM>>>(t);  // gcat = relu(L@BHW + b)
        sgemm_kernel<<<dim3(64, 4), 256, SG_SMEM>>>(2);   // hs + gh (one launch)
        gruhw_kernel<<<256, 256, GW_SMEM>>>(t, 1);        // gates + hist + BHW
    }

    // ---- output ----
    predout_kernel<<<SS*ROWS/64, 256>>>(inputs, out_W, out_b, out);
}

// round 14
// speedup vs baseline: 1.1136x; 1.1136x over previous
#include <cuda_runtime.h>
#include <cuda_bf16.h>
#include <math.h>

#define BB 8
#define TT 32
#define CC 1024
#define HH 128
#define DST 32
#define FIN 64
#define SS 27            // T - INIT_LENGTH - 1
#define NT 31            // scan steps
#define ROWS (BB*CC)     // 8192

// ================= warp-MMA helpers =================
__device__ __forceinline__ unsigned smem_u32(const void* p){
    unsigned a;
    asm("{ .reg .u64 t; cvta.to.shared.u64 t, %1; cvt.u32.u64 %0, t; }" : "=r"(a) : "l"(p));
    return a;
}

__device__ __forceinline__ void ldsm4(unsigned& r0, unsigned& r1, unsigned& r2, unsigned& r3,
                                      unsigned addr){
    asm volatile("ldmatrix.sync.aligned.m8n8.x4.shared.b16 {%0,%1,%2,%3}, [%4];"
                 : "=r"(r0), "=r"(r1), "=r"(r2), "=r"(r3) : "r"(addr));
}

__device__ __forceinline__ void mma16816(float* c, const unsigned* a, unsigned b0, unsigned b1){
    asm volatile("mma.sync.aligned.m16n8k16.row.col.f32.bf16.bf16.f32 "
                 "{%0,%1,%2,%3}, {%4,%5,%6,%7}, {%8,%9}, {%0,%1,%2,%3};"
                 : "+f"(c[0]), "+f"(c[1]), "+f"(c[2]), "+f"(c[3])
                 : "r"(a[0]), "r"(a[1]), "r"(a[2]), "r"(a[3]), "r"(b0), "r"(b1));
}

__device__ __forceinline__ void cp16(unsigned dst, const void* src){
    asm volatile("cp.async.cg.shared.global [%0], [%1], 16;"
                 :: "r"(dst), "l"(__cvta_generic_to_global(src)));
}
#define CP_COMMIT() asm volatile("cp.async.commit_group;" ::: "memory")
#define CP_WAIT0()  asm volatile("cp.async.wait_group 0;" ::: "memory")

__device__ __forceinline__ unsigned swz(unsigned boff){
    return boff ^ ((boff >> 3) & 0x70);
}

// ---------------- device scratch ----------------
__device__ __nv_bfloat16 g_Lf[(size_t)TT*CC*CC];
__device__ __nv_bfloat16 g_Lb[(size_t)TT*CC*CC];
__device__ __nv_bfloat16 g_BX[(size_t)BB*TT*FIN*CC];   // [b][t][f][c]
__device__ __nv_bfloat16 g_BH[(size_t)BB*HH*CC];       // [b][f][c]

__device__ __nv_bfloat16 g_Zxf[(size_t)NT*ROWS*64];
__device__ __nv_bfloat16 g_Zxb[(size_t)NT*ROWS*64];
__device__ __nv_bfloat16 g_Zhf[(size_t)ROWS*HH];
__device__ __nv_bfloat16 g_Zhb[(size_t)ROWS*HH];
__device__ __nv_bfloat16 g_tmp[(size_t)NT*ROWS*64];
__device__ __nv_bfloat16 g_gi_all[(size_t)NT*ROWS*384];
__device__ __nv_bfloat16 g_gcat[(size_t)ROWS*256];
__device__ float         g_hsf[(size_t)ROWS*HH];
__device__ __nv_bfloat16 g_ghb[(size_t)ROWS*384];
__device__ float         g_hist[(size_t)SS*ROWS*HH];
__device__ float         g_h[(size_t)ROWS*HH];
__device__ float         g_dinvf[TT*CC];
__device__ float         g_dinvb[TT*CC];
__device__ int           g_mask[CC];

// weights bf16 [N][K]
__device__ __nv_bfloat16 g_Winit[128*64];
__device__ __nv_bfloat16 g_WfeF[32*64];
__device__ __nv_bfloat16 g_WfeB[32*64];
__device__ __nv_bfloat16 g_Wfwd[128*128];
__device__ __nv_bfloat16 g_Wbwd[128*128];
__device__ __nv_bfloat16 g_Wmerge[128*256];
__device__ __nv_bfloat16 g_Wmh[384*256];     // (Wmerge @ Whh)^T, bf16 [N][K]
__device__ __nv_bfloat16 g_Wih[384*64];
__device__ float         g_bias2[384];       // bm @ Whh + bhh

#define OFF_INIT  0
#define OFF_FEF   128
#define OFF_FEB   160
#define OFF_FWD   192
#define OFF_BWD   320
#define OFF_MERGE 448
#define OFF_BIH   576
__device__ float g_bias[960];

// ---------------- prolog kernels ----------------
__global__ void rowsum_kernel(const float* __restrict__ adj){
    int warp = (blockIdx.x*blockDim.x + threadIdx.x) >> 5;
    int lane = threadIdx.x & 31;
    if (warp >= TT*CC) return;
    const float* row = adj + (size_t)warp*CC;
    float s = 0.f;
    for (int j = lane; j < CC; j += 32) s += row[j];
    #pragma unroll
    for (int o = 16; o; o >>= 1) s += __shfl_xor_sync(0xffffffffu, s, o);
    if (!lane) g_dinvf[warp] = 1.0f / sqrtf(s + 1.0f);
}

__global__ void colsum_kernel(const float* __restrict__ adj){
    int t = blockIdx.y;
    int i = blockIdx.x*blockDim.x + threadIdx.x;
    const float* base = adj + (size_t)t*CC*CC + i;
    float s = 0.f;
    for (int j = 0; j < CC; j++) s += base[(size_t)j*CC];
    g_dinvb[t*CC + i] = 1.0f / sqrtf(s + 1.0f);
}

__global__ void build_L_kernel(const float* __restrict__ adj){
    __shared__ float tile[32][33];
    int t = blockIdx.z;
    int i0 = blockIdx.y*32, j0 = blockIdx.x*32;
    int tx = threadIdx.x, ty = threadIdx.y;
    const float* df = g_dinvf + t*CC;
    const float* db = g_dinvb + t*CC;
    #pragma unroll
    for (int r = 0; r < 4; r++){
        int li = ty + r*8;
        int i = i0 + li, j = j0 + tx;
        float v = adj[((size_t)t*CC + i)*CC + j] + ((i == j) ? 1.f : 0.f);
        g_Lf[((size_t)t*CC + i)*CC + j] = __float2bfloat16(v * df[i] * df[j]);
        tile[li][tx] = v * db[i] * db[j];
    }
    __syncthreads();
    #pragma unroll
    for (int r = 0; r < 4; r++){
        int lj = ty + r*8;
        int p = j0 + lj, q = i0 + tx;
        g_Lb[((size_t)t*CC + p)*CC + q] = __float2bfloat16(tile[tx][lj]);
    }
}

__global__ void build_BX_kernel(const float* __restrict__ in){
    __shared__ float tile[32][33];
    int c0 = blockIdx.x*32, f0 = blockIdx.y*32;
    int bt = blockIdx.z;
    int tx = threadIdx.x, ty = threadIdx.y;
    #pragma unroll
    for (int r = 0; r < 4; r++){
        int c = c0 + ty + r*8;
        int f = f0 + tx;
        int col = (f < 32) ? f : 96 + f;
        tile[ty + r*8][tx] = in[(((size_t)bt*CC) + c)*160 + col];
    }
    __syncthreads();
    #pragma unroll
    for (int r = 0; r < 4; r++){
        int f = f0 + ty + r*8;
        int c = c0 + tx;
        g_BX[(((size_t)bt*FIN) + f)*CC + c] = __float2bfloat16(tile[tx][ty + r*8]);
    }
}

__global__ void transpose_h_kernel(){
    __shared__ float tile[32][33];
    int c0 = blockIdx.x*32, f0 = blockIdx.y*32;
    int b = blockIdx.z;
    int tx = threadIdx.x, ty = threadIdx.y;
    #pragma unroll
    for (int r = 0; r < 4; r++){
        int c = c0 + ty + r*8;
        int f = f0 + tx;
        tile[ty + r*8][tx] = g_h[((size_t)b*CC + c)*HH + f];
    }
    __syncthreads();
    #pragma unroll
    for (int r = 0; r < 4; r++){
        int f = f0 + ty + r*8;
        int c = c0 + tx;
        g_BH[((size_t)b*HH + f)*CC + c] = __float2bfloat16(tile[tx][ty + r*8]);
    }
}

__global__ void mask_init_kernel(){
    int i = blockIdx.x*blockDim.x + threadIdx.x;
    if (i < CC) g_mask[i] = 0;
}
__global__ void mask_set_kernel(const int* __restrict__ cells, int n){
    int i = blockIdx.x*blockDim.x + threadIdx.x;
    if (i < n) g_mask[cells[i]] = 1;
}

__global__ void wconv_kernel(const float* __restrict__ W, __nv_bfloat16* w, int K, int N){
    int idx = blockIdx.x*blockDim.x + threadIdx.x;
    if (idx >= N*K) return;
    int n = idx / K, k = idx - n*K;
    w[idx] = __float2bfloat16(W[(size_t)k*N + n]);
}

// Wmh[n][k] = sum_j Wmerge[k][j] * Whh[j][n]; bias2[n] = sum_j bm[j]*Whh[j][n] + bhh[n]
__global__ void compose_kernel(const float* __restrict__ Wm, const float* __restrict__ Whh,
                               const float* __restrict__ bm, const float* __restrict__ bhh){
    int idx = blockIdx.x*blockDim.x + threadIdx.x;
    if (idx < 384*256){
        int n = idx >> 8, k = idx & 255;
        float s = 0.f;
        #pragma unroll 8
        for (int j = 0; j < 128; j++) s += Wm[k*128 + j]*Whh[(size_t)j*384 + n];
        g_Wmh[(size_t)n*256 + k] = __float2bfloat16(s);
    }
    if (idx < 384){
        float s = bhh[idx];
        for (int j = 0; j < 128; j++) s += bm[j]*Whh[(size_t)j*384 + idx];
        g_bias2[idx] = s;
    }
}

__global__ void bias_copy_kernel(const float* initb, const float* fef, const float* feb,
                                 const float* fwd, const float* bwd, const float* merge,
                                 const float* bih){
    int i = blockIdx.x*blockDim.x + threadIdx.x;
    if (i < 128){
        g_bias[OFF_INIT + i] = initb[i];
        g_bias[OFF_FWD + i]  = fwd[i];
        g_bias[OFF_BWD + i]  = bwd[i];
        g_bias[OFF_MERGE + i]= merge[i];
    }
    if (i < 32){
        g_bias[OFF_FEF + i] = fef[i];
        g_bias[OFF_FEB + i] = feb[i];
    }
    if (i < 384) g_bias[OFF_BIH + i] = bih[i];
}

// ================ x-propagation: Zx = L @ BX  (M=128, N=64) ================
#define PX_BUFSZ (16384 + 64*128)
#define PX_SMEM  (2*PX_BUFSZ)

__global__ void __launch_bounds__(256) propx_kernel(){
    constexpr int NB = 64;
    constexpr int NCC = NB/32;
    constexpr int TOTAL = 1024 + NB*8;
    extern __shared__ char smem[];
    unsigned smem_base = smem_u32(smem);
    int tid = threadIdx.x;
    int b = blockIdx.x;
    int mtile = blockIdx.y;
    int t = blockIdx.z >> 1;
    int dir = blockIdx.z & 1;

    const __nv_bfloat16* L = (dir ? g_Lb : g_Lf) + (size_t)t*CC*CC + (size_t)mtile*128*CC;
    const __nv_bfloat16* Bsrc = g_BX + (size_t)(b*TT + t)*FIN*CC;
    __nv_bfloat16* Zdst = (dir ? g_Zxb : g_Zxf) + ((size_t)t*ROWS + b*CC + mtile*128)*64;

    int wid = tid >> 5, lane = tid & 31;
    int m0 = (wid >> 1)*32;
    int n0 = (wid & 1)*(NB/2);
    int lrow = lane & 7, lq8 = (lane >> 3) & 1, lkhi = lane >> 4;

    float acc[2][NCC][2][4];
    #pragma unroll
    for (int mi = 0; mi < 2; mi++)
        #pragma unroll
        for (int nc = 0; nc < NCC; nc++)
            #pragma unroll
            for (int sb = 0; sb < 2; sb++)
                #pragma unroll
                for (int q = 0; q < 4; q++) acc[mi][nc][sb][q] = 0.f;

    {
        #pragma unroll
        for (int it = 0; it < TOTAL/256; it++){
            int idx = tid + it*256;
            const __nv_bfloat16* src; unsigned sec; int row, col;
            if (idx < 1024){ row = idx >> 3; col = idx & 7; src = L + (size_t)row*CC + col*8; sec = 0; }
            else { int i2 = idx - 1024; row = i2 >> 3; col = i2 & 7; src = Bsrc + (size_t)row*CC + col*8; sec = 16384; }
            cp16(smem_base + sec + swz(row*128 + col*16), src);
        }
        CP_COMMIT();
    }

    for (int s = 0; s < 16; s++){
        int buf = s & 1;
        if (s + 1 < 16){
            int k0 = (s+1)*64;
            unsigned base = smem_base + (buf^1)*PX_BUFSZ;
            #pragma unroll
            for (int it = 0; it < TOTAL/256; it++){
                int idx = tid + it*256;
                const __nv_bfloat16* src; unsigned sec; int row, col;
                if (idx < 1024){ row = idx >> 3; col = idx & 7; src = L + (size_t)row*CC + k0 + col*8; sec = 0; }
                else { int i2 = idx - 1024; row = i2 >> 3; col = i2 & 7; src = Bsrc + (size_t)row*CC + k0 + col*8; sec = 16384; }
                cp16(base + sec + swz(row*128 + col*16), src);
            }
            CP_COMMIT();
            asm volatile("cp.async.wait_group 1;" ::: "memory");
        } else {
            CP_WAIT0();
        }
        __syncthreads();

        unsigned ab = smem_base + buf*PX_BUFSZ;
        #pragma unroll
        for (int kk = 0; kk < 4; kk++){
            unsigned a[2][4];
            #pragma unroll
            for (int mi = 0; mi < 2; mi++){
                unsigned row = m0 + mi*16 + lrow + lq8*8;
                unsigned sw = swz(row*128 + kk*32 + lkhi*16);
                ldsm4(a[mi][0], a[mi][1], a[mi][2], a[mi][3], ab + sw);
            }
            #pragma unroll
            for (int nc = 0; nc < NCC; nc++){
                unsigned row = n0 + nc*16 + lrow + lq8*8;
                unsigned sw = swz(row*128 + kk*32 + lkhi*16);
                unsigned bh[4];
                ldsm4(bh[0], bh[1], bh[2], bh[3], ab + 16384 + sw);
                #pragma unroll
                for (int mi = 0; mi < 2; mi++){
                    mma16816(acc[mi][nc][0], a[mi], bh[0], bh[2]);
                    mma16816(acc[mi][nc][1], a[mi], bh[1], bh[3]);
                }
            }
        }
        __syncthreads();
    }

    int g = lane >> 2, cpair = (lane & 3)*2;
    #pragma unroll
    for (int mi = 0; mi < 2; mi++){
        int row = m0 + mi*16 + g;
        #pragma unroll
        for (int nc = 0; nc < NCC; nc++){
            #pragma unroll
            for (int sb = 0; sb < 2; sb++){
                int col = n0 + nc*16 + sb*8 + cpair;
                float* cc = acc[mi][nc][sb];
                *(__nv_bfloat162*)(Zdst + (size_t)row*64 + col) =
                    __floats2bfloat162_rn(cc[0], cc[1]);
                *(__nv_bfloat162*)(Zdst + (size_t)(row+8)*64 + col) =
                    __floats2bfloat162_rn(cc[2], cc[3]);
            }
        }
    }
}

// ================ h-propagation: Zh = L @ BH  (M=64 rows/CTA, N=128) ================
#define PH_BUFSZ (8192 + 16384)
#define PH_SMEM  (2*PH_BUFSZ)

__global__ void __launch_bounds__(256) proph_kernel(int t){
    extern __shared__ char smem[];
    unsigned smem_base = smem_u32(smem);
    int tid = threadIdx.x;
    int b = blockIdx.x;
    int mtile = blockIdx.y & 15;
    int dir = blockIdx.y >> 4;

    const __nv_bfloat16* L = (dir ? g_Lb : g_Lf) + (size_t)t*CC*CC + (size_t)mtile*64*CC;
    const __nv_bfloat16* Bsrc = g_BH + (size_t)b*HH*CC;
    __nv_bfloat16* Zdst = (dir ? g_Zhb : g_Zhf) + ((size_t)(b*CC + mtile*64))*HH;

    int wid = tid >> 5, lane = tid & 31;
    int m0 = (wid & 1)*32;
    int n0 = (wid >> 1)*32;
    int lrow = lane & 7, lq8 = (lane >> 3) & 1, lkhi = lane >> 4;

    float acc[2][2][2][4];
    #pragma unroll
    for (int mi = 0; mi < 2; mi++)
        #pragma unroll
        for (int nc = 0; nc < 2; nc++)
            #pragma unroll
            for (int sb = 0; sb < 2; sb++)
                #pragma unroll
                for (int q = 0; q < 4; q++) acc[mi][nc][sb][q] = 0.f;

    {
        #pragma unroll
        for (int it = 0; it < 6; it++){
            int idx = tid + it*256;
            const __nv_bfloat16* src; unsigned sec; int row, col;
            if (idx < 512){ row = idx >> 3; col = idx & 7; src = L + (size_t)row*CC + col*8; sec = 0; }
            else { int i2 = idx - 512; row = i2 >> 3; col = i2 & 7; src = Bsrc + (size_t)row*CC + col*8; sec = 8192; }
            cp16(smem_base + sec + swz(row*128 + col*16), src);
        }
        CP_COMMIT();
    }

    for (int s = 0; s < 16; s++){
        int buf = s & 1;
        if (s + 1 < 16){
            int k0 = (s+1)*64;
            unsigned base = smem_base + (buf^1)*PH_BUFSZ;
            #pragma unroll
            for (int it = 0; it < 6; it++){
                int idx = tid + it*256;
                const __nv_bfloat16* src; unsigned sec; int row, col;
                if (idx < 512){ row = idx >> 3; col = idx & 7; src = L + (size_t)row*CC + k0 + col*8; sec = 0; }
                else { int i2 = idx - 512; row = i2 >> 3; col = i2 & 7; src = Bsrc + (size_t)row*CC + k0 + col*8; sec = 8192; }
                cp16(base + sec + swz(row*128 + col*16), src);
            }
            CP_COMMIT();
            asm volatile("cp.async.wait_group 1;" ::: "memory");
        } else {
            CP_WAIT0();
        }
        __syncthreads();

        unsigned ab = smem_base + buf*PH_BUFSZ;
        #pragma unroll
        for (int kk = 0; kk < 4; kk++){
            unsigned a[2][4];
            #pragma unroll
            for (int mi = 0; mi < 2; mi++){
                unsigned row = m0 + mi*16 + lrow + lq8*8;
                unsigned sw = swz(row*128 + kk*32 + lkhi*16);
                ldsm4(a[mi][0], a[mi][1], a[mi][2], a[mi][3], ab + sw);
            }
            #pragma unroll
            for (int nc = 0; nc < 2; nc++){
                unsigned row = n0 + nc*16 + lrow + lq8*8;
                unsigned sw = swz(row*128 + kk*32 + lkhi*16);
                unsigned bh[4];
                ldsm4(bh[0], bh[1], bh[2], bh[3], ab + 8192 + sw);
                #pragma unroll
                for (int mi = 0; mi < 2; mi++){
                    mma16816(acc[mi][nc][0], a[mi], bh[0], bh[2]);
                    mma16816(acc[mi][nc][1], a[mi], bh[1], bh[3]);
                }
            }
        }
        __syncthreads();
    }

    int g = lane >> 2, cpair = (lane & 3)*2;
    #pragma unroll
    for (int mi = 0; mi < 2; mi++){
        int row = m0 + mi*16 + g;
        #pragma unroll
        for (int nc = 0; nc < 2; nc++){
            #pragma unroll
            for (int sb = 0; sb < 2; sb++){
                int col = n0 + nc*16 + sb*8 + cpair;
                float* cc = acc[mi][nc][sb];
                *(__nv_bfloat162*)(Zdst + (size_t)row*HH + col) =
                    __floats2bfloat162_rn(cc[0], cc[1]);
                *(__nv_bfloat162*)(Zdst + (size_t)(row+8)*HH + col) =
                    __floats2bfloat162_rn(cc[2], cc[3]);
            }
        }
    }
}

// ================ generic bf16 HMMA GEMM (task table) ================
// Loop tasks: 0=fwd, 1=bwd, 2=hs(gcat@Wmerge), 3..5=gh chunks (gcat@Wmh_j)
// Precompute: 10=feF, 11=feB, 12/13=gi, 14=init
#define SG_BUFSZ 40960
#define SG_SMEM  (2*SG_BUFSZ)

__global__ void __launch_bounds__(256) sgemm_kernel(int basecfg){
    int which = basecfg + blockIdx.y;
    const __nv_bfloat16 *A, *W;
    int lda, K, N, ldc, act = 0;
    const float* bias;
    float* Cf = nullptr;
    __nv_bfloat16 *Cbf = nullptr;

    switch (which){
    case 0: A=g_Zhf; lda=128; K=128; W=g_Wfwd; N=128; bias=g_bias+OFF_FWD;
            Cbf=g_gcat; ldc=256; act=1; break;
    case 1: A=g_Zhb; lda=128; K=128; W=g_Wbwd; N=128; bias=g_bias+OFF_BWD;
            Cbf=g_gcat+128; ldc=256; act=1; break;
    case 2: A=g_gcat; lda=256; K=256; W=g_Wmerge; N=128; bias=g_bias+OFF_MERGE;
            Cf=g_hsf; ldc=128; break;
    case 3: case 4: case 5: {
        int j = which - 3;
        A=g_gcat; lda=256; K=256; W=g_Wmh + (size_t)j*128*256; N=128;
        bias=g_bias2 + j*128; Cbf=g_ghb + j*128; ldc=384; break; }
    case 10: A=g_Zxf; lda=64; K=64; W=g_WfeF; N=32; bias=g_bias+OFF_FEF;
            Cbf=g_tmp; ldc=64; act=1; break;
    case 11: A=g_Zxb; lda=64; K=64; W=g_WfeB; N=32; bias=g_bias+OFF_FEB;
            Cbf=g_tmp+32; ldc=64; act=1; break;
    case 12: case 13: {
        int j = which - 12;
        A=g_tmp; lda=64; K=64; W=g_Wih + j*192*64; N=192; bias=g_bias+OFF_BIH+j*192;
        Cbf=g_gi_all + j*192; ldc=384; break; }
    default: // 14: init
        A=g_Zxf; lda=64; K=64; W=g_Winit; N=128; bias=g_bias+OFF_INIT;
        Cf=g_h; ldc=128; act=1; break;
    }

    extern __shared__ char smem[];
    unsigned smem_base = smem_u32(smem);
    int tid = threadIdx.x;
    int mtile = blockIdx.x;
    int wid = tid >> 5, lane = tid & 31;
    int m0 = (wid >> 1)*32;
    int Nw = N >> 1;
    int n0 = (wid & 1)*Nw;
    int ncCount = Nw >> 4; if (ncCount < 1) ncCount = 1;
    int lrow = lane & 7, lq8 = (lane >> 3) & 1, lkhi = lane >> 4;
    int nstages = K >> 6;

    float acc[2][6][2][4];
    #pragma unroll
    for (int mi = 0; mi < 2; mi++)
        #pragma unroll
        for (int nc = 0; nc < 6; nc++)
            #pragma unroll
            for (int sb = 0; sb < 2; sb++)
                #pragma unroll
                for (int q = 0; q < 4; q++) acc[mi][nc][sb][q] = 0.f;

    int total = 1024 + N*8;
    for (int idx = tid; idx < total; idx += 256){
        const __nv_bfloat16* src; unsigned sec; int row, col;
        if (idx < 1024){ row = idx >> 3; col = idx & 7;
            src = A + ((size_t)mtile*128 + row)*lda + col*8; sec = 0; }
        else { int i2 = idx - 1024; row = i2 >> 3; col = i2 & 7;
            src = W + (size_t)row*K + col*8; sec = 16384; }
        cp16(smem_base + sec + swz(row*128 + col*16), src);
    }
    CP_COMMIT();

    for (int s = 0; s < nstages; s++){
        int buf = s & 1;
        if (s + 1 < nstages){
            int k0 = (s+1)*64;
            unsigned base = smem_base + (buf^1)*SG_BUFSZ;
            for (int idx = tid; idx < total; idx += 256){
                const __nv_bfloat16* src; unsigned sec; int row, col;
                if (idx < 1024){ row = idx >> 3; col = idx & 7;
                    src = A + ((size_t)mtile*128 + row)*lda + k0 + col*8; sec = 0; }
                else { int i2 = idx - 1024; row = i2 >> 3; col = i2 & 7;
                    src = W + (size_t)row*K + k0 + col*8; sec = 16384; }
                cp16(base + sec + swz(row*128 + col*16), src);
            }
            CP_COMMIT();
            asm volatile("cp.async.wait_group 1;" ::: "memory");
        } else {
            CP_WAIT0();
        }
        __syncthreads();

        unsigned ab = smem_base + buf*SG_BUFSZ;
        #pragma unroll
        for (int kk = 0; kk < 4; kk++){
            unsigned a[2][4];
            #pragma unroll
            for (int mi = 0; mi < 2; mi++){
                unsigned row = m0 + mi*16 + lrow + lq8*8;
                unsigned sw = swz(row*128 + kk*32 + lkhi*16);
                ldsm4(a[mi][0], a[mi][1], a[mi][2], a[mi][3], ab + sw);
            }
            for (int nc = 0; nc < ncCount; nc++){
                unsigned row = n0 + nc*16 + lrow + lq8*8;
                unsigned sw = swz(row*128 + kk*32 + lkhi*16);
                unsigned bh[4];
                ldsm4(bh[0], bh[1], bh[2], bh[3], ab + 16384 + sw);
                #pragma unroll
                for (int mi = 0; mi < 2; mi++){
                    mma16816(acc[mi][nc][0], a[mi], bh[0], bh[2]);
                    mma16816(acc[mi][nc][1], a[mi], bh[1], bh[3]);
                }
            }
        }
        __syncthreads();
    }

    int g = lane >> 2, cpair = (lane & 3)*2;
    #pragma unroll
    for (int mi = 0; mi < 2; mi++){
        int row = mtile*128 + m0 + mi*16 + g;
        for (int nc = 0; nc < ncCount; nc++){
            #pragma unroll
            for (int sb = 0; sb < 2; sb++){
                int col = n0 + nc*16 + sb*8 + cpair;
                float b0 = bias[col], b1 = bias[col+1];
                float* cc = acc[mi][nc][sb];
                float v00 = cc[0] + b0, v01 = cc[1] + b1;
                float v10 = cc[2] + b0, v11 = cc[3] + b1;
                if (act){
                    v00 = fmaxf(v00, 0.f); v01 = fmaxf(v01, 0.f);
                    v10 = fmaxf(v10, 0.f); v11 = fmaxf(v11, 0.f);
                }
                if (Cf){
                    *(float2*)(Cf + (size_t)row*ldc + col)     = make_float2(v00, v01);
                    *(float2*)(Cf + (size_t)(row+8)*ldc + col) = make_float2(v10, v11);
                }
                if (Cbf){
                    *(__nv_bfloat162*)(Cbf + (size_t)row*ldc + col)     = __floats2bfloat162_rn(v00, v01);
                    *(__nv_bfloat162*)(Cbf + (size_t)(row+8)*ldc + col) = __floats2bfloat162_rn(v10, v11);
                }
            }
        }
    }
}

// ---------------- fused GRU gates + h transpose + history ----------------
__global__ void gru_tr_kernel(int t){
    __shared__ float tile[32][33];
    int c0 = blockIdx.x*32, f0 = blockIdx.y*32;
    int b = blockIdx.z;
    int tx = threadIdx.x, ty = threadIdx.y;
    #pragma unroll
    for (int r = 0; r < 4; r++){
        int cl = ty + r*8;
        size_t row = (size_t)b*CC + c0 + cl;
        int f = f0 + tx;
        const __nv_bfloat16* gi = g_gi_all + ((size_t)t*ROWS + row)*384;
        const __nv_bfloat16* gh = g_ghb + row*384;
        float ir = __bfloat162float(gi[f]);
        float iz = __bfloat162float(gi[128 + f]);
        float inn = __bfloat162float(gi[256 + f]);
        float hr = __bfloat162float(gh[f]);
        float hz = __bfloat162float(gh[128 + f]);
        float hn = __bfloat162float(gh[256 + f]);
        float rg = 1.f / (1.f + expf(-(ir + hr)));
        float zg = 1.f / (1.f + expf(-(iz + hz)));
        float ng = tanhf(inn + rg*hn);
        float hs = g_hsf[row*HH + f];
        float h = (1.f - zg)*ng + zg*hs;
        tile[cl][tx] = h;
        if (t >= 4) g_hist[((size_t)(t-4)*ROWS + row)*HH + f] = h;
    }
    __syncthreads();
    #pragma unroll
    for (int r = 0; r < 4; r++){
        int fl = ty + r*8;
        int f = f0 + fl, c = c0 + tx;
        g_BH[((size_t)b*HH + f)*CC + c] = __float2bfloat16(tile[tx][fl]);
    }
}

// ---------------- final: pred = hist @ outW + outb, fused mask-scatter ----------------
__global__ void __launch_bounds__(256) predout_kernel(const float* __restrict__ in,
                                                      const float* __restrict__ outW,
                                                      const float* __restrict__ outb,
                                                      float* __restrict__ out){
    __shared__ float Ws[128*32];
    __shared__ float As[64*128];
    int r0 = blockIdx.x*64;
    int tid = threadIdx.x;
    for (int i = tid; i < 128*32; i += 256) Ws[i] = outW[i];
    {
        const float4* src = (const float4*)(g_hist + (size_t)r0*HH);
        float4* dst = (float4*)As;
        for (int i = tid; i < 64*128/4; i += 256) dst[i] = src[i];
    }
    __syncthreads();

    #pragma unroll
    for (int it = 0; it < 2; it++){
        int item = tid + it*256;
        int rl = item >> 3;
        int cg = (item & 7)*4;
        float a0 = outb[cg], a1 = outb[cg+1], a2 = outb[cg+2], a3 = outb[cg+3];
        const float* Ar = As + rl*128;
        #pragma unroll 8
        for (int k = 0; k < 128; k++){
            float av = Ar[k];
            const float* wr = Ws + k*32 + cg;
            a0 += av*wr[0]; a1 += av*wr[1]; a2 += av*wr[2]; a3 += av*wr[3];
        }
        int r = r0 + rl;
        int t = r >> 13;
        int rb = r & 8191;
        int b = rb >> 10, c = rb & 1023;
        float4 v;
        if (g_mask[c])
            v = *(const float4*)(in + (((size_t)(b*TT + t + 5)*CC + c)*160) + cg);
        else
            v = make_float4(a0, a1, a2, a3);
        *(float4*)(out + (((size_t)(b*SS + t)*CC + c)*DST) + cg) = v;
    }
}

// ---------------- host orchestration ----------------
static __nv_bfloat16* symb(const void* s){ void* p = nullptr; cudaGetSymbolAddress(&p, s); return (__nv_bfloat16*)p; }

extern "C" void kernel_launch(void* const* d_in, const int* in_sizes, int n_in,
                              void* d_out, int out_size)
{
    const float* inputs   = (const float*)d_in[0];
    const float* adj      = (const float*)d_in[1];
    const float* init_W   = (const float*)d_in[2];
    const float* init_b   = (const float*)d_in[3];
    const float* fe_fwd_W = (const float*)d_in[4];
    const float* fe_fwd_b = (const float*)d_in[5];
    const float* fe_bwd_W = (const float*)d_in[6];
    const float* fe_bwd_b = (const float*)d_in[7];
    const float* fwd_W    = (const float*)d_in[8];
    const float* fwd_b    = (const float*)d_in[9];
    const float* bwd_W    = (const float*)d_in[10];
    const float* bwd_b    = (const float*)d_in[11];
    const float* merge_W  = (const float*)d_in[12];
    const float* merge_b  = (const float*)d_in[13];
    const float* gru_Wih  = (const float*)d_in[14];
    const float* gru_bih  = (const float*)d_in[15];
    const float* gru_Whh  = (const float*)d_in[16];
    const float* gru_bhh  = (const float*)d_in[17];
    const float* out_W    = (const float*)d_in[18];
    const float* out_b    = (const float*)d_in[19];
    const int*   cells    = (const int*)  d_in[20];
    float* out = (float*)d_out;

    cudaFuncSetAttribute(propx_kernel, cudaFuncAttributeMaxDynamicSharedMemorySize, PX_SMEM);
    cudaFuncSetAttribute(proph_kernel, cudaFuncAttributeMaxDynamicSharedMemorySize, PH_SMEM);
    cudaFuncSetAttribute(sgemm_kernel, cudaFuncAttributeMaxDynamicSharedMemorySize, SG_SMEM);

    // ---- prolog ----
    rowsum_kernel<<<TT*CC/8, 256>>>(adj);
    colsum_kernel<<<dim3(4, TT), 256>>>(adj);
    build_L_kernel<<<dim3(CC/32, CC/32, TT), dim3(32, 8)>>>(adj);
    build_BX_kernel<<<dim3(CC/32, FIN/32, BB*TT), dim3(32, 8)>>>(inputs);
    mask_init_kernel<<<4, 256>>>();
    int nic = in_sizes[20];
    mask_set_kernel<<<(nic + 255)/256, 256>>>(cells, nic);

    wconv_kernel<<<(128*64 + 255)/256, 256>>>(init_W,  symb(g_Winit), 64, 128);
    wconv_kernel<<<(32*64 + 255)/256, 256>>>(fe_fwd_W, symb(g_WfeF),  64, 32);
    wconv_kernel<<<(32*64 + 255)/256, 256>>>(fe_bwd_W, symb(g_WfeB),  64, 32);
    wconv_kernel<<<(128*128 + 255)/256, 256>>>(fwd_W,  symb(g_Wfwd),  128, 128);
    wconv_kernel<<<(128*128 + 255)/256, 256>>>(bwd_W,  symb(g_Wbwd),  128, 128);
    wconv_kernel<<<(128*256 + 255)/256, 256>>>(merge_W,symb(g_Wmerge),256, 128);
    wconv_kernel<<<(384*64 + 255)/256, 256>>>(gru_Wih, symb(g_Wih),   64, 384);
    compose_kernel<<<(384*256 + 255)/256, 256>>>(merge_W, gru_Whh, merge_b, gru_bhh);
    bias_copy_kernel<<<2, 256>>>(init_b, fe_fwd_b, fe_bwd_b, fwd_b, bwd_b, merge_b,
                                 gru_bih);

    // ---- x-dependent precompute ----
    propx_kernel<<<dim3(BB, 8, NT*2), 256, PX_SMEM>>>();
    sgemm_kernel<<<dim3(NT*64, 2), 256, SG_SMEM>>>(10);   // fe fwd+bwd -> tmp
    sgemm_kernel<<<dim3(NT*64, 2), 256, SG_SMEM>>>(12);   // gi
    sgemm_kernel<<<dim3(64, 1), 256, SG_SMEM>>>(14);      // hidden0
    transpose_h_kernel<<<dim3(CC/32, HH/32, BB), dim3(32, 8)>>>();

    // ---- scan: 4 kernels per step, hs+gh parallel ----
    for (int t = 0; t < NT; t++){
        proph_kernel<<<dim3(BB, 32), 256, PH_SMEM>>>(t);
        sgemm_kernel<<<dim3(64, 2), 256, SG_SMEM>>>(0);   // fwd, bwd -> gcat
        sgemm_kernel<<<dim3(64, 4), 256, SG_SMEM>>>(2);   // hs + gh(3 chunks), one launch
        gru_tr_kernel<<<dim3(32, 4, BB), dim3(32, 8)>>>(t);
    }

    // ---- output ----
    predout_kernel<<<SS*ROWS/64, 256>>>(inputs, out_W, out_b, out);
}

// round 15
// speedup vs baseline: 1.2103x; 1.0869x over previous
#include <cuda_runtime.h>
#include <cuda_bf16.h>
#include <math.h>

#define BB 8
#define TT 32
#define CC 1024
#define HH 128
#define DST 32
#define FIN 64
#define SS 27            // T - INIT_LENGTH - 1
#define NT 31            // scan steps
#define ROWS (BB*CC)     // 8192

// ================= warp-MMA helpers =================
__device__ __forceinline__ unsigned smem_u32(const void* p){
    unsigned a;
    asm("{ .reg .u64 t; cvta.to.shared.u64 t, %1; cvt.u32.u64 %0, t; }" : "=r"(a) : "l"(p));
    return a;
}

__device__ __forceinline__ void ldsm4(unsigned& r0, unsigned& r1, unsigned& r2, unsigned& r3,
                                      unsigned addr){
    asm volatile("ldmatrix.sync.aligned.m8n8.x4.shared.b16 {%0,%1,%2,%3}, [%4];"
                 : "=r"(r0), "=r"(r1), "=r"(r2), "=r"(r3) : "r"(addr));
}

__device__ __forceinline__ void mma16816(float* c, const unsigned* a, unsigned b0, unsigned b1){
    asm volatile("mma.sync.aligned.m16n8k16.row.col.f32.bf16.bf16.f32 "
                 "{%0,%1,%2,%3}, {%4,%5,%6,%7}, {%8,%9}, {%0,%1,%2,%3};"
                 : "+f"(c[0]), "+f"(c[1]), "+f"(c[2]), "+f"(c[3])
                 : "r"(a[0]), "r"(a[1]), "r"(a[2]), "r"(a[3]), "r"(b0), "r"(b1));
}

__device__ __forceinline__ void cp16(unsigned dst, const void* src){
    asm volatile("cp.async.cg.shared.global [%0], [%1], 16;"
                 :: "r"(dst), "l"(__cvta_generic_to_global(src)));
}
#define CP_COMMIT() asm volatile("cp.async.commit_group;" ::: "memory")
#define CP_WAIT0()  asm volatile("cp.async.wait_group 0;" ::: "memory")

__device__ __forceinline__ unsigned swz(unsigned boff){
    return boff ^ ((boff >> 3) & 0x70);
}

// load rows x K bf16 matrix into k-panel smem layout (panel = 64 k, swizzled 128B rows)
template<int RM, int KD>
__device__ __forceinline__ void load_mat(unsigned dst, const __nv_bfloat16* src, int ld, int tid){
    constexpr int UPR = KD/8;
    constexpr int UNITS = RM*UPR;
    for (int u = tid; u < UNITS; u += 256){
        int row = u / UPR, k8 = u % UPR;
        int kp = k8 >> 3, kc8 = k8 & 7;
        cp16(dst + kp*(RM*128) + swz(row*128 + kc8*16),
             src + (size_t)row*ld + kp*64 + kc8*8);
    }
}

// ---------------- device scratch ----------------
__device__ __nv_bfloat16 g_Lf[(size_t)TT*CC*CC];
__device__ __nv_bfloat16 g_Lb[(size_t)TT*CC*CC];
__device__ __nv_bfloat16 g_BX[(size_t)BB*TT*FIN*CC];   // [b][t][f][c]
__device__ __nv_bfloat16 g_BH[(size_t)BB*HH*CC];       // [b][f][c]

__device__ __nv_bfloat16 g_Zxf[(size_t)NT*ROWS*64];
__device__ __nv_bfloat16 g_Zxb[(size_t)NT*ROWS*64];
__device__ __nv_bfloat16 g_tmp[(size_t)NT*ROWS*64];
__device__ __nv_bfloat16 g_gi_all[(size_t)NT*ROWS*384];
__device__ __nv_bfloat16 g_gcat[(size_t)ROWS*256];
__device__ float         g_hsf[(size_t)ROWS*HH];
__device__ __nv_bfloat16 g_ghb[(size_t)ROWS*384];
__device__ float         g_hist[(size_t)SS*ROWS*HH];
__device__ float         g_h[(size_t)ROWS*HH];
__device__ float         g_dinvf[TT*CC];
__device__ float         g_dinvb[TT*CC];
__device__ int           g_mask[CC];

// weights bf16 [N][K]
__device__ __nv_bfloat16 g_Winit[128*64];
__device__ __nv_bfloat16 g_WfeF[32*64];
__device__ __nv_bfloat16 g_WfeB[32*64];
__device__ __nv_bfloat16 g_Wfwd[128*128];
__device__ __nv_bfloat16 g_Wbwd[128*128];
__device__ __nv_bfloat16 g_Wmerge[128*256];
__device__ __nv_bfloat16 g_Wmh[384*256];     // (Wmerge @ Whh)^T, bf16 [N][K]
__device__ __nv_bfloat16 g_Wih[384*64];
__device__ float         g_bias2[384];       // bm @ Whh + bhh

#define OFF_INIT  0
#define OFF_FEF   128
#define OFF_FEB   160
#define OFF_FWD   192
#define OFF_BWD   320
#define OFF_MERGE 448
#define OFF_BIH   576
__device__ float g_bias[960];

// ---------------- prolog kernels ----------------
__global__ void rowsum_kernel(const float* __restrict__ adj){
    int warp = (blockIdx.x*blockDim.x + threadIdx.x) >> 5;
    int lane = threadIdx.x & 31;
    if (warp >= TT*CC) return;
    const float* row = adj + (size_t)warp*CC;
    float s = 0.f;
    for (int j = lane; j < CC; j += 32) s += row[j];
    #pragma unroll
    for (int o = 16; o; o >>= 1) s += __shfl_xor_sync(0xffffffffu, s, o);
    if (!lane) g_dinvf[warp] = 1.0f / sqrtf(s + 1.0f);
}

__global__ void colsum_kernel(const float* __restrict__ adj){
    int t = blockIdx.y;
    int i = blockIdx.x*blockDim.x + threadIdx.x;
    const float* base = adj + (size_t)t*CC*CC + i;
    float s = 0.f;
    for (int j = 0; j < CC; j++) s += base[(size_t)j*CC];
    g_dinvb[t*CC + i] = 1.0f / sqrtf(s + 1.0f);
}

__global__ void build_L_kernel(const float* __restrict__ adj){
    __shared__ float tile[32][33];
    int t = blockIdx.z;
    int i0 = blockIdx.y*32, j0 = blockIdx.x*32;
    int tx = threadIdx.x, ty = threadIdx.y;
    const float* df = g_dinvf + t*CC;
    const float* db = g_dinvb + t*CC;
    #pragma unroll
    for (int r = 0; r < 4; r++){
        int li = ty + r*8;
        int i = i0 + li, j = j0 + tx;
        float v = adj[((size_t)t*CC + i)*CC + j] + ((i == j) ? 1.f : 0.f);
        g_Lf[((size_t)t*CC + i)*CC + j] = __float2bfloat16(v * df[i] * df[j]);
        tile[li][tx] = v * db[i] * db[j];
    }
    __syncthreads();
    #pragma unroll
    for (int r = 0; r < 4; r++){
        int lj = ty + r*8;
        int p = j0 + lj, q = i0 + tx;
        g_Lb[((size_t)t*CC + p)*CC + q] = __float2bfloat16(tile[tx][lj]);
    }
}

__global__ void build_BX_kernel(const float* __restrict__ in){
    __shared__ float tile[32][33];
    int c0 = blockIdx.x*32, f0 = blockIdx.y*32;
    int bt = blockIdx.z;
    int tx = threadIdx.x, ty = threadIdx.y;
    #pragma unroll
    for (int r = 0; r < 4; r++){
        int c = c0 + ty + r*8;
        int f = f0 + tx;
        int col = (f < 32) ? f : 96 + f;
        tile[ty + r*8][tx] = in[(((size_t)bt*CC) + c)*160 + col];
    }
    __syncthreads();
    #pragma unroll
    for (int r = 0; r < 4; r++){
        int f = f0 + ty + r*8;
        int c = c0 + tx;
        g_BX[(((size_t)bt*FIN) + f)*CC + c] = __float2bfloat16(tile[tx][ty + r*8]);
    }
}

__global__ void transpose_h_kernel(){
    __shared__ float tile[32][33];
    int c0 = blockIdx.x*32, f0 = blockIdx.y*32;
    int b = blockIdx.z;
    int tx = threadIdx.x, ty = threadIdx.y;
    #pragma unroll
    for (int r = 0; r < 4; r++){
        int c = c0 + ty + r*8;
        int f = f0 + tx;
        tile[ty + r*8][tx] = g_h[((size_t)b*CC + c)*HH + f];
    }
    __syncthreads();
    #pragma unroll
    for (int r = 0; r < 4; r++){
        int f = f0 + ty + r*8;
        int c = c0 + tx;
        g_BH[((size_t)b*HH + f)*CC + c] = __float2bfloat16(tile[tx][ty + r*8]);
    }
}

__global__ void mask_init_kernel(){
    int i = blockIdx.x*blockDim.x + threadIdx.x;
    if (i < CC) g_mask[i] = 0;
}
__global__ void mask_set_kernel(const int* __restrict__ cells, int n){
    int i = blockIdx.x*blockDim.x + threadIdx.x;
    if (i < n) g_mask[cells[i]] = 1;
}

__global__ void wconv_kernel(const float* __restrict__ W, __nv_bfloat16* w, int K, int N){
    int idx = blockIdx.x*blockDim.x + threadIdx.x;
    if (idx >= N*K) return;
    int n = idx / K, k = idx - n*K;
    w[idx] = __float2bfloat16(W[(size_t)k*N + n]);
}

// Wmh[n][k] = sum_j Wmerge[k][j] * Whh[j][n]; bias2[n] = sum_j bm[j]*Whh[j][n] + bhh[n]
__global__ void compose_kernel(const float* __restrict__ Wm, const float* __restrict__ Whh,
                               const float* __restrict__ bm, const float* __restrict__ bhh){
    int idx = blockIdx.x*blockDim.x + threadIdx.x;
    if (idx < 384*256){
        int n = idx >> 8, k = idx & 255;
        float s = 0.f;
        #pragma unroll 8
        for (int j = 0; j < 128; j++) s += Wm[k*128 + j]*Whh[(size_t)j*384 + n];
        g_Wmh[(size_t)n*256 + k] = __float2bfloat16(s);
    }
    if (idx < 384){
        float s = bhh[idx];
        for (int j = 0; j < 128; j++) s += bm[j]*Whh[(size_t)j*384 + idx];
        g_bias2[idx] = s;
    }
}

__global__ void bias_copy_kernel(const float* initb, const float* fef, const float* feb,
                                 const float* fwd, const float* bwd, const float* merge,
                                 const float* bih){
    int i = blockIdx.x*blockDim.x + threadIdx.x;
    if (i < 128){
        g_bias[OFF_INIT + i] = initb[i];
        g_bias[OFF_FWD + i]  = fwd[i];
        g_bias[OFF_BWD + i]  = bwd[i];
        g_bias[OFF_MERGE + i]= merge[i];
    }
    if (i < 32){
        g_bias[OFF_FEF + i] = fef[i];
        g_bias[OFF_FEB + i] = feb[i];
    }
    if (i < 384) g_bias[OFF_BIH + i] = bih[i];
}

// ================ x-propagation: Zx = L @ BX  (M=128, N=64) ================
#define PX_BUFSZ (16384 + 64*128)
#define PX_SMEM  (2*PX_BUFSZ)

__global__ void __launch_bounds__(256) propx_kernel(){
    constexpr int NB = 64;
    constexpr int NCC = NB/32;
    constexpr int TOTAL = 1024 + NB*8;
    extern __shared__ char smem[];
    unsigned smem_base = smem_u32(smem);
    int tid = threadIdx.x;
    int b = blockIdx.x;
    int mtile = blockIdx.y;
    int t = blockIdx.z >> 1;
    int dir = blockIdx.z & 1;

    const __nv_bfloat16* L = (dir ? g_Lb : g_Lf) + (size_t)t*CC*CC + (size_t)mtile*128*CC;
    const __nv_bfloat16* Bsrc = g_BX + (size_t)(b*TT + t)*FIN*CC;
    __nv_bfloat16* Zdst = (dir ? g_Zxb : g_Zxf) + ((size_t)t*ROWS + b*CC + mtile*128)*64;

    int wid = tid >> 5, lane = tid & 31;
    int m0 = (wid >> 1)*32;
    int n0 = (wid & 1)*(NB/2);
    int lrow = lane & 7, lq8 = (lane >> 3) & 1, lkhi = lane >> 4;

    float acc[2][NCC][2][4];
    #pragma unroll
    for (int mi = 0; mi < 2; mi++)
        #pragma unroll
        for (int nc = 0; nc < NCC; nc++)
            #pragma unroll
            for (int sb = 0; sb < 2; sb++)
                #pragma unroll
                for (int q = 0; q < 4; q++) acc[mi][nc][sb][q] = 0.f;

    {
        #pragma unroll
        for (int it = 0; it < TOTAL/256; it++){
            int idx = tid + it*256;
            const __nv_bfloat16* src; unsigned sec; int row, col;
            if (idx < 1024){ row = idx >> 3; col = idx & 7; src = L + (size_t)row*CC + col*8; sec = 0; }
            else { int i2 = idx - 1024; row = i2 >> 3; col = i2 & 7; src = Bsrc + (size_t)row*CC + col*8; sec = 16384; }
            cp16(smem_base + sec + swz(row*128 + col*16), src);
        }
        CP_COMMIT();
    }

    for (int s = 0; s < 16; s++){
        int buf = s & 1;
        if (s + 1 < 16){
            int k0 = (s+1)*64;
            unsigned base = smem_base + (buf^1)*PX_BUFSZ;
            #pragma unroll
            for (int it = 0; it < TOTAL/256; it++){
                int idx = tid + it*256;
                const __nv_bfloat16* src; unsigned sec; int row, col;
                if (idx < 1024){ row = idx >> 3; col = idx & 7; src = L + (size_t)row*CC + k0 + col*8; sec = 0; }
                else { int i2 = idx - 1024; row = i2 >> 3; col = i2 & 7; src = Bsrc + (size_t)row*CC + k0 + col*8; sec = 16384; }
                cp16(base + sec + swz(row*128 + col*16), src);
            }
            CP_COMMIT();
            asm volatile("cp.async.wait_group 1;" ::: "memory");
        } else {
            CP_WAIT0();
        }
        __syncthreads();

        unsigned ab = smem_base + buf*PX_BUFSZ;
        #pragma unroll
        for (int kk = 0; kk < 4; kk++){
            unsigned a[2][4];
            #pragma unroll
            for (int mi = 0; mi < 2; mi++){
                unsigned row = m0 + mi*16 + lrow + lq8*8;
                unsigned sw = swz(row*128 + kk*32 + lkhi*16);
                ldsm4(a[mi][0], a[mi][1], a[mi][2], a[mi][3], ab + sw);
            }
            #pragma unroll
            for (int nc = 0; nc < NCC; nc++){
                unsigned row = n0 + nc*16 + lrow + lq8*8;
                unsigned sw = swz(row*128 + kk*32 + lkhi*16);
                unsigned bh[4];
                ldsm4(bh[0], bh[1], bh[2], bh[3], ab + 16384 + sw);
                #pragma unroll
                for (int mi = 0; mi < 2; mi++){
                    mma16816(acc[mi][nc][0], a[mi], bh[0], bh[2]);
                    mma16816(acc[mi][nc][1], a[mi], bh[1], bh[3]);
                }
            }
        }
        __syncthreads();
    }

    int g = lane >> 2, cpair = (lane & 3)*2;
    #pragma unroll
    for (int mi = 0; mi < 2; mi++){
        int row = m0 + mi*16 + g;
        #pragma unroll
        for (int nc = 0; nc < NCC; nc++){
            #pragma unroll
            for (int sb = 0; sb < 2; sb++){
                int col = n0 + nc*16 + sb*8 + cpair;
                float* cc = acc[mi][nc][sb];
                *(__nv_bfloat162*)(Zdst + (size_t)row*64 + col) =
                    __floats2bfloat162_rn(cc[0], cc[1]);
                *(__nv_bfloat162*)(Zdst + (size_t)(row+8)*64 + col) =
                    __floats2bfloat162_rn(cc[2], cc[3]);
            }
        }
    }
}

// ================ fused h-prop + GCN: gcat = relu((L @ BH) @ W + b) ================
// grid (b=8, y=dir*16+mtile); CTA = 64 L-rows, full N=128.
// smem: buf0[0,24576) buf1[24576,49152) W[49152,81920); Zh tile reuses buf0.
#define PH_BUFSZ 24576
#define PH_W     49152
#define PH_SMEM  81920

__global__ void __launch_bounds__(256, 2) proph_kernel(int t){
    extern __shared__ char smem[];
    unsigned smem_base = smem_u32(smem);
    int tid = threadIdx.x;
    int b = blockIdx.x;
    int mtile = blockIdx.y & 15;
    int dir = blockIdx.y >> 4;

    const __nv_bfloat16* L = (dir ? g_Lb : g_Lf) + (size_t)t*CC*CC + (size_t)mtile*64*CC;
    const __nv_bfloat16* Bsrc = g_BH + (size_t)b*HH*CC;
    const __nv_bfloat16* Wsrc = dir ? g_Wbwd : g_Wfwd;
    const float* bias = g_bias + (dir ? OFF_BWD : OFF_FWD);
    __nv_bfloat16* Gdst = g_gcat + ((size_t)(b*CC + mtile*64))*256 + dir*128;

    int wid = tid >> 5, lane = tid & 31;
    int m0 = (wid & 1)*32;
    int n0 = (wid >> 1)*32;
    int lrow = lane & 7, lq8 = (lane >> 3) & 1, lkhi = lane >> 4;
    int g = lane >> 2, cpair = (lane & 3)*2;

    float acc[2][2][2][4];
    #pragma unroll
    for (int mi = 0; mi < 2; mi++)
        #pragma unroll
        for (int nc = 0; nc < 2; nc++)
            #pragma unroll
            for (int sb = 0; sb < 2; sb++)
                #pragma unroll
                for (int q = 0; q < 4; q++) acc[mi][nc][sb][q] = 0.f;

    // stage 0 + W prefetch (one commit group; W completes during early stages)
    {
        load_mat<128,128>(smem_base + PH_W, Wsrc, 128, tid);
        #pragma unroll
        for (int it = 0; it < 6; it++){
            int idx = tid + it*256;
            const __nv_bfloat16* src; unsigned sec; int row, col;
            if (idx < 512){ row = idx >> 3; col = idx & 7; src = L + (size_t)row*CC + col*8; sec = 0; }
            else { int i2 = idx - 512; row = i2 >> 3; col = i2 & 7; src = Bsrc + (size_t)row*CC + col*8; sec = 8192; }
            cp16(smem_base + sec + swz(row*128 + col*16), src);
        }
        CP_COMMIT();
    }

    for (int s = 0; s < 16; s++){
        int buf = s & 1;
        if (s + 1 < 16){
            int k0 = (s+1)*64;
            unsigned base = smem_base + (buf^1)*PH_BUFSZ;
            #pragma unroll
            for (int it = 0; it < 6; it++){
                int idx = tid + it*256;
                const __nv_bfloat16* src; unsigned sec; int row, col;
                if (idx < 512){ row = idx >> 3; col = idx & 7; src = L + (size_t)row*CC + k0 + col*8; sec = 0; }
                else { int i2 = idx - 512; row = i2 >> 3; col = i2 & 7; src = Bsrc + (size_t)row*CC + k0 + col*8; sec = 8192; }
                cp16(base + sec + swz(row*128 + col*16), src);
            }
            CP_COMMIT();
            asm volatile("cp.async.wait_group 1;" ::: "memory");
        } else {
            CP_WAIT0();
        }
        __syncthreads();

        unsigned ab = smem_base + buf*PH_BUFSZ;
        #pragma unroll
        for (int kk = 0; kk < 4; kk++){
            unsigned a[2][4];
            #pragma unroll
            for (int mi = 0; mi < 2; mi++){
                unsigned row = m0 + mi*16 + lrow + lq8*8;
                unsigned sw = swz(row*128 + kk*32 + lkhi*16);
                ldsm4(a[mi][0], a[mi][1], a[mi][2], a[mi][3], ab + sw);
            }
            #pragma unroll
            for (int nc = 0; nc < 2; nc++){
                unsigned row = n0 + nc*16 + lrow + lq8*8;
                unsigned sw = swz(row*128 + kk*32 + lkhi*16);
                unsigned bh[4];
                ldsm4(bh[0], bh[1], bh[2], bh[3], ab + 8192 + sw);
                #pragma unroll
                for (int mi = 0; mi < 2; mi++){
                    mma16816(acc[mi][nc][0], a[mi], bh[0], bh[2]);
                    mma16816(acc[mi][nc][1], a[mi], bh[1], bh[3]);
                }
            }
        }
        __syncthreads();
    }

    // ---- spill Zh (bf16) into buf0 as k-panel [64 rows][128 k] ----
    {
        unsigned zb = smem_base;   // buf0 reuse
        #pragma unroll
        for (int mi = 0; mi < 2; mi++){
            int row = m0 + mi*16 + g;
            #pragma unroll
            for (int nc = 0; nc < 2; nc++){
                #pragma unroll
                for (int sb = 0; sb < 2; sb++){
                    int col = n0 + nc*16 + sb*8 + cpair;
                    int kp = col >> 6, kc = col & 63;
                    float* cc = acc[mi][nc][sb];
                    *(__nv_bfloat162*)(smem + (zb - smem_base) + kp*8192 + swz(row*128 + kc*2)) =
                        __floats2bfloat162_rn(cc[0], cc[1]);
                    *(__nv_bfloat162*)(smem + (zb - smem_base) + kp*8192 + swz((row+8)*128 + kc*2)) =
                        __floats2bfloat162_rn(cc[2], cc[3]);
                }
            }
        }
    }
    __syncthreads();

    // ---- second GEMM: gcat_tile = relu(Zh @ W + bias), M=64 N=128 K=128 ----
    {
        float acc2[2][2][2][4];
        #pragma unroll
        for (int mi = 0; mi < 2; mi++)
            #pragma unroll
            for (int nc = 0; nc < 2; nc++)
                #pragma unroll
                for (int sb = 0; sb < 2; sb++)
                    #pragma unroll
                    for (int q = 0; q < 4; q++) acc2[mi][nc][sb][q] = 0.f;

        #pragma unroll
        for (int s = 0; s < 2; s++){
            unsigned aP = smem_base + s*8192;
            unsigned wP = smem_base + PH_W + s*16384;
            #pragma unroll
            for (int kk = 0; kk < 4; kk++){
                unsigned a[2][4];
                #pragma unroll
                for (int mi = 0; mi < 2; mi++){
                    unsigned row = m0 + mi*16 + lrow + lq8*8;
                    ldsm4(a[mi][0], a[mi][1], a[mi][2], a[mi][3],
                          aP + swz(row*128 + kk*32 + lkhi*16));
                }
                #pragma unroll
                for (int nc = 0; nc < 2; nc++){
                    unsigned row = n0 + nc*16 + lrow + lq8*8;
                    unsigned bh[4];
                    ldsm4(bh[0], bh[1], bh[2], bh[3], wP + swz(row*128 + kk*32 + lkhi*16));
                    #pragma unroll
                    for (int mi = 0; mi < 2; mi++){
                        mma16816(acc2[mi][nc][0], a[mi], bh[0], bh[2]);
                        mma16816(acc2[mi][nc][1], a[mi], bh[1], bh[3]);
                    }
                }
            }
        }
        #pragma unroll
        for (int mi = 0; mi < 2; mi++){
            int row = m0 + mi*16 + g;
            #pragma unroll
            for (int nc = 0; nc < 2; nc++){
                #pragma unroll
                for (int sb = 0; sb < 2; sb++){
                    int col = n0 + nc*16 + sb*8 + cpair;
                    float b0 = bias[col], b1 = bias[col+1];
                    float* cc = acc2[mi][nc][sb];
                    float v00 = fmaxf(cc[0]+b0, 0.f), v01 = fmaxf(cc[1]+b1, 0.f);
                    float v10 = fmaxf(cc[2]+b0, 0.f), v11 = fmaxf(cc[3]+b1, 0.f);
                    *(__nv_bfloat162*)(Gdst + (size_t)row*256 + col) =
                        __floats2bfloat162_rn(v00, v01);
                    *(__nv_bfloat162*)(Gdst + (size_t)(row+8)*256 + col) =
                        __floats2bfloat162_rn(v10, v11);
                }
            }
        }
    }
}

// ================ generic bf16 HMMA GEMM (task table) ================
// Loop tasks: 2=hs(gcat@Wmerge), 3..5=gh chunks (gcat@Wmh_j)
// Precompute: 10=feF, 11=feB, 12/13=gi, 14=init
#define SG_BUFSZ 40960
#define SG_SMEM  (2*SG_BUFSZ)

__global__ void __launch_bounds__(256) sgemm_kernel(int basecfg){
    int which = basecfg + blockIdx.y;
    const __nv_bfloat16 *A, *W;
    int lda, K, N, ldc, act = 0;
    const float* bias;
    float* Cf = nullptr;
    __nv_bfloat16 *Cbf = nullptr;

    switch (which){
    case 2: A=g_gcat; lda=256; K=256; W=g_Wmerge; N=128; bias=g_bias+OFF_MERGE;
            Cf=g_hsf; ldc=128; break;
    case 3: case 4: case 5: {
        int j = which - 3;
        A=g_gcat; lda=256; K=256; W=g_Wmh + (size_t)j*128*256; N=128;
        bias=g_bias2 + j*128; Cbf=g_ghb + j*128; ldc=384; break; }
    case 10: A=g_Zxf; lda=64; K=64; W=g_WfeF; N=32; bias=g_bias+OFF_FEF;
            Cbf=g_tmp; ldc=64; act=1; break;
    case 11: A=g_Zxb; lda=64; K=64; W=g_WfeB; N=32; bias=g_bias+OFF_FEB;
            Cbf=g_tmp+32; ldc=64; act=1; break;
    case 12: case 13: {
        int j = which - 12;
        A=g_tmp; lda=64; K=64; W=g_Wih + j*192*64; N=192; bias=g_bias+OFF_BIH+j*192;
        Cbf=g_gi_all + j*192; ldc=384; break; }
    default: // 14: init
        A=g_Zxf; lda=64; K=64; W=g_Winit; N=128; bias=g_bias+OFF_INIT;
        Cf=g_h; ldc=128; act=1; break;
    }

    extern __shared__ char smem[];
    unsigned smem_base = smem_u32(smem);
    int tid = threadIdx.x;
    int mtile = blockIdx.x;
    int wid = tid >> 5, lane = tid & 31;
    int m0 = (wid >> 1)*32;
    int Nw = N >> 1;
    int n0 = (wid & 1)*Nw;
    int ncCount = Nw >> 4; if (ncCount < 1) ncCount = 1;
    int lrow = lane & 7, lq8 = (lane >> 3) & 1, lkhi = lane >> 4;
    int nstages = K >> 6;

    float acc[2][6][2][4];
    #pragma unroll
    for (int mi = 0; mi < 2; mi++)
        #pragma unroll
        for (int nc = 0; nc < 6; nc++)
            #pragma unroll
            for (int sb = 0; sb < 2; sb++)
                #pragma unroll
                for (int q = 0; q < 4; q++) acc[mi][nc][sb][q] = 0.f;

    int total = 1024 + N*8;
    for (int idx = tid; idx < total; idx += 256){
        const __nv_bfloat16* src; unsigned sec; int row, col;
        if (idx < 1024){ row = idx >> 3; col = idx & 7;
            src = A + ((size_t)mtile*128 + row)*lda + col*8; sec = 0; }
        else { int i2 = idx - 1024; row = i2 >> 3; col = i2 & 7;
            src = W + (size_t)row*K + col*8; sec = 16384; }
        cp16(smem_base + sec + swz(row*128 + col*16), src);
    }
    CP_COMMIT();

    for (int s = 0; s < nstages; s++){
        int buf = s & 1;
        if (s + 1 < nstages){
            int k0 = (s+1)*64;
            unsigned base = smem_base + (buf^1)*SG_BUFSZ;
            for (int idx = tid; idx < total; idx += 256){
                const __nv_bfloat16* src; unsigned sec; int row, col;
                if (idx < 1024){ row = idx >> 3; col = idx & 7;
                    src = A + ((size_t)mtile*128 + row)*lda + k0 + col*8; sec = 0; }
                else { int i2 = idx - 1024; row = i2 >> 3; col = i2 & 7;
                    src = W + (size_t)row*K + k0 + col*8; sec = 16384; }
                cp16(base + sec + swz(row*128 + col*16), src);
            }
            CP_COMMIT();
            asm volatile("cp.async.wait_group 1;" ::: "memory");
        } else {
            CP_WAIT0();
        }
        __syncthreads();

        unsigned ab = smem_base + buf*SG_BUFSZ;
        #pragma unroll
        for (int kk = 0; kk < 4; kk++){
            unsigned a[2][4];
            #pragma unroll
            for (int mi = 0; mi < 2; mi++){
                unsigned row = m0 + mi*16 + lrow + lq8*8;
                unsigned sw = swz(row*128 + kk*32 + lkhi*16);
                ldsm4(a[mi][0], a[mi][1], a[mi][2], a[mi][3], ab + sw);
            }
            for (int nc = 0; nc < ncCount; nc++){
                unsigned row = n0 + nc*16 + lrow + lq8*8;
                unsigned sw = swz(row*128 + kk*32 + lkhi*16);
                unsigned bh[4];
                ldsm4(bh[0], bh[1], bh[2], bh[3], ab + 16384 + sw);
                #pragma unroll
                for (int mi = 0; mi < 2; mi++){
                    mma16816(acc[mi][nc][0], a[mi], bh[0], bh[2]);
                    mma16816(acc[mi][nc][1], a[mi], bh[1], bh[3]);
                }
            }
        }
        __syncthreads();
    }

    int g = lane >> 2, cpair = (lane & 3)*2;
    #pragma unroll
    for (int mi = 0; mi < 2; mi++){
        int row = mtile*128 + m0 + mi*16 + g;
        for (int nc = 0; nc < ncCount; nc++){
            #pragma unroll
            for (int sb = 0; sb < 2; sb++){
                int col = n0 + nc*16 + sb*8 + cpair;
                float b0 = bias[col], b1 = bias[col+1];
                float* cc = acc[mi][nc][sb];
                float v00 = cc[0] + b0, v01 = cc[1] + b1;
                float v10 = cc[2] + b0, v11 = cc[3] + b1;
                if (act){
                    v00 = fmaxf(v00, 0.f); v01 = fmaxf(v01, 0.f);
                    v10 = fmaxf(v10, 0.f); v11 = fmaxf(v11, 0.f);
                }
                if (Cf){
                    *(float2*)(Cf + (size_t)row*ldc + col)     = make_float2(v00, v01);
                    *(float2*)(Cf + (size_t)(row+8)*ldc + col) = make_float2(v10, v11);
                }
                if (Cbf){
                    *(__nv_bfloat162*)(Cbf + (size_t)row*ldc + col)     = __floats2bfloat162_rn(v00, v01);
                    *(__nv_bfloat162*)(Cbf + (size_t)(row+8)*ldc + col) = __floats2bfloat162_rn(v10, v11);
                }
            }
        }
    }
}

// ---------------- fused GRU gates + h transpose + history ----------------
__global__ void gru_tr_kernel(int t){
    __shared__ float tile[32][33];
    int c0 = blockIdx.x*32, f0 = blockIdx.y*32;
    int b = blockIdx.z;
    int tx = threadIdx.x, ty = threadIdx.y;
    #pragma unroll
    for (int r = 0; r < 4; r++){
        int cl = ty + r*8;
        size_t row = (size_t)b*CC + c0 + cl;
        int f = f0 + tx;
        const __nv_bfloat16* gi = g_gi_all + ((size_t)t*ROWS + row)*384;
        const __nv_bfloat16* gh = g_ghb + row*384;
        float ir = __bfloat162float(gi[f]);
        float iz = __bfloat162float(gi[128 + f]);
        float inn = __bfloat162float(gi[256 + f]);
        float hr = __bfloat162float(gh[f]);
        float hz = __bfloat162float(gh[128 + f]);
        float hn = __bfloat162float(gh[256 + f]);
        float rg = 1.f / (1.f + expf(-(ir + hr)));
        float zg = 1.f / (1.f + expf(-(iz + hz)));
        float ng = tanhf(inn + rg*hn);
        float hs = g_hsf[row*HH + f];
        float h = (1.f - zg)*ng + zg*hs;
        tile[cl][tx] = h;
        if (t >= 4) g_hist[((size_t)(t-4)*ROWS + row)*HH + f] = h;
    }
    __syncthreads();
    #pragma unroll
    for (int r = 0; r < 4; r++){
        int fl = ty + r*8;
        int f = f0 + fl, c = c0 + tx;
        g_BH[((size_t)b*HH + f)*CC + c] = __float2bfloat16(tile[tx][fl]);
    }
}

// ---------------- final: pred = hist @ outW + outb, fused mask-scatter ----------------
__global__ void __launch_bounds__(256) predout_kernel(const float* __restrict__ in,
                                                      const float* __restrict__ outW,
                                                      const float* __restrict__ outb,
                                                      float* __restrict__ out){
    __shared__ float Ws[128*32];
    __shared__ float As[64*128];
    int r0 = blockIdx.x*64;
    int tid = threadIdx.x;
    for (int i = tid; i < 128*32; i += 256) Ws[i] = outW[i];
    {
        const float4* src = (const float4*)(g_hist + (size_t)r0*HH);
        float4* dst = (float4*)As;
        for (int i = tid; i < 64*128/4; i += 256) dst[i] = src[i];
    }
    __syncthreads();

    #pragma unroll
    for (int it = 0; it < 2; it++){
        int item = tid + it*256;
        int rl = item >> 3;
        int cg = (item & 7)*4;
        float a0 = outb[cg], a1 = outb[cg+1], a2 = outb[cg+2], a3 = outb[cg+3];
        const float* Ar = As + rl*128;
        #pragma unroll 8
        for (int k = 0; k < 128; k++){
            float av = Ar[k];
            const float* wr = Ws + k*32 + cg;
            a0 += av*wr[0]; a1 += av*wr[1]; a2 += av*wr[2]; a3 += av*wr[3];
        }
        int r = r0 + rl;
        int t = r >> 13;
        int rb = r & 8191;
        int b = rb >> 10, c = rb & 1023;
        float4 v;
        if (g_mask[c])
            v = *(const float4*)(in + (((size_t)(b*TT + t + 5)*CC + c)*160) + cg);
        else
            v = make_float4(a0, a1, a2, a3);
        *(float4*)(out + (((size_t)(b*SS + t)*CC + c)*DST) + cg) = v;
    }
}

// ---------------- host orchestration ----------------
static __nv_bfloat16* symb(const void* s){ void* p = nullptr; cudaGetSymbolAddress(&p, s); return (__nv_bfloat16*)p; }

extern "C" void kernel_launch(void* const* d_in, const int* in_sizes, int n_in,
                              void* d_out, int out_size)
{
    const float* inputs   = (const float*)d_in[0];
    const float* adj      = (const float*)d_in[1];
    const float* init_W   = (const float*)d_in[2];
    const float* init_b   = (const float*)d_in[3];
    const float* fe_fwd_W = (const float*)d_in[4];
    const float* fe_fwd_b = (const float*)d_in[5];
    const float* fe_bwd_W = (const float*)d_in[6];
    const float* fe_bwd_b = (const float*)d_in[7];
    const float* fwd_W    = (const float*)d_in[8];
    const float* fwd_b    = (const float*)d_in[9];
    const float* bwd_W    = (const float*)d_in[10];
    const float* bwd_b    = (const float*)d_in[11];
    const float* merge_W  = (const float*)d_in[12];
    const float* merge_b  = (const float*)d_in[13];
    const float* gru_Wih  = (const float*)d_in[14];
    const float* gru_bih  = (const float*)d_in[15];
    const float* gru_Whh  = (const float*)d_in[16];
    const float* gru_bhh  = (const float*)d_in[17];
    const float* out_W    = (const float*)d_in[18];
    const float* out_b    = (const float*)d_in[19];
    const int*   cells    = (const int*)  d_in[20];
    float* out = (float*)d_out;

    cudaFuncSetAttribute(propx_kernel, cudaFuncAttributeMaxDynamicSharedMemorySize, PX_SMEM);
    cudaFuncSetAttribute(proph_kernel, cudaFuncAttributeMaxDynamicSharedMemorySize, PH_SMEM);
    cudaFuncSetAttribute(sgemm_kernel, cudaFuncAttributeMaxDynamicSharedMemorySize, SG_SMEM);

    // ---- prolog ----
    rowsum_kernel<<<TT*CC/8, 256>>>(adj);
    colsum_kernel<<<dim3(4, TT), 256>>>(adj);
    build_L_kernel<<<dim3(CC/32, CC/32, TT), dim3(32, 8)>>>(adj);
    build_BX_kernel<<<dim3(CC/32, FIN/32, BB*TT), dim3(32, 8)>>>(inputs);
    mask_init_kernel<<<4, 256>>>();
    int nic = in_sizes[20];
    mask_set_kernel<<<(nic + 255)/256, 256>>>(cells, nic);

    wconv_kernel<<<(128*64 + 255)/256, 256>>>(init_W,  symb(g_Winit), 64, 128);
    wconv_kernel<<<(32*64 + 255)/256, 256>>>(fe_fwd_W, symb(g_WfeF),  64, 32);
    wconv_kernel<<<(32*64 + 255)/256, 256>>>(fe_bwd_W, symb(g_WfeB),  64, 32);
    wconv_kernel<<<(128*128 + 255)/256, 256>>>(fwd_W,  symb(g_Wfwd),  128, 128);
    wconv_kernel<<<(128*128 + 255)/256, 256>>>(bwd_W,  symb(g_Wbwd),  128, 128);
    wconv_kernel<<<(128*256 + 255)/256, 256>>>(merge_W,symb(g_Wmerge),256, 128);
    wconv_kernel<<<(384*64 + 255)/256, 256>>>(gru_Wih, symb(g_Wih),   64, 384);
    compose_kernel<<<(384*256 + 255)/256, 256>>>(merge_W, gru_Whh, merge_b, gru_bhh);
    bias_copy_kernel<<<2, 256>>>(init_b, fe_fwd_b, fe_bwd_b, fwd_b, bwd_b, merge_b,
                                 gru_bih);

    // ---- x-dependent precompute ----
    propx_kernel<<<dim3(BB, 8, NT*2), 256, PX_SMEM>>>();
    sgemm_kernel<<<dim3(NT*64, 2), 256, SG_SMEM>>>(10);   // fe fwd+bwd -> tmp
    sgemm_kernel<<<dim3(NT*64, 2), 256, SG_SMEM>>>(12);   // gi
    sgemm_kernel<<<dim3(64, 1), 256, SG_SMEM>>>(14);      // hidden0
    transpose_h_kernel<<<dim3(CC/32, HH/32, BB), dim3(32, 8)>>>();

    // ---- scan: 3 kernels per step ----
    for (int t = 0; t < NT; t++){
        proph_kernel<<<dim3(BB, 32), 256, PH_SMEM>>>(t);  // gcat = relu((L@BH)@W + b)
        sgemm_kernel<<<dim3(64, 4), 256, SG_SMEM>>>(2);   // hs + gh (one launch)
        gru_tr_kernel<<<dim3(32, 4, BB), dim3(32, 8)>>>(t);
    }

    // ---- output ----
    predout_kernel<<<SS*ROWS/64, 256>>>(inputs, out_W, out_b, out);
}

// round 16
// speedup vs baseline: 1.2644x; 1.0447x over previous
#include <cuda_runtime.h>
#include <cuda_bf16.h>
#include <math.h>

#define BB 8
#define TT 32
#define CC 1024
#define HH 128
#define DST 32
#define FIN 64
#define SS 27            // T - INIT_LENGTH - 1
#define NT 31            // scan steps
#define ROWS (BB*CC)     // 8192

// ================= warp-MMA helpers =================
__device__ __forceinline__ unsigned smem_u32(const void* p){
    unsigned a;
    asm("{ .reg .u64 t; cvta.to.shared.u64 t, %1; cvt.u32.u64 %0, t; }" : "=r"(a) : "l"(p));
    return a;
}

__device__ __forceinline__ void ldsm4(unsigned& r0, unsigned& r1, unsigned& r2, unsigned& r3,
                                      unsigned addr){
    asm volatile("ldmatrix.sync.aligned.m8n8.x4.shared.b16 {%0,%1,%2,%3}, [%4];"
                 : "=r"(r0), "=r"(r1), "=r"(r2), "=r"(r3) : "r"(addr));
}

__device__ __forceinline__ void mma16816(float* c, const unsigned* a, unsigned b0, unsigned b1){
    asm volatile("mma.sync.aligned.m16n8k16.row.col.f32.bf16.bf16.f32 "
                 "{%0,%1,%2,%3}, {%4,%5,%6,%7}, {%8,%9}, {%0,%1,%2,%3};"
                 : "+f"(c[0]), "+f"(c[1]), "+f"(c[2]), "+f"(c[3])
                 : "r"(a[0]), "r"(a[1]), "r"(a[2]), "r"(a[3]), "r"(b0), "r"(b1));
}

__device__ __forceinline__ void cp16(unsigned dst, const void* src){
    asm volatile("cp.async.cg.shared.global [%0], [%1], 16;"
                 :: "r"(dst), "l"(__cvta_generic_to_global(src)));
}
#define CP_COMMIT() asm volatile("cp.async.commit_group;" ::: "memory")
#define CP_WAIT0()  asm volatile("cp.async.wait_group 0;" ::: "memory")

__device__ __forceinline__ unsigned swz(unsigned boff){
    return boff ^ ((boff >> 3) & 0x70);
}

// load rows x K bf16 matrix into k-panel smem layout (panel = 64 k, swizzled 128B rows)
template<int RM, int KD>
__device__ __forceinline__ void load_mat(unsigned dst, const __nv_bfloat16* src, int ld, int tid){
    constexpr int UPR = KD/8;
    constexpr int UNITS = RM*UPR;
    for (int u = tid; u < UNITS; u += 256){
        int row = u / UPR, k8 = u % UPR;
        int kp = k8 >> 3, kc8 = k8 & 7;
        cp16(dst + kp*(RM*128) + swz(row*128 + kc8*16),
             src + (size_t)row*ld + kp*64 + kc8*8);
    }
}

// ---------------- device scratch ----------------
__device__ __nv_bfloat16 g_Lf[(size_t)TT*CC*CC];
__device__ __nv_bfloat16 g_Lb[(size_t)TT*CC*CC];
__device__ __nv_bfloat16 g_Xcf[(size_t)BB*TT*CC*FIN];  // [bt][c][f] gathered x, bf16
__device__ __nv_bfloat16 g_BXW[(size_t)BB*TT*64*CC];   // (x@Wfe)^T [bt][n(64)][c]
__device__ __nv_bfloat16 g_BXWi[(size_t)BB*128*CC];    // (x0@Winit)^T [b][n(128)][c]
__device__ __nv_bfloat16 g_BH[(size_t)BB*HH*CC];       // [b][f][c]

__device__ __nv_bfloat16 g_tmp[(size_t)NT*ROWS*64];
__device__ __nv_bfloat16 g_gi_all[(size_t)NT*ROWS*384];
__device__ __nv_bfloat16 g_gcat[(size_t)ROWS*256];
__device__ float         g_hsf[(size_t)ROWS*HH];
__device__ __nv_bfloat16 g_ghb[(size_t)ROWS*384];
__device__ float         g_hist[(size_t)SS*ROWS*HH];
__device__ float         g_h[(size_t)ROWS*HH];
__device__ float         g_dinvf[TT*CC];
__device__ float         g_dinvb[TT*CC];
__device__ int           g_mask[CC];

// weights bf16 [N][K]
__device__ __nv_bfloat16 g_Winit[128*64];
__device__ __nv_bfloat16 g_Wfe2[64*64];      // rows 0..31 = WfeF^T, 32..63 = WfeB^T
__device__ __nv_bfloat16 g_Wfwd[128*128];
__device__ __nv_bfloat16 g_Wbwd[128*128];
__device__ __nv_bfloat16 g_Wmerge[128*256];
__device__ __nv_bfloat16 g_Wmh[384*256];     // (Wmerge @ Whh)^T, bf16 [N][K]
__device__ __nv_bfloat16 g_Wih[384*64];
__device__ float         g_bias2[384];       // bm @ Whh + bhh

#define OFF_INIT  0
#define OFF_FEF   128
#define OFF_FEB   160
#define OFF_FWD   192
#define OFF_BWD   320
#define OFF_MERGE 448
#define OFF_BIH   576
__device__ float g_bias[960];

// ---------------- prolog kernels ----------------
__global__ void zero_sums_kernel(){
    int i = blockIdx.x*blockDim.x + threadIdx.x;
    if (i < TT*CC){ g_dinvf[i] = 0.f; g_dinvb[i] = 0.f; }
}

// one pass over adj: row sums (direct) + col sums (atomics)
__global__ void sums_kernel(const float* __restrict__ adj){
    int t = blockIdx.y;
    int i0 = blockIdx.x*64;
    int tid = threadIdx.x, lane = tid & 31;
    __shared__ float rows[64];
    if (tid < 64) rows[tid] = 0.f;
    __syncthreads();
    const float* base = adj + (size_t)t*CC*CC + (size_t)i0*CC + tid*4;
    float c0 = 0.f, c1 = 0.f, c2 = 0.f, c3 = 0.f;
    for (int r = 0; r < 64; r++){
        float4 v = *(const float4*)(base + (size_t)r*CC);
        c0 += v.x; c1 += v.y; c2 += v.z; c3 += v.w;
        float s = v.x + v.y + v.z + v.w;
        #pragma unroll
        for (int o = 16; o; o >>= 1) s += __shfl_xor_sync(0xffffffffu, s, o);
        if (!lane) atomicAdd(&rows[r], s);
    }
    __syncthreads();
    if (tid < 64) g_dinvf[t*CC + i0 + tid] = rows[tid];
    atomicAdd(&g_dinvb[t*CC + tid*4 + 0], c0);
    atomicAdd(&g_dinvb[t*CC + tid*4 + 1], c1);
    atomicAdd(&g_dinvb[t*CC + tid*4 + 2], c2);
    atomicAdd(&g_dinvb[t*CC + tid*4 + 3], c3);
}

__global__ void rsqrt_kernel(){
    int i = blockIdx.x*blockDim.x + threadIdx.x;
    if (i < TT*CC){
        g_dinvf[i] = 1.0f / sqrtf(g_dinvf[i] + 1.0f);
        g_dinvb[i] = 1.0f / sqrtf(g_dinvb[i] + 1.0f);
    }
}

__global__ void build_L_kernel(const float* __restrict__ adj){
    __shared__ float tile[32][33];
    int t = blockIdx.z;
    int i0 = blockIdx.y*32, j0 = blockIdx.x*32;
    int tx = threadIdx.x, ty = threadIdx.y;
    const float* df = g_dinvf + t*CC;
    const float* db = g_dinvb + t*CC;
    #pragma unroll
    for (int r = 0; r < 4; r++){
        int li = ty + r*8;
        int i = i0 + li, j = j0 + tx;
        float v = adj[((size_t)t*CC + i)*CC + j] + ((i == j) ? 1.f : 0.f);
        g_Lf[((size_t)t*CC + i)*CC + j] = __float2bfloat16(v * df[i] * df[j]);
        tile[li][tx] = v * db[i] * db[j];
    }
    __syncthreads();
    #pragma unroll
    for (int r = 0; r < 4; r++){
        int lj = ty + r*8;
        int p = j0 + lj, q = i0 + tx;
        g_Lb[((size_t)t*CC + p)*CC + q] = __float2bfloat16(tile[tx][lj]);
    }
}

// x_cf[bt][c][f] = bf16(input[bt][c][colmap(f)])
__global__ void xcf_kernel(const float* __restrict__ in){
    size_t idx = (size_t)blockIdx.x*blockDim.x + threadIdx.x;
    if (idx >= (size_t)BB*TT*CC*FIN) return;
    int f = (int)(idx & 63);
    size_t row = idx >> 6;
    int col = (f < 32) ? f : 96 + f;
    g_Xcf[idx] = __float2bfloat16(in[row*160 + col]);
}

__global__ void transpose_h_kernel(){
    __shared__ float tile[32][33];
    int c0 = blockIdx.x*32, f0 = blockIdx.y*32;
    int b = blockIdx.z;
    int tx = threadIdx.x, ty = threadIdx.y;
    #pragma unroll
    for (int r = 0; r < 4; r++){
        int c = c0 + ty + r*8;
        int f = f0 + tx;
        tile[ty + r*8][tx] = g_h[((size_t)b*CC + c)*HH + f];
    }
    __syncthreads();
    #pragma unroll
    for (int r = 0; r < 4; r++){
        int f = f0 + ty + r*8;
        int c = c0 + tx;
        g_BH[((size_t)b*HH + f)*CC + c] = __float2bfloat16(tile[tx][ty + r*8]);
    }
}

__global__ void mask_init_kernel(){
    int i = blockIdx.x*blockDim.x + threadIdx.x;
    if (i < CC) g_mask[i] = 0;
}
__global__ void mask_set_kernel(const int* __restrict__ cells, int n){
    int i = blockIdx.x*blockDim.x + threadIdx.x;
    if (i < n) g_mask[cells[i]] = 1;
}

__global__ void wconv_kernel(const float* __restrict__ W, __nv_bfloat16* w, int K, int N){
    int idx = blockIdx.x*blockDim.x + threadIdx.x;
    if (idx >= N*K) return;
    int n = idx / K, k = idx - n*K;
    w[idx] = __float2bfloat16(W[(size_t)k*N + n]);
}

__global__ void compose_kernel(const float* __restrict__ Wm, const float* __restrict__ Whh,
                               const float* __restrict__ bm, const float* __restrict__ bhh){
    int idx = blockIdx.x*blockDim.x + threadIdx.x;
    if (idx < 384*256){
        int n = idx >> 8, k = idx & 255;
        float s = 0.f;
        #pragma unroll 8
        for (int j = 0; j < 128; j++) s += Wm[k*128 + j]*Whh[(size_t)j*384 + n];
        g_Wmh[(size_t)n*256 + k] = __float2bfloat16(s);
    }
    if (idx < 384){
        float s = bhh[idx];
        for (int j = 0; j < 128; j++) s += bm[j]*Whh[(size_t)j*384 + idx];
        g_bias2[idx] = s;
    }
}

__global__ void bias_copy_kernel(const float* initb, const float* fef, const float* feb,
                                 const float* fwd, const float* bwd, const float* merge,
                                 const float* bih){
    int i = blockIdx.x*blockDim.x + threadIdx.x;
    if (i < 128){
        g_bias[OFF_INIT + i] = initb[i];
        g_bias[OFF_FWD + i]  = fwd[i];
        g_bias[OFF_BWD + i]  = bwd[i];
        g_bias[OFF_MERGE + i]= merge[i];
    }
    if (i < 32){
        g_bias[OFF_FEF + i] = fef[i];
        g_bias[OFF_FEB + i] = feb[i];
    }
    if (i < 384) g_bias[OFF_BIH + i] = bih[i];
}

// ================ xw: BXW[bt][n][c] = (Wfe2 @ Xcf[bt]^T), M=64 N=128c K=64 ================
__global__ void __launch_bounds__(256) xw_kernel(){
    extern __shared__ char smem[];
    unsigned sb = smem_u32(smem);
    int tid = threadIdx.x;
    int c0 = blockIdx.x*128;
    int y = blockIdx.y;            // 0..247
    int b = y / NT, t = y % NT;
    int bt = b*TT + t;

    load_mat<64,64>(sb + 0, g_Wfe2, 64, tid);                                  // A 8KB
    load_mat<128,64>(sb + 8192, g_Xcf + ((size_t)bt*CC + c0)*FIN, FIN, tid);   // B 16KB
    CP_COMMIT(); CP_WAIT0(); __syncthreads();

    int wid = tid >> 5, lane = tid & 31;
    int m0 = (wid & 1)*32;
    int n0 = (wid >> 1)*32;
    int lrow = lane & 7, lq8 = (lane >> 3) & 1, lkhi = lane >> 4;
    int g = lane >> 2, cpair = (lane & 3)*2;

    float acc[2][2][2][4];
    #pragma unroll
    for (int mi=0;mi<2;mi++) for (int nc=0;nc<2;nc++) for (int sq=0;sq<2;sq++)
        for (int q=0;q<4;q++) acc[mi][nc][sq][q] = 0.f;

    #pragma unroll
    for (int kk = 0; kk < 4; kk++){
        unsigned a[2][4];
        #pragma unroll
        for (int mi = 0; mi < 2; mi++){
            unsigned row = m0 + mi*16 + lrow + lq8*8;
            ldsm4(a[mi][0], a[mi][1], a[mi][2], a[mi][3], sb + swz(row*128 + kk*32 + lkhi*16));
        }
        #pragma unroll
        for (int nc = 0; nc < 2; nc++){
            unsigned row = n0 + nc*16 + lrow + lq8*8;
            unsigned bh[4];
            ldsm4(bh[0], bh[1], bh[2], bh[3], sb + 8192 + swz(row*128 + kk*32 + lkhi*16));
            #pragma unroll
            for (int mi = 0; mi < 2; mi++){
                mma16816(acc[mi][nc][0], a[mi], bh[0], bh[2]);
                mma16816(acc[mi][nc][1], a[mi], bh[1], bh[3]);
            }
        }
    }
    #pragma unroll
    for (int mi = 0; mi < 2; mi++){
        int m = m0 + mi*16 + g;
        #pragma unroll
        for (int nc = 0; nc < 2; nc++){
            #pragma unroll
            for (int sq = 0; sq < 2; sq++){
                int col = n0 + nc*16 + sq*8 + cpair;
                float* cc = acc[mi][nc][sq];
                *(__nv_bfloat162*)(g_BXW + ((size_t)bt*64 + m)*CC + c0 + col) =
                    __floats2bfloat162_rn(cc[0], cc[1]);
                *(__nv_bfloat162*)(g_BXW + ((size_t)bt*64 + m + 8)*CC + c0 + col) =
                    __floats2bfloat162_rn(cc[2], cc[3]);
            }
        }
    }
}

// ================ xwinit: BXWi[b][n][c] = Winit @ Xcf[b,0]^T, M=128 N=64c K=64 ========
__global__ void __launch_bounds__(256) xwinit_kernel(){
    extern __shared__ char smem[];
    unsigned sb = smem_u32(smem);
    int tid = threadIdx.x;
    int c0 = blockIdx.x*64;
    int b = blockIdx.y;
    int bt = b*TT;

    load_mat<128,64>(sb + 0, g_Winit, 64, tid);                                 // A 16KB
    load_mat<64,64>(sb + 16384, g_Xcf + ((size_t)bt*CC + c0)*FIN, FIN, tid);    // B 8KB
    CP_COMMIT(); CP_WAIT0(); __syncthreads();

    int wid = tid >> 5, lane = tid & 31;
    int m0 = (wid >> 1)*32;
    int n0 = (wid & 1)*32;
    int lrow = lane & 7, lq8 = (lane >> 3) & 1, lkhi = lane >> 4;
    int g = lane >> 2, cpair = (lane & 3)*2;

    float acc[2][2][2][4];
    #pragma unroll
    for (int mi=0;mi<2;mi++) for (int nc=0;nc<2;nc++) for (int sq=0;sq<2;sq++)
        for (int q=0;q<4;q++) acc[mi][nc][sq][q] = 0.f;

    #pragma unroll
    for (int kk = 0; kk < 4; kk++){
        unsigned a[2][4];
        #pragma unroll
        for (int mi = 0; mi < 2; mi++){
            unsigned row = m0 + mi*16 + lrow + lq8*8;
            ldsm4(a[mi][0], a[mi][1], a[mi][2], a[mi][3], sb + swz(row*128 + kk*32 + lkhi*16));
        }
        #pragma unroll
        for (int nc = 0; nc < 2; nc++){
            unsigned row = n0 + nc*16 + lrow + lq8*8;
            unsigned bh[4];
            ldsm4(bh[0], bh[1], bh[2], bh[3], sb + 16384 + swz(row*128 + kk*32 + lkhi*16));
            #pragma unroll
            for (int mi = 0; mi < 2; mi++){
                mma16816(acc[mi][nc][0], a[mi], bh[0], bh[2]);
                mma16816(acc[mi][nc][1], a[mi], bh[1], bh[3]);
            }
        }
    }
    #pragma unroll
    for (int mi = 0; mi < 2; mi++){
        int m = m0 + mi*16 + g;
        #pragma unroll
        for (int nc = 0; nc < 2; nc++){
            #pragma unroll
            for (int sq = 0; sq < 2; sq++){
                int col = n0 + nc*16 + sq*8 + cpair;
                float* cc = acc[mi][nc][sq];
                *(__nv_bfloat162*)(g_BXWi + ((size_t)b*128 + m)*CC + c0 + col) =
                    __floats2bfloat162_rn(cc[0], cc[1]);
                *(__nv_bfloat162*)(g_BXWi + ((size_t)b*128 + m + 8)*CC + c0 + col) =
                    __floats2bfloat162_rn(cc[2], cc[3]);
            }
        }
    }
}

// ================ tmp_prop: tmp = relu(L @ BXW + bias), M=128 N=32 K=1024 ================
#define TP_BUFSZ (16384 + 4096)
#define TP_SMEM  (2*TP_BUFSZ)

__global__ void __launch_bounds__(256) tmp_prop_kernel(){
    extern __shared__ char smem[];
    unsigned smem_base = smem_u32(smem);
    int tid = threadIdx.x;
    int b = blockIdx.x;
    int mtile = blockIdx.y;
    int t = blockIdx.z >> 1;
    int dir = blockIdx.z & 1;

    const __nv_bfloat16* L = (dir ? g_Lb : g_Lf) + (size_t)t*CC*CC + (size_t)mtile*128*CC;
    const __nv_bfloat16* Bsrc = g_BXW + ((size_t)(b*TT + t)*64 + dir*32)*CC;
    const float* bias = g_bias + (dir ? OFF_FEB : OFF_FEF);
    __nv_bfloat16* Tdst = g_tmp + ((size_t)t*ROWS + b*CC + mtile*128)*64 + dir*32;

    int wid = tid >> 5, lane = tid & 31;
    int m0 = (wid >> 1)*32;
    int n0 = (wid & 1)*16;
    int lrow = lane & 7, lq8 = (lane >> 3) & 1, lkhi = lane >> 4;
    int g = lane >> 2, cpair = (lane & 3)*2;

    float acc[2][2][4];
    #pragma unroll
    for (int mi=0;mi<2;mi++) for (int sq=0;sq<2;sq++)
        for (int q=0;q<4;q++) acc[mi][sq][q] = 0.f;

    {
        #pragma unroll
        for (int it = 0; it < 5; it++){
            int idx = tid + it*256;
            const __nv_bfloat16* src; unsigned sec; int row, col;
            if (idx < 1024){ row = idx >> 3; col = idx & 7; src = L + (size_t)row*CC + col*8; sec = 0; }
            else { int i2 = idx - 1024; row = i2 >> 3; col = i2 & 7; src = Bsrc + (size_t)row*CC + col*8; sec = 16384; }
            cp16(smem_base + sec + swz(row*128 + col*16), src);
        }
        CP_COMMIT();
    }

    for (int s = 0; s < 16; s++){
        int buf = s & 1;
        if (s + 1 < 16){
            int k0 = (s+1)*64;
            unsigned base = smem_base + (buf^1)*TP_BUFSZ;
            #pragma unroll
            for (int it = 0; it < 5; it++){
                int idx = tid + it*256;
                const __nv_bfloat16* src; unsigned sec; int row, col;
                if (idx < 1024){ row = idx >> 3; col = idx & 7; src = L + (size_t)row*CC + k0 + col*8; sec = 0; }
                else { int i2 = idx - 1024; row = i2 >> 3; col = i2 & 7; src = Bsrc + (size_t)row*CC + k0 + col*8; sec = 16384; }
                cp16(base + sec + swz(row*128 + col*16), src);
            }
            CP_COMMIT();
            asm volatile("cp.async.wait_group 1;" ::: "memory");
        } else {
            CP_WAIT0();
        }
        __syncthreads();

        unsigned ab = smem_base + buf*TP_BUFSZ;
        #pragma unroll
        for (int kk = 0; kk < 4; kk++){
            unsigned a[2][4];
            #pragma unroll
            for (int mi = 0; mi < 2; mi++){
                unsigned row = m0 + mi*16 + lrow + lq8*8;
                ldsm4(a[mi][0], a[mi][1], a[mi][2], a[mi][3],
                      ab + swz(row*128 + kk*32 + lkhi*16));
            }
            unsigned row = n0 + lrow + lq8*8;
            unsigned bh[4];
            ldsm4(bh[0], bh[1], bh[2], bh[3], ab + 16384 + swz(row*128 + kk*32 + lkhi*16));
            #pragma unroll
            for (int mi = 0; mi < 2; mi++){
                mma16816(acc[mi][0], a[mi], bh[0], bh[2]);
                mma16816(acc[mi][1], a[mi], bh[1], bh[3]);
            }
        }
        __syncthreads();
    }

    #pragma unroll
    for (int mi = 0; mi < 2; mi++){
        int row = m0 + mi*16 + g;
        #pragma unroll
        for (int sq = 0; sq < 2; sq++){
            int col = n0 + sq*8 + cpair;
            float b0 = bias[col], b1 = bias[col+1];
            float* cc = acc[mi][sq];
            float v00 = fmaxf(cc[0]+b0, 0.f), v01 = fmaxf(cc[1]+b1, 0.f);
            float v10 = fmaxf(cc[2]+b0, 0.f), v11 = fmaxf(cc[3]+b1, 0.f);
            *(__nv_bfloat162*)(Tdst + (size_t)row*64 + col) = __floats2bfloat162_rn(v00, v01);
            *(__nv_bfloat162*)(Tdst + (size_t)(row+8)*64 + col) = __floats2bfloat162_rn(v10, v11);
        }
    }
}

// ================ initprop: h0 = relu(Lf[0] @ BXWi + initb), M=128 N=128 K=1024 ========
#define IP_BUFSZ 32768
#define IP_SMEM  (2*IP_BUFSZ)

__global__ void __launch_bounds__(256) initprop_kernel(){
    extern __shared__ char smem[];
    unsigned smem_base = smem_u32(smem);
    int tid = threadIdx.x;
    int b = blockIdx.y;
    int mtile = blockIdx.x;

    const __nv_bfloat16* L = g_Lf + (size_t)mtile*128*CC;
    const __nv_bfloat16* Bsrc = g_BXWi + (size_t)b*128*CC;
    const float* bias = g_bias + OFF_INIT;
    float* Hdst = g_h + ((size_t)(b*CC + mtile*128))*HH;

    int wid = tid >> 5, lane = tid & 31;
    int m0 = (wid >> 1)*32;
    int n0 = (wid & 1)*64;
    int lrow = lane & 7, lq8 = (lane >> 3) & 1, lkhi = lane >> 4;
    int g = lane >> 2, cpair = (lane & 3)*2;

    float acc[2][4][2][4];
    #pragma unroll
    for (int mi=0;mi<2;mi++) for (int nc=0;nc<4;nc++) for (int sq=0;sq<2;sq++)
        for (int q=0;q<4;q++) acc[mi][nc][sq][q] = 0.f;

    {
        #pragma unroll
        for (int it = 0; it < 8; it++){
            int idx = tid + it*256;
            const __nv_bfloat16* src; unsigned sec; int row, col;
            if (idx < 1024){ row = idx >> 3; col = idx & 7; src = L + (size_t)row*CC + col*8; sec = 0; }
            else { int i2 = idx - 1024; row = i2 >> 3; col = i2 & 7; src = Bsrc + (size_t)row*CC + col*8; sec = 16384; }
            cp16(smem_base + sec + swz(row*128 + col*16), src);
        }
        CP_COMMIT();
    }

    for (int s = 0; s < 16; s++){
        int buf = s & 1;
        if (s + 1 < 16){
            int k0 = (s+1)*64;
            unsigned base = smem_base + (buf^1)*IP_BUFSZ;
            #pragma unroll
            for (int it = 0; it < 8; it++){
                int idx = tid + it*256;
                const __nv_bfloat16* src; unsigned sec; int row, col;
                if (idx < 1024){ row = idx >> 3; col = idx & 7; src = L + (size_t)row*CC + k0 + col*8; sec = 0; }
                else { int i2 = idx - 1024; row = i2 >> 3; col = i2 & 7; src = Bsrc + (size_t)row*CC + k0 + col*8; sec = 16384; }
                cp16(base + sec + swz(row*128 + col*16), src);
            }
            CP_COMMIT();
            asm volatile("cp.async.wait_group 1;" ::: "memory");
        } else {
            CP_WAIT0();
        }
        __syncthreads();

        unsigned ab = smem_base + buf*IP_BUFSZ;
        #pragma unroll
        for (int kk = 0; kk < 4; kk++){
            unsigned a[2][4];
            #pragma unroll
            for (int mi = 0; mi < 2; mi++){
                unsigned row = m0 + mi*16 + lrow + lq8*8;
                ldsm4(a[mi][0], a[mi][1], a[mi][2], a[mi][3],
                      ab + swz(row*128 + kk*32 + lkhi*16));
            }
            #pragma unroll
            for (int nc = 0; nc < 4; nc++){
                unsigned row = n0 + nc*16 + lrow + lq8*8;
                unsigned bh[4];
                ldsm4(bh[0], bh[1], bh[2], bh[3], ab + 16384 + swz(row*128 + kk*32 + lkhi*16));
                #pragma unroll
                for (int mi = 0; mi < 2; mi++){
                    mma16816(acc[mi][nc][0], a[mi], bh[0], bh[2]);
                    mma16816(acc[mi][nc][1], a[mi], bh[1], bh[3]);
                }
            }
        }
        __syncthreads();
    }

    #pragma unroll
    for (int mi = 0; mi < 2; mi++){
        int row = m0 + mi*16 + g;
        #pragma unroll
        for (int nc = 0; nc < 4; nc++){
            #pragma unroll
            for (int sq = 0; sq < 2; sq++){
                int col = n0 + nc*16 + sq*8 + cpair;
                float b0 = bias[col], b1 = bias[col+1];
                float* cc = acc[mi][nc][sq];
                *(float2*)(Hdst + (size_t)row*HH + col) =
                    make_float2(fmaxf(cc[0]+b0, 0.f), fmaxf(cc[1]+b1, 0.f));
                *(float2*)(Hdst + (size_t)(row+8)*HH + col) =
                    make_float2(fmaxf(cc[2]+b0, 0.f), fmaxf(cc[3]+b1, 0.f));
            }
        }
    }
}

// ================ fused h-prop + GCN: gcat = relu((L @ BH) @ W + b) ================
#define PH_BUFSZ 24576
#define PH_W     49152
#define PH_SMEM  81920

__global__ void __launch_bounds__(256, 2) proph_kernel(int t){
    extern __shared__ char smem[];
    unsigned smem_base = smem_u32(smem);
    int tid = threadIdx.x;
    int b = blockIdx.x;
    int mtile = blockIdx.y & 15;
    int dir = blockIdx.y >> 4;

    const __nv_bfloat16* L = (dir ? g_Lb : g_Lf) + (size_t)t*CC*CC + (size_t)mtile*64*CC;
    const __nv_bfloat16* Bsrc = g_BH + (size_t)b*HH*CC;
    const __nv_bfloat16* Wsrc = dir ? g_Wbwd : g_Wfwd;
    const float* bias = g_bias + (dir ? OFF_BWD : OFF_FWD);
    __nv_bfloat16* Gdst = g_gcat + ((size_t)(b*CC + mtile*64))*256 + dir*128;

    int wid = tid >> 5, lane = tid & 31;
    int m0 = (wid & 1)*32;
    int n0 = (wid >> 1)*32;
    int lrow = lane & 7, lq8 = (lane >> 3) & 1, lkhi = lane >> 4;
    int g = lane >> 2, cpair = (lane & 3)*2;

    float acc[2][2][2][4];
    #pragma unroll
    for (int mi = 0; mi < 2; mi++)
        #pragma unroll
        for (int nc = 0; nc < 2; nc++)
            #pragma unroll
            for (int sb = 0; sb < 2; sb++)
                #pragma unroll
                for (int q = 0; q < 4; q++) acc[mi][nc][sb][q] = 0.f;

    {
        load_mat<128,128>(smem_base + PH_W, Wsrc, 128, tid);
        #pragma unroll
        for (int it = 0; it < 6; it++){
            int idx = tid + it*256;
            const __nv_bfloat16* src; unsigned sec; int row, col;
            if (idx < 512){ row = idx >> 3; col = idx & 7; src = L + (size_t)row*CC + col*8; sec = 0; }
            else { int i2 = idx - 512; row = i2 >> 3; col = i2 & 7; src = Bsrc + (size_t)row*CC + col*8; sec = 8192; }
            cp16(smem_base + sec + swz(row*128 + col*16), src);
        }
        CP_COMMIT();
    }

    for (int s = 0; s < 16; s++){
        int buf = s & 1;
        if (s + 1 < 16){
            int k0 = (s+1)*64;
            unsigned base = smem_base + (buf^1)*PH_BUFSZ;
            #pragma unroll
            for (int it = 0; it < 6; it++){
                int idx = tid + it*256;
                const __nv_bfloat16* src; unsigned sec; int row, col;
                if (idx < 512){ row = idx >> 3; col = idx & 7; src = L + (size_t)row*CC + k0 + col*8; sec = 0; }
                else { int i2 = idx - 512; row = i2 >> 3; col = i2 & 7; src = Bsrc + (size_t)row*CC + k0 + col*8; sec = 8192; }
                cp16(base + sec + swz(row*128 + col*16), src);
            }
            CP_COMMIT();
            asm volatile("cp.async.wait_group 1;" ::: "memory");
        } else {
            CP_WAIT0();
        }
        __syncthreads();

        unsigned ab = smem_base + buf*PH_BUFSZ;
        #pragma unroll
        for (int kk = 0; kk < 4; kk++){
            unsigned a[2][4];
            #pragma unroll
            for (int mi = 0; mi < 2; mi++){
                unsigned row = m0 + mi*16 + lrow + lq8*8;
                unsigned sw = swz(row*128 + kk*32 + lkhi*16);
                ldsm4(a[mi][0], a[mi][1], a[mi][2], a[mi][3], ab + sw);
            }
            #pragma unroll
            for (int nc = 0; nc < 2; nc++){
                unsigned row = n0 + nc*16 + lrow + lq8*8;
                unsigned sw = swz(row*128 + kk*32 + lkhi*16);
                unsigned bh[4];
                ldsm4(bh[0], bh[1], bh[2], bh[3], ab + 8192 + sw);
                #pragma unroll
                for (int mi = 0; mi < 2; mi++){
                    mma16816(acc[mi][nc][0], a[mi], bh[0], bh[2]);
                    mma16816(acc[mi][nc][1], a[mi], bh[1], bh[3]);
                }
            }
        }
        __syncthreads();
    }

    // spill Zh (bf16) into buf0 as k-panel
    {
        #pragma unroll
        for (int mi = 0; mi < 2; mi++){
            int row = m0 + mi*16 + g;
            #pragma unroll
            for (int nc = 0; nc < 2; nc++){
                #pragma unroll
                for (int sb = 0; sb < 2; sb++){
                    int col = n0 + nc*16 + sb*8 + cpair;
                    int kp = col >> 6, kc = col & 63;
                    float* cc = acc[mi][nc][sb];
                    *(__nv_bfloat162*)(smem + kp*8192 + swz(row*128 + kc*2)) =
                        __floats2bfloat162_rn(cc[0], cc[1]);
                    *(__nv_bfloat162*)(smem + kp*8192 + swz((row+8)*128 + kc*2)) =
                        __floats2bfloat162_rn(cc[2], cc[3]);
                }
            }
        }
    }
    __syncthreads();

    // second GEMM: gcat_tile = relu(Zh @ W + bias)
    {
        float acc2[2][2][2][4];
        #pragma unroll
        for (int mi=0;mi<2;mi++) for (int nc=0;nc<2;nc++) for (int sb=0;sb<2;sb++)
            for (int q=0;q<4;q++) acc2[mi][nc][sb][q] = 0.f;

        #pragma unroll
        for (int s = 0; s < 2; s++){
            unsigned aP = smem_base + s*8192;
            unsigned wP = smem_base + PH_W + s*16384;
            #pragma unroll
            for (int kk = 0; kk < 4; kk++){
                unsigned a[2][4];
                #pragma unroll
                for (int mi = 0; mi < 2; mi++){
                    unsigned row = m0 + mi*16 + lrow + lq8*8;
                    ldsm4(a[mi][0], a[mi][1], a[mi][2], a[mi][3],
                          aP + swz(row*128 + kk*32 + lkhi*16));
                }
                #pragma unroll
                for (int nc = 0; nc < 2; nc++){
                    unsigned row = n0 + nc*16 + lrow + lq8*8;
                    unsigned bh[4];
                    ldsm4(bh[0], bh[1], bh[2], bh[3], wP + swz(row*128 + kk*32 + lkhi*16));
                    #pragma unroll
                    for (int mi = 0; mi < 2; mi++){
                        mma16816(acc2[mi][nc][0], a[mi], bh[0], bh[2]);
                        mma16816(acc2[mi][nc][1], a[mi], bh[1], bh[3]);
                    }
                }
            }
        }
        #pragma unroll
        for (int mi = 0; mi < 2; mi++){
            int row = m0 + mi*16 + g;
            #pragma unroll
            for (int nc = 0; nc < 2; nc++){
                #pragma unroll
                for (int sb = 0; sb < 2; sb++){
                    int col = n0 + nc*16 + sb*8 + cpair;
                    float b0 = bias[col], b1 = bias[col+1];
                    float* cc = acc2[mi][nc][sb];
                    float v00 = fmaxf(cc[0]+b0, 0.f), v01 = fmaxf(cc[1]+b1, 0.f);
                    float v10 = fmaxf(cc[2]+b0, 0.f), v11 = fmaxf(cc[3]+b1, 0.f);
                    *(__nv_bfloat162*)(Gdst + (size_t)row*256 + col) =
                        __floats2bfloat162_rn(v00, v01);
                    *(__nv_bfloat162*)(Gdst + (size_t)(row+8)*256 + col) =
                        __floats2bfloat162_rn(v10, v11);
                }
            }
        }
    }
}

// ================ generic bf16 HMMA GEMM (task table) ================
// Loop: 2=hs(gcat@Wmerge), 3..5=gh chunks. Precompute: 12/13=gi
#define SG_BUFSZ 40960
#define SG_SMEM  (2*SG_BUFSZ)

__global__ void __launch_bounds__(256) sgemm_kernel(int basecfg){
    int which = basecfg + blockIdx.y;
    const __nv_bfloat16 *A, *W;
    int lda, K, N, ldc, act = 0;
    const float* bias;
    float* Cf = nullptr;
    __nv_bfloat16 *Cbf = nullptr;

    switch (which){
    case 2: A=g_gcat; lda=256; K=256; W=g_Wmerge; N=128; bias=g_bias+OFF_MERGE;
            Cf=g_hsf; ldc=128; break;
    case 3: case 4: case 5: {
        int j = which - 3;
        A=g_gcat; lda=256; K=256; W=g_Wmh + (size_t)j*128*256; N=128;
        bias=g_bias2 + j*128; Cbf=g_ghb + j*128; ldc=384; break; }
    default: {
        int j = which - 12;
        A=g_tmp; lda=64; K=64; W=g_Wih + j*192*64; N=192; bias=g_bias+OFF_BIH+j*192;
        Cbf=g_gi_all + j*192; ldc=384; break; }
    }

    extern __shared__ char smem[];
    unsigned smem_base = smem_u32(smem);
    int tid = threadIdx.x;
    int mtile = blockIdx.x;
    int wid = tid >> 5, lane = tid & 31;
    int m0 = (wid >> 1)*32;
    int Nw = N >> 1;
    int n0 = (wid & 1)*Nw;
    int ncCount = Nw >> 4; if (ncCount < 1) ncCount = 1;
    int lrow = lane & 7, lq8 = (lane >> 3) & 1, lkhi = lane >> 4;
    int nstages = K >> 6;

    float acc[2][6][2][4];
    #pragma unroll
    for (int mi = 0; mi < 2; mi++)
        #pragma unroll
        for (int nc = 0; nc < 6; nc++)
            #pragma unroll
            for (int sb = 0; sb < 2; sb++)
                #pragma unroll
                for (int q = 0; q < 4; q++) acc[mi][nc][sb][q] = 0.f;

    int total = 1024 + N*8;
    for (int idx = tid; idx < total; idx += 256){
        const __nv_bfloat16* src; unsigned sec; int row, col;
        if (idx < 1024){ row = idx >> 3; col = idx & 7;
            src = A + ((size_t)mtile*128 + row)*lda + col*8; sec = 0; }
        else { int i2 = idx - 1024; row = i2 >> 3; col = i2 & 7;
            src = W + (size_t)row*K + col*8; sec = 16384; }
        cp16(smem_base + sec + swz(row*128 + col*16), src);
    }
    CP_COMMIT();

    for (int s = 0; s < nstages; s++){
        int buf = s & 1;
        if (s + 1 < nstages){
            int k0 = (s+1)*64;
            unsigned base = smem_base + (buf^1)*SG_BUFSZ;
            for (int idx = tid; idx < total; idx += 256){
                const __nv_bfloat16* src; unsigned sec; int row, col;
                if (idx < 1024){ row = idx >> 3; col = idx & 7;
                    src = A + ((size_t)mtile*128 + row)*lda + k0 + col*8; sec = 0; }
                else { int i2 = idx - 1024; row = i2 >> 3; col = i2 & 7;
                    src = W + (size_t)row*K + k0 + col*8; sec = 16384; }
                cp16(base + sec + swz(row*128 + col*16), src);
            }
            CP_COMMIT();
            asm volatile("cp.async.wait_group 1;" ::: "memory");
        } else {
            CP_WAIT0();
        }
        __syncthreads();

        unsigned ab = smem_base + buf*SG_BUFSZ;
        #pragma unroll
        for (int kk = 0; kk < 4; kk++){
            unsigned a[2][4];
            #pragma unroll
            for (int mi = 0; mi < 2; mi++){
                unsigned row = m0 + mi*16 + lrow + lq8*8;
                unsigned sw = swz(row*128 + kk*32 + lkhi*16);
                ldsm4(a[mi][0], a[mi][1], a[mi][2], a[mi][3], ab + sw);
            }
            for (int nc = 0; nc < ncCount; nc++){
                unsigned row = n0 + nc*16 + lrow + lq8*8;
                unsigned sw = swz(row*128 + kk*32 + lkhi*16);
                unsigned bh[4];
                ldsm4(bh[0], bh[1], bh[2], bh[3], ab + 16384 + sw);
                #pragma unroll
                for (int mi = 0; mi < 2; mi++){
                    mma16816(acc[mi][nc][0], a[mi], bh[0], bh[2]);
                    mma16816(acc[mi][nc][1], a[mi], bh[1], bh[3]);
                }
            }
        }
        __syncthreads();
    }

    int g = lane >> 2, cpair = (lane & 3)*2;
    #pragma unroll
    for (int mi = 0; mi < 2; mi++){
        int row = mtile*128 + m0 + mi*16 + g;
        for (int nc = 0; nc < ncCount; nc++){
            #pragma unroll
            for (int sb = 0; sb < 2; sb++){
                int col = n0 + nc*16 + sb*8 + cpair;
                float b0 = bias[col], b1 = bias[col+1];
                float* cc = acc[mi][nc][sb];
                float v00 = cc[0] + b0, v01 = cc[1] + b1;
                float v10 = cc[2] + b0, v11 = cc[3] + b1;
                if (act){
                    v00 = fmaxf(v00, 0.f); v01 = fmaxf(v01, 0.f);
                    v10 = fmaxf(v10, 0.f); v11 = fmaxf(v11, 0.f);
                }
                if (Cf){
                    *(float2*)(Cf + (size_t)row*ldc + col)     = make_float2(v00, v01);
                    *(float2*)(Cf + (size_t)(row+8)*ldc + col) = make_float2(v10, v11);
                }
                if (Cbf){
                    *(__nv_bfloat162*)(Cbf + (size_t)row*ldc + col)     = __floats2bfloat162_rn(v00, v01);
                    *(__nv_bfloat162*)(Cbf + (size_t)(row+8)*ldc + col) = __floats2bfloat162_rn(v10, v11);
                }
            }
        }
    }
}

// ---------------- fused GRU gates + h transpose + history ----------------
__global__ void gru_tr_kernel(int t){
    __shared__ float tile[32][33];
    int c0 = blockIdx.x*32, f0 = blockIdx.y*32;
    int b = blockIdx.z;
    int tx = threadIdx.x, ty = threadIdx.y;
    #pragma unroll
    for (int r = 0; r < 4; r++){
        int cl = ty + r*8;
        size_t row = (size_t)b*CC + c0 + cl;
        int f = f0 + tx;
        const __nv_bfloat16* gi = g_gi_all + ((size_t)t*ROWS + row)*384;
        const __nv_bfloat16* gh = g_ghb + row*384;
        float ir = __bfloat162float(gi[f]);
        float iz = __bfloat162float(gi[128 + f]);
        float inn = __bfloat162float(gi[256 + f]);
        float hr = __bfloat162float(gh[f]);
        float hz = __bfloat162float(gh[128 + f]);
        float hn = __bfloat162float(gh[256 + f]);
        float rg = 1.f / (1.f + expf(-(ir + hr)));
        float zg = 1.f / (1.f + expf(-(iz + hz)));
        float ng = tanhf(inn + rg*hn);
        float hs = g_hsf[row*HH + f];
        float h = (1.f - zg)*ng + zg*hs;
        tile[cl][tx] = h;
        if (t >= 4) g_hist[((size_t)(t-4)*ROWS + row)*HH + f] = h;
    }
    __syncthreads();
    #pragma unroll
    for (int r = 0; r < 4; r++){
        int fl = ty + r*8;
        int f = f0 + fl, c = c0 + tx;
        g_BH[((size_t)b*HH + f)*CC + c] = __float2bfloat16(tile[tx][fl]);
    }
}

// ---------------- final: pred = hist @ outW + outb, fused mask-scatter ----------------
__global__ void __launch_bounds__(256) predout_kernel(const float* __restrict__ in,
                                                      const float* __restrict__ outW,
                                                      const float* __restrict__ outb,
                                                      float* __restrict__ out){
    __shared__ float Ws[128*32];
    __shared__ float As[64*128];
    int r0 = blockIdx.x*64;
    int tid = threadIdx.x;
    for (int i = tid; i < 128*32; i += 256) Ws[i] = outW[i];
    {
        const float4* src = (const float4*)(g_hist + (size_t)r0*HH);
        float4* dst = (float4*)As;
        for (int i = tid; i < 64*128/4; i += 256) dst[i] = src[i];
    }
    __syncthreads();

    #pragma unroll
    for (int it = 0; it < 2; it++){
        int item = tid + it*256;
        int rl = item >> 3;
        int cg = (item & 7)*4;
        float a0 = outb[cg], a1 = outb[cg+1], a2 = outb[cg+2], a3 = outb[cg+3];
        const float* Ar = As + rl*128;
        #pragma unroll 8
        for (int k = 0; k < 128; k++){
            float av = Ar[k];
            const float* wr = Ws + k*32 + cg;
            a0 += av*wr[0]; a1 += av*wr[1]; a2 += av*wr[2]; a3 += av*wr[3];
        }
        int r = r0 + rl;
        int t = r >> 13;
        int rb = r & 8191;
        int b = rb >> 10, c = rb & 1023;
        float4 v;
        if (g_mask[c])
            v = *(const float4*)(in + (((size_t)(b*TT + t + 5)*CC + c)*160) + cg);
        else
            v = make_float4(a0, a1, a2, a3);
        *(float4*)(out + (((size_t)(b*SS + t)*CC + c)*DST) + cg) = v;
    }
}

// ---------------- host orchestration ----------------
static __nv_bfloat16* symb(const void* s){ void* p = nullptr; cudaGetSymbolAddress(&p, s); return (__nv_bfloat16*)p; }

extern "C" void kernel_launch(void* const* d_in, const int* in_sizes, int n_in,
                              void* d_out, int out_size)
{
    const float* inputs   = (const float*)d_in[0];
    const float* adj      = (const float*)d_in[1];
    const float* init_W   = (const float*)d_in[2];
    const float* init_b   = (const float*)d_in[3];
    const float* fe_fwd_W = (const float*)d_in[4];
    const float* fe_fwd_b = (const float*)d_in[5];
    const float* fe_bwd_W = (const float*)d_in[6];
    const float* fe_bwd_b = (const float*)d_in[7];
    const float* fwd_W    = (const float*)d_in[8];
    const float* fwd_b    = (const float*)d_in[9];
    const float* bwd_W    = (const float*)d_in[10];
    const float* bwd_b    = (const float*)d_in[11];
    const float* merge_W  = (const float*)d_in[12];
    const float* merge_b  = (const float*)d_in[13];
    const float* gru_Wih  = (const float*)d_in[14];
    const float* gru_bih  = (const float*)d_in[15];
    const float* gru_Whh  = (const float*)d_in[16];
    const float* gru_bhh  = (const float*)d_in[17];
    const float* out_W    = (const float*)d_in[18];
    const float* out_b    = (const float*)d_in[19];
    const int*   cells    = (const int*)  d_in[20];
    float* out = (float*)d_out;

    cudaFuncSetAttribute(tmp_prop_kernel, cudaFuncAttributeMaxDynamicSharedMemorySize, TP_SMEM);
    cudaFuncSetAttribute(initprop_kernel, cudaFuncAttributeMaxDynamicSharedMemorySize, IP_SMEM);
    cudaFuncSetAttribute(proph_kernel, cudaFuncAttributeMaxDynamicSharedMemorySize, PH_SMEM);
    cudaFuncSetAttribute(sgemm_kernel, cudaFuncAttributeMaxDynamicSharedMemorySize, SG_SMEM);
    cudaFuncSetAttribute(xw_kernel,    cudaFuncAttributeMaxDynamicSharedMemorySize, 24576);
    cudaFuncSetAttribute(xwinit_kernel,cudaFuncAttributeMaxDynamicSharedMemorySize, 24576);

    // ---- prolog ----
    zero_sums_kernel<<<(TT*CC + 255)/256, 256>>>();
    sums_kernel<<<dim3(16, TT), 256>>>(adj);
    rsqrt_kernel<<<(TT*CC + 255)/256, 256>>>();
    build_L_kernel<<<dim3(CC/32, CC/32, TT), dim3(32, 8)>>>(adj);
    xcf_kernel<<<(int)(((size_t)BB*TT*CC*FIN + 255)/256), 256>>>(inputs);
    mask_init_kernel<<<4, 256>>>();
    int nic = in_sizes[20];
    mask_set_kernel<<<(nic + 255)/256, 256>>>(cells, nic);

    wconv_kernel<<<(128*64 + 255)/256, 256>>>(init_W,  symb(g_Winit), 64, 128);
    wconv_kernel<<<(32*64 + 255)/256, 256>>>(fe_fwd_W, symb(g_Wfe2),         64, 32);
    wconv_kernel<<<(32*64 + 255)/256, 256>>>(fe_bwd_W, symb(g_Wfe2)+32*64,   64, 32);
    wconv_kernel<<<(128*128 + 255)/256, 256>>>(fwd_W,  symb(g_Wfwd),  128, 128);
    wconv_kernel<<<(128*128 + 255)/256, 256>>>(bwd_W,  symb(g_Wbwd),  128, 128);
    wconv_kernel<<<(128*256 + 255)/256, 256>>>(merge_W,symb(g_Wmerge),256, 128);
    wconv_kernel<<<(384*64 + 255)/256, 256>>>(gru_Wih, symb(g_Wih),   64, 384);
    compose_kernel<<<(384*256 + 255)/256, 256>>>(merge_W, gru_Whh, merge_b, gru_bhh);
    bias_copy_kernel<<<2, 256>>>(init_b, fe_fwd_b, fe_bwd_b, fwd_b, bwd_b, merge_b,
                                 gru_bih);

    // ---- x-dependent precompute ----
    xw_kernel<<<dim3(8, BB*NT), 256, 24576>>>();                    // BXW = (x@Wfe)^T
    xwinit_kernel<<<dim3(16, BB), 256, 24576>>>();                  // BXWi = (x0@Winit)^T
    tmp_prop_kernel<<<dim3(BB, 8, NT*2), 256, TP_SMEM>>>();         // tmp = relu(L@BXW+b)
    sgemm_kernel<<<dim3(NT*64, 2), 256, SG_SMEM>>>(12);             // gi
    initprop_kernel<<<dim3(8, BB), 256, IP_SMEM>>>();               // h0
    transpose_h_kernel<<<dim3(CC/32, HH/32, BB), dim3(32, 8)>>>();

    // ---- scan: 3 kernels per step ----
    for (int t = 0; t < NT; t++){
        proph_kernel<<<dim3(BB, 32), 256, PH_SMEM>>>(t);  // gcat = relu((L@BH)@W + b)
        sgemm_kernel<<<dim3(64, 4), 256, SG_SMEM>>>(2);   // hs + gh (one launch)
        gru_tr_kernel<<<dim3(32, 4, BB), dim3(32, 8)>>>(t);
    }

    // ---- output ----
    predout_kernel<<<SS*ROWS/64, 256>>>(inputs, out_W, out_b, out);
}

// round 17
// speedup vs baseline: 1.2746x; 1.0080x over previous
#include <cuda_runtime.h>
#include <cuda_bf16.h>
#include <math.h>

#define BB 8
#define TT 32
#define CC 1024
#define HH 128
#define DST 32
#define FIN 64
#define SS 27            // T - INIT_LENGTH - 1
#define NT 31            // scan steps
#define ROWS (BB*CC)     // 8192

// ================= warp-MMA helpers =================
__device__ __forceinline__ unsigned smem_u32(const void* p){
    unsigned a;
    asm("{ .reg .u64 t; cvta.to.shared.u64 t, %1; cvt.u32.u64 %0, t; }" : "=r"(a) : "l"(p));
    return a;
}

__device__ __forceinline__ void ldsm4(unsigned& r0, unsigned& r1, unsigned& r2, unsigned& r3,
                                      unsigned addr){
    asm volatile("ldmatrix.sync.aligned.m8n8.x4.shared.b16 {%0,%1,%2,%3}, [%4];"
                 : "=r"(r0), "=r"(r1), "=r"(r2), "=r"(r3) : "r"(addr));
}

__device__ __forceinline__ void mma16816(float* c, const unsigned* a, unsigned b0, unsigned b1){
    asm volatile("mma.sync.aligned.m16n8k16.row.col.f32.bf16.bf16.f32 "
                 "{%0,%1,%2,%3}, {%4,%5,%6,%7}, {%8,%9}, {%0,%1,%2,%3};"
                 : "+f"(c[0]), "+f"(c[1]), "+f"(c[2]), "+f"(c[3])
                 : "r"(a[0]), "r"(a[1]), "r"(a[2]), "r"(a[3]), "r"(b0), "r"(b1));
}

__device__ __forceinline__ void cp16(unsigned dst, const void* src){
    asm volatile("cp.async.cg.shared.global [%0], [%1], 16;"
                 :: "r"(dst), "l"(__cvta_generic_to_global(src)));
}
#define CP_COMMIT() asm volatile("cp.async.commit_group;" ::: "memory")
#define CP_WAIT0()  asm volatile("cp.async.wait_group 0;" ::: "memory")

__device__ __forceinline__ unsigned swz(unsigned boff){
    return boff ^ ((boff >> 3) & 0x70);
}

// load rows x K bf16 matrix into k-panel smem layout (panel = 64 k, swizzled 128B rows)
template<int RM, int KD>
__device__ __forceinline__ void load_mat(unsigned dst, const __nv_bfloat16* src, int ld, int tid){
    constexpr int UPR = KD/8;
    constexpr int UNITS = RM*UPR;
    for (int u = tid; u < UNITS; u += 256){
        int row = u / UPR, k8 = u % UPR;
        int kp = k8 >> 3, kc8 = k8 & 7;
        cp16(dst + kp*(RM*128) + swz(row*128 + kc8*16),
             src + (size_t)row*ld + kp*64 + kc8*8);
    }
}

// ---------------- device scratch ----------------
__device__ __nv_bfloat16 g_Lf[(size_t)TT*CC*CC];
__device__ __nv_bfloat16 g_Lb[(size_t)TT*CC*CC];
__device__ __nv_bfloat16 g_Xcf[(size_t)BB*TT*CC*FIN];  // [bt][c][f] gathered x, bf16
__device__ __nv_bfloat16 g_BXW[(size_t)BB*TT*64*CC];   // (x@Wfe)^T [bt][n(64)][c]
__device__ __nv_bfloat16 g_BXWi[(size_t)BB*128*CC];    // (x0@Winit)^T [b][n(128)][c]
__device__ __nv_bfloat16 g_BH[(size_t)BB*HH*CC];       // [b][f][c]

__device__ __nv_bfloat16 g_tmp[(size_t)NT*ROWS*64];
__device__ __nv_bfloat16 g_gi_all[(size_t)NT*ROWS*384];
__device__ __nv_bfloat16 g_gcat[(size_t)ROWS*256];
__device__ float         g_hsf[(size_t)ROWS*HH];
__device__ __nv_bfloat16 g_ghb[(size_t)ROWS*384];
__device__ float         g_hist[(size_t)SS*ROWS*HH];
__device__ float         g_h[(size_t)ROWS*HH];
__device__ float         g_dinvf[TT*CC];
__device__ float         g_dinvb[TT*CC];
__device__ int           g_mask[CC];

// weights bf16 [N][K]
__device__ __nv_bfloat16 g_Winit[128*64];
__device__ __nv_bfloat16 g_Wfe2[64*64];      // rows 0..31 = WfeF^T, 32..63 = WfeB^T
__device__ __nv_bfloat16 g_Wfwd[128*128];
__device__ __nv_bfloat16 g_Wbwd[128*128];
__device__ __nv_bfloat16 g_Wmerge[128*256];
__device__ __nv_bfloat16 g_Wmh[384*256];     // (Wmerge @ Whh)^T, bf16 [N][K]
__device__ __nv_bfloat16 g_Wih[384*64];
__device__ float         g_bias2[384];       // bm @ Whh + bhh

#define OFF_INIT  0
#define OFF_FEF   128
#define OFF_FEB   160
#define OFF_FWD   192
#define OFF_BWD   320
#define OFF_MERGE 448
#define OFF_BIH   576
__device__ float g_bias[960];

// ---------------- prolog kernels ----------------
__global__ void zero_sums_kernel(){
    int i = blockIdx.x*blockDim.x + threadIdx.x;
    if (i < TT*CC){ g_dinvf[i] = 0.f; g_dinvb[i] = 0.f; }
}

// one pass over adj: row sums (direct) + col sums (atomics)
__global__ void sums_kernel(const float* __restrict__ adj){
    int t = blockIdx.y;
    int i0 = blockIdx.x*64;
    int tid = threadIdx.x, lane = tid & 31;
    __shared__ float rows[64];
    if (tid < 64) rows[tid] = 0.f;
    __syncthreads();
    const float* base = adj + (size_t)t*CC*CC + (size_t)i0*CC + tid*4;
    float c0 = 0.f, c1 = 0.f, c2 = 0.f, c3 = 0.f;
    for (int r = 0; r < 64; r++){
        float4 v = *(const float4*)(base + (size_t)r*CC);
        c0 += v.x; c1 += v.y; c2 += v.z; c3 += v.w;
        float s = v.x + v.y + v.z + v.w;
        #pragma unroll
        for (int o = 16; o; o >>= 1) s += __shfl_xor_sync(0xffffffffu, s, o);
        if (!lane) atomicAdd(&rows[r], s);
    }
    __syncthreads();
    if (tid < 64) g_dinvf[t*CC + i0 + tid] = rows[tid];
    atomicAdd(&g_dinvb[t*CC + tid*4 + 0], c0);
    atomicAdd(&g_dinvb[t*CC + tid*4 + 1], c1);
    atomicAdd(&g_dinvb[t*CC + tid*4 + 2], c2);
    atomicAdd(&g_dinvb[t*CC + tid*4 + 3], c3);
}

__global__ void rsqrt_kernel(){
    int i = blockIdx.x*blockDim.x + threadIdx.x;
    if (i < TT*CC){
        g_dinvf[i] = 1.0f / sqrtf(g_dinvf[i] + 1.0f);
        g_dinvb[i] = 1.0f / sqrtf(g_dinvb[i] + 1.0f);
    }
}

// 64x64 tiles, vectorized: Lf row-major bf162 stores, Lb via smem transpose
__global__ void build_L_kernel(const float* __restrict__ adj){
    __shared__ float tile[64][65];
    int t = blockIdx.z;
    int i0 = blockIdx.y*64, j0 = blockIdx.x*64;
    int tx = threadIdx.x, ty = threadIdx.y;   // (32,8)
    const float* df = g_dinvf + t*CC;
    const float* db = g_dinvb + t*CC;
    int jl = tx*2;
    float dfj0 = df[j0 + jl], dfj1 = df[j0 + jl + 1];
    #pragma unroll
    for (int r = 0; r < 8; r++){
        int il = ty + r*8;
        int i = i0 + il;
        float2 a = *(const float2*)(adj + ((size_t)t*CC + i)*CC + j0 + jl);
        float v0 = a.x + ((i == j0 + jl)     ? 1.f : 0.f);
        float v1 = a.y + ((i == j0 + jl + 1) ? 1.f : 0.f);
        float dfi = df[i];
        *(__nv_bfloat162*)(g_Lf + ((size_t)t*CC + i)*CC + j0 + jl) =
            __floats2bfloat162_rn(v0*dfi*dfj0, v1*dfi*dfj1);
        tile[il][jl] = v0;
        tile[il][jl + 1] = v1;
    }
    __syncthreads();
    int ql = tx*2;
    float dbq0 = db[i0 + ql], dbq1 = db[i0 + ql + 1];
    #pragma unroll
    for (int r = 0; r < 8; r++){
        int pl = ty + r*8;
        int p = j0 + pl;
        float dbp = db[p];
        float v0 = tile[ql][pl], v1 = tile[ql + 1][pl];
        *(__nv_bfloat162*)(g_Lb + ((size_t)t*CC + p)*CC + i0 + ql) =
            __floats2bfloat162_rn(v0*dbp*dbq0, v1*dbp*dbq1);
    }
}

// x_cf[bt][c][f] = bf16(input[bt][c][colmap(f)])
__global__ void xcf_kernel(const float* __restrict__ in){
    size_t idx = (size_t)blockIdx.x*blockDim.x + threadIdx.x;
    if (idx >= (size_t)BB*TT*CC*FIN) return;
    int f = (int)(idx & 63);
    size_t row = idx >> 6;
    int col = (f < 32) ? f : 96 + f;
    g_Xcf[idx] = __float2bfloat16(in[row*160 + col]);
}

__global__ void transpose_h_kernel(){
    __shared__ float tile[32][33];
    int c0 = blockIdx.x*32, f0 = blockIdx.y*32;
    int b = blockIdx.z;
    int tx = threadIdx.x, ty = threadIdx.y;
    #pragma unroll
    for (int r = 0; r < 4; r++){
        int c = c0 + ty + r*8;
        int f = f0 + tx;
        tile[ty + r*8][tx] = g_h[((size_t)b*CC + c)*HH + f];
    }
    __syncthreads();
    #pragma unroll
    for (int r = 0; r < 4; r++){
        int f = f0 + ty + r*8;
        int c = c0 + tx;
        g_BH[((size_t)b*HH + f)*CC + c] = __float2bfloat16(tile[tx][ty + r*8]);
    }
}

__global__ void mask_init_kernel(){
    int i = blockIdx.x*blockDim.x + threadIdx.x;
    if (i < CC) g_mask[i] = 0;
}
__global__ void mask_set_kernel(const int* __restrict__ cells, int n){
    int i = blockIdx.x*blockDim.x + threadIdx.x;
    if (i < n) g_mask[cells[i]] = 1;
}

__global__ void wconv_kernel(const float* __restrict__ W, __nv_bfloat16* w, int K, int N){
    int idx = blockIdx.x*blockDim.x + threadIdx.x;
    if (idx >= N*K) return;
    int n = idx / K, k = idx - n*K;
    w[idx] = __float2bfloat16(W[(size_t)k*N + n]);
}

__global__ void compose_kernel(const float* __restrict__ Wm, const float* __restrict__ Whh,
                               const float* __restrict__ bm, const float* __restrict__ bhh){
    int idx = blockIdx.x*blockDim.x + threadIdx.x;
    if (idx < 384*256){
        int n = idx >> 8, k = idx & 255;
        float s = 0.f;
        #pragma unroll 8
        for (int j = 0; j < 128; j++) s += Wm[k*128 + j]*Whh[(size_t)j*384 + n];
        g_Wmh[(size_t)n*256 + k] = __float2bfloat16(s);
    }
    if (idx < 384){
        float s = bhh[idx];
        for (int j = 0; j < 128; j++) s += bm[j]*Whh[(size_t)j*384 + idx];
        g_bias2[idx] = s;
    }
}

__global__ void bias_copy_kernel(const float* initb, const float* fef, const float* feb,
                                 const float* fwd, const float* bwd, const float* merge,
                                 const float* bih){
    int i = blockIdx.x*blockDim.x + threadIdx.x;
    if (i < 128){
        g_bias[OFF_INIT + i] = initb[i];
        g_bias[OFF_FWD + i]  = fwd[i];
        g_bias[OFF_BWD + i]  = bwd[i];
        g_bias[OFF_MERGE + i]= merge[i];
    }
    if (i < 32){
        g_bias[OFF_FEF + i] = fef[i];
        g_bias[OFF_FEB + i] = feb[i];
    }
    if (i < 384) g_bias[OFF_BIH + i] = bih[i];
}

// ================ xw: BXW[bt][n][c] = (Wfe2 @ Xcf[bt]^T), M=64 N=128c K=64 ================
__global__ void __launch_bounds__(256) xw_kernel(){
    extern __shared__ char smem[];
    unsigned sb = smem_u32(smem);
    int tid = threadIdx.x;
    int c0 = blockIdx.x*128;
    int y = blockIdx.y;
    int b = y / NT, t = y % NT;
    int bt = b*TT + t;

    load_mat<64,64>(sb + 0, g_Wfe2, 64, tid);
    load_mat<128,64>(sb + 8192, g_Xcf + ((size_t)bt*CC + c0)*FIN, FIN, tid);
    CP_COMMIT(); CP_WAIT0(); __syncthreads();

    int wid = tid >> 5, lane = tid & 31;
    int m0 = (wid & 1)*32;
    int n0 = (wid >> 1)*32;
    int lrow = lane & 7, lq8 = (lane >> 3) & 1, lkhi = lane >> 4;
    int g = lane >> 2, cpair = (lane & 3)*2;

    float acc[2][2][2][4];
    #pragma unroll
    for (int mi=0;mi<2;mi++) for (int nc=0;nc<2;nc++) for (int sq=0;sq<2;sq++)
        for (int q=0;q<4;q++) acc[mi][nc][sq][q] = 0.f;

    #pragma unroll
    for (int kk = 0; kk < 4; kk++){
        unsigned a[2][4];
        #pragma unroll
        for (int mi = 0; mi < 2; mi++){
            unsigned row = m0 + mi*16 + lrow + lq8*8;
            ldsm4(a[mi][0], a[mi][1], a[mi][2], a[mi][3], sb + swz(row*128 + kk*32 + lkhi*16));
        }
        #pragma unroll
        for (int nc = 0; nc < 2; nc++){
            unsigned row = n0 + nc*16 + lrow + lq8*8;
            unsigned bh[4];
            ldsm4(bh[0], bh[1], bh[2], bh[3], sb + 8192 + swz(row*128 + kk*32 + lkhi*16));
            #pragma unroll
            for (int mi = 0; mi < 2; mi++){
                mma16816(acc[mi][nc][0], a[mi], bh[0], bh[2]);
                mma16816(acc[mi][nc][1], a[mi], bh[1], bh[3]);
            }
        }
    }
    #pragma unroll
    for (int mi = 0; mi < 2; mi++){
        int m = m0 + mi*16 + g;
        #pragma unroll
        for (int nc = 0; nc < 2; nc++){
            #pragma unroll
            for (int sq = 0; sq < 2; sq++){
                int col = n0 + nc*16 + sq*8 + cpair;
                float* cc = acc[mi][nc][sq];
                *(__nv_bfloat162*)(g_BXW + ((size_t)bt*64 + m)*CC + c0 + col) =
                    __floats2bfloat162_rn(cc[0], cc[1]);
                *(__nv_bfloat162*)(g_BXW + ((size_t)bt*64 + m + 8)*CC + c0 + col) =
                    __floats2bfloat162_rn(cc[2], cc[3]);
            }
        }
    }
}

// ================ xwinit: BXWi[b][n][c] = Winit @ Xcf[b,0]^T ================
__global__ void __launch_bounds__(256) xwinit_kernel(){
    extern __shared__ char smem[];
    unsigned sb = smem_u32(smem);
    int tid = threadIdx.x;
    int c0 = blockIdx.x*64;
    int b = blockIdx.y;
    int bt = b*TT;

    load_mat<128,64>(sb + 0, g_Winit, 64, tid);
    load_mat<64,64>(sb + 16384, g_Xcf + ((size_t)bt*CC + c0)*FIN, FIN, tid);
    CP_COMMIT(); CP_WAIT0(); __syncthreads();

    int wid = tid >> 5, lane = tid & 31;
    int m0 = (wid >> 1)*32;
    int n0 = (wid & 1)*32;
    int lrow = lane & 7, lq8 = (lane >> 3) & 1, lkhi = lane >> 4;
    int g = lane >> 2, cpair = (lane & 3)*2;

    float acc[2][2][2][4];
    #pragma unroll
    for (int mi=0;mi<2;mi++) for (int nc=0;nc<2;nc++) for (int sq=0;sq<2;sq++)
        for (int q=0;q<4;q++) acc[mi][nc][sq][q] = 0.f;

    #pragma unroll
    for (int kk = 0; kk < 4; kk++){
        unsigned a[2][4];
        #pragma unroll
        for (int mi = 0; mi < 2; mi++){
            unsigned row = m0 + mi*16 + lrow + lq8*8;
            ldsm4(a[mi][0], a[mi][1], a[mi][2], a[mi][3], sb + swz(row*128 + kk*32 + lkhi*16));
        }
        #pragma unroll
        for (int nc = 0; nc < 2; nc++){
            unsigned row = n0 + nc*16 + lrow + lq8*8;
            unsigned bh[4];
            ldsm4(bh[0], bh[1], bh[2], bh[3], sb + 16384 + swz(row*128 + kk*32 + lkhi*16));
            #pragma unroll
            for (int mi = 0; mi < 2; mi++){
                mma16816(acc[mi][nc][0], a[mi], bh[0], bh[2]);
                mma16816(acc[mi][nc][1], a[mi], bh[1], bh[3]);
            }
        }
    }
    #pragma unroll
    for (int mi = 0; mi < 2; mi++){
        int m = m0 + mi*16 + g;
        #pragma unroll
        for (int nc = 0; nc < 2; nc++){
            #pragma unroll
            for (int sq = 0; sq < 2; sq++){
                int col = n0 + nc*16 + sq*8 + cpair;
                float* cc = acc[mi][nc][sq];
                *(__nv_bfloat162*)(g_BXWi + ((size_t)b*128 + m)*CC + c0 + col) =
                    __floats2bfloat162_rn(cc[0], cc[1]);
                *(__nv_bfloat162*)(g_BXWi + ((size_t)b*128 + m + 8)*CC + c0 + col) =
                    __floats2bfloat162_rn(cc[2], cc[3]);
            }
        }
    }
}

// ================ tmp_prop: tmp = relu(L @ BXW + bias), M=128 N=32 K=1024 ================
#define TP_BUFSZ (16384 + 4096)
#define TP_SMEM  (2*TP_BUFSZ)

__global__ void __launch_bounds__(256) tmp_prop_kernel(){
    extern __shared__ char smem[];
    unsigned smem_base = smem_u32(smem);
    int tid = threadIdx.x;
    int b = blockIdx.x;
    int mtile = blockIdx.y;
    int t = blockIdx.z >> 1;
    int dir = blockIdx.z & 1;

    const __nv_bfloat16* L = (dir ? g_Lb : g_Lf) + (size_t)t*CC*CC + (size_t)mtile*128*CC;
    const __nv_bfloat16* Bsrc = g_BXW + ((size_t)(b*TT + t)*64 + dir*32)*CC;
    const float* bias = g_bias + (dir ? OFF_FEB : OFF_FEF);
    __nv_bfloat16* Tdst = g_tmp + ((size_t)t*ROWS + b*CC + mtile*128)*64 + dir*32;

    int wid = tid >> 5, lane = tid & 31;
    int m0 = (wid >> 1)*32;
    int n0 = (wid & 1)*16;
    int lrow = lane & 7, lq8 = (lane >> 3) & 1, lkhi = lane >> 4;
    int g = lane >> 2, cpair = (lane & 3)*2;

    float acc[2][2][4];
    #pragma unroll
    for (int mi=0;mi<2;mi++) for (int sq=0;sq<2;sq++)
        for (int q=0;q<4;q++) acc[mi][sq][q] = 0.f;

    {
        #pragma unroll
        for (int it = 0; it < 5; it++){
            int idx = tid + it*256;
            const __nv_bfloat16* src; unsigned sec; int row, col;
            if (idx < 1024){ row = idx >> 3; col = idx & 7; src = L + (size_t)row*CC + col*8; sec = 0; }
            else { int i2 = idx - 1024; row = i2 >> 3; col = i2 & 7; src = Bsrc + (size_t)row*CC + col*8; sec = 16384; }
            cp16(smem_base + sec + swz(row*128 + col*16), src);
        }
        CP_COMMIT();
    }

    for (int s = 0; s < 16; s++){
        int buf = s & 1;
        if (s + 1 < 16){
            int k0 = (s+1)*64;
            unsigned base = smem_base + (buf^1)*TP_BUFSZ;
            #pragma unroll
            for (int it = 0; it < 5; it++){
                int idx = tid + it*256;
                const __nv_bfloat16* src; unsigned sec; int row, col;
                if (idx < 1024){ row = idx >> 3; col = idx & 7; src = L + (size_t)row*CC + k0 + col*8; sec = 0; }
                else { int i2 = idx - 1024; row = i2 >> 3; col = i2 & 7; src = Bsrc + (size_t)row*CC + k0 + col*8; sec = 16384; }
                cp16(base + sec + swz(row*128 + col*16), src);
            }
            CP_COMMIT();
            asm volatile("cp.async.wait_group 1;" ::: "memory");
        } else {
            CP_WAIT0();
        }
        __syncthreads();

        unsigned ab = smem_base + buf*TP_BUFSZ;
        #pragma unroll
        for (int kk = 0; kk < 4; kk++){
            unsigned a[2][4];
            #pragma unroll
            for (int mi = 0; mi < 2; mi++){
                unsigned row = m0 + mi*16 + lrow + lq8*8;
                ldsm4(a[mi][0], a[mi][1], a[mi][2], a[mi][3],
                      ab + swz(row*128 + kk*32 + lkhi*16));
            }
            unsigned row = n0 + lrow + lq8*8;
            unsigned bh[4];
            ldsm4(bh[0], bh[1], bh[2], bh[3], ab + 16384 + swz(row*128 + kk*32 + lkhi*16));
            #pragma unroll
            for (int mi = 0; mi < 2; mi++){
                mma16816(acc[mi][0], a[mi], bh[0], bh[2]);
                mma16816(acc[mi][1], a[mi], bh[1], bh[3]);
            }
        }
        __syncthreads();
    }

    #pragma unroll
    for (int mi = 0; mi < 2; mi++){
        int row = m0 + mi*16 + g;
        #pragma unroll
        for (int sq = 0; sq < 2; sq++){
            int col = n0 + sq*8 + cpair;
            float b0 = bias[col], b1 = bias[col+1];
            float* cc = acc[mi][sq];
            float v00 = fmaxf(cc[0]+b0, 0.f), v01 = fmaxf(cc[1]+b1, 0.f);
            float v10 = fmaxf(cc[2]+b0, 0.f), v11 = fmaxf(cc[3]+b1, 0.f);
            *(__nv_bfloat162*)(Tdst + (size_t)row*64 + col) = __floats2bfloat162_rn(v00, v01);
            *(__nv_bfloat162*)(Tdst + (size_t)(row+8)*64 + col) = __floats2bfloat162_rn(v10, v11);
        }
    }
}

// ================ initprop: h0 = relu(Lf[0] @ BXWi + initb) ================
#define IP_BUFSZ 32768
#define IP_SMEM  (2*IP_BUFSZ)

__global__ void __launch_bounds__(256) initprop_kernel(){
    extern __shared__ char smem[];
    unsigned smem_base = smem_u32(smem);
    int tid = threadIdx.x;
    int b = blockIdx.y;
    int mtile = blockIdx.x;

    const __nv_bfloat16* L = g_Lf + (size_t)mtile*128*CC;
    const __nv_bfloat16* Bsrc = g_BXWi + (size_t)b*128*CC;
    const float* bias = g_bias + OFF_INIT;
    float* Hdst = g_h + ((size_t)(b*CC + mtile*128))*HH;

    int wid = tid >> 5, lane = tid & 31;
    int m0 = (wid >> 1)*32;
    int n0 = (wid & 1)*64;
    int lrow = lane & 7, lq8 = (lane >> 3) & 1, lkhi = lane >> 4;
    int g = lane >> 2, cpair = (lane & 3)*2;

    float acc[2][4][2][4];
    #pragma unroll
    for (int mi=0;mi<2;mi++) for (int nc=0;nc<4;nc++) for (int sq=0;sq<2;sq++)
        for (int q=0;q<4;q++) acc[mi][nc][sq][q] = 0.f;

    {
        #pragma unroll
        for (int it = 0; it < 8; it++){
            int idx = tid + it*256;
            const __nv_bfloat16* src; unsigned sec; int row, col;
            if (idx < 1024){ row = idx >> 3; col = idx & 7; src = L + (size_t)row*CC + col*8; sec = 0; }
            else { int i2 = idx - 1024; row = i2 >> 3; col = i2 & 7; src = Bsrc + (size_t)row*CC + col*8; sec = 16384; }
            cp16(smem_base + sec + swz(row*128 + col*16), src);
        }
        CP_COMMIT();
    }

    for (int s = 0; s < 16; s++){
        int buf = s & 1;
        if (s + 1 < 16){
            int k0 = (s+1)*64;
            unsigned base = smem_base + (buf^1)*IP_BUFSZ;
            #pragma unroll
            for (int it = 0; it < 8; it++){
                int idx = tid + it*256;
                const __nv_bfloat16* src; unsigned sec; int row, col;
                if (idx < 1024){ row = idx >> 3; col = idx & 7; src = L + (size_t)row*CC + k0 + col*8; sec = 0; }
                else { int i2 = idx - 1024; row = i2 >> 3; col = i2 & 7; src = Bsrc + (size_t)row*CC + k0 + col*8; sec = 16384; }
                cp16(base + sec + swz(row*128 + col*16), src);
            }
            CP_COMMIT();
            asm volatile("cp.async.wait_group 1;" ::: "memory");
        } else {
            CP_WAIT0();
        }
        __syncthreads();

        unsigned ab = smem_base + buf*IP_BUFSZ;
        #pragma unroll
        for (int kk = 0; kk < 4; kk++){
            unsigned a[2][4];
            #pragma unroll
            for (int mi = 0; mi < 2; mi++){
                unsigned row = m0 + mi*16 + lrow + lq8*8;
                ldsm4(a[mi][0], a[mi][1], a[mi][2], a[mi][3],
                      ab + swz(row*128 + kk*32 + lkhi*16));
            }
            #pragma unroll
            for (int nc = 0; nc < 4; nc++){
                unsigned row = n0 + nc*16 + lrow + lq8*8;
                unsigned bh[4];
                ldsm4(bh[0], bh[1], bh[2], bh[3], ab + 16384 + swz(row*128 + kk*32 + lkhi*16));
                #pragma unroll
                for (int mi = 0; mi < 2; mi++){
                    mma16816(acc[mi][nc][0], a[mi], bh[0], bh[2]);
                    mma16816(acc[mi][nc][1], a[mi], bh[1], bh[3]);
                }
            }
        }
        __syncthreads();
    }

    #pragma unroll
    for (int mi = 0; mi < 2; mi++){
        int row = m0 + mi*16 + g;
        #pragma unroll
        for (int nc = 0; nc < 4; nc++){
            #pragma unroll
            for (int sq = 0; sq < 2; sq++){
                int col = n0 + nc*16 + sq*8 + cpair;
                float b0 = bias[col], b1 = bias[col+1];
                float* cc = acc[mi][nc][sq];
                *(float2*)(Hdst + (size_t)row*HH + col) =
                    make_float2(fmaxf(cc[0]+b0, 0.f), fmaxf(cc[1]+b1, 0.f));
                *(float2*)(Hdst + (size_t)(row+8)*HH + col) =
                    make_float2(fmaxf(cc[2]+b0, 0.f), fmaxf(cc[3]+b1, 0.f));
            }
        }
    }
}

// ================ fused h-prop + GCN (M=128): gcat = relu((L @ BH) @ W + b) ===========
// grid (b=8, y=dir*8+mtile) = (8,16) = 128 CTAs; M=128 L-rows, N=128.
#define PH_BUFSZ 32768
#define PH_W     65536
#define PH_SMEM  98304

__global__ void __launch_bounds__(256) proph_kernel(int t){
    extern __shared__ char smem[];
    unsigned smem_base = smem_u32(smem);
    int tid = threadIdx.x;
    int b = blockIdx.x;
    int mtile = blockIdx.y & 7;
    int dir = blockIdx.y >> 3;

    const __nv_bfloat16* L = (dir ? g_Lb : g_Lf) + (size_t)t*CC*CC + (size_t)mtile*128*CC;
    const __nv_bfloat16* Bsrc = g_BH + (size_t)b*HH*CC;
    const __nv_bfloat16* Wsrc = dir ? g_Wbwd : g_Wfwd;
    const float* bias = g_bias + (dir ? OFF_BWD : OFF_FWD);
    __nv_bfloat16* Gdst = g_gcat + ((size_t)(b*CC + mtile*128))*256 + dir*128;

    int wid = tid >> 5, lane = tid & 31;
    int m0 = (wid >> 1)*32;
    int n0 = (wid & 1)*64;
    int lrow = lane & 7, lq8 = (lane >> 3) & 1, lkhi = lane >> 4;
    int g = lane >> 2, cpair = (lane & 3)*2;

    float acc[2][4][2][4];
    #pragma unroll
    for (int mi = 0; mi < 2; mi++)
        #pragma unroll
        for (int nc = 0; nc < 4; nc++)
            #pragma unroll
            for (int sb = 0; sb < 2; sb++)
                #pragma unroll
                for (int q = 0; q < 4; q++) acc[mi][nc][sb][q] = 0.f;

    // stage 0 + W prefetch (single commit group)
    {
        load_mat<128,128>(smem_base + PH_W, Wsrc, 128, tid);
        #pragma unroll
        for (int it = 0; it < 8; it++){
            int idx = tid + it*256;
            const __nv_bfloat16* src; unsigned sec; int row, col;
            if (idx < 1024){ row = idx >> 3; col = idx & 7; src = L + (size_t)row*CC + col*8; sec = 0; }
            else { int i2 = idx - 1024; row = i2 >> 3; col = i2 & 7; src = Bsrc + (size_t)row*CC + col*8; sec = 16384; }
            cp16(smem_base + sec + swz(row*128 + col*16), src);
        }
        CP_COMMIT();
    }

    for (int s = 0; s < 16; s++){
        int buf = s & 1;
        if (s + 1 < 16){
            int k0 = (s+1)*64;
            unsigned base = smem_base + (buf^1)*PH_BUFSZ;
            #pragma unroll
            for (int it = 0; it < 8; it++){
                int idx = tid + it*256;
                const __nv_bfloat16* src; unsigned sec; int row, col;
                if (idx < 1024){ row = idx >> 3; col = idx & 7; src = L + (size_t)row*CC + k0 + col*8; sec = 0; }
                else { int i2 = idx - 1024; row = i2 >> 3; col = i2 & 7; src = Bsrc + (size_t)row*CC + k0 + col*8; sec = 16384; }
                cp16(base + sec + swz(row*128 + col*16), src);
            }
            CP_COMMIT();
            asm volatile("cp.async.wait_group 1;" ::: "memory");
        } else {
            CP_WAIT0();
        }
        __syncthreads();

        unsigned ab = smem_base + buf*PH_BUFSZ;
        #pragma unroll
        for (int kk = 0; kk < 4; kk++){
            unsigned a[2][4];
            #pragma unroll
            for (int mi = 0; mi < 2; mi++){
                unsigned row = m0 + mi*16 + lrow + lq8*8;
                ldsm4(a[mi][0], a[mi][1], a[mi][2], a[mi][3],
                      ab + swz(row*128 + kk*32 + lkhi*16));
            }
            #pragma unroll
            for (int nc = 0; nc < 4; nc++){
                unsigned row = n0 + nc*16 + lrow + lq8*8;
                unsigned bh[4];
                ldsm4(bh[0], bh[1], bh[2], bh[3], ab + 16384 + swz(row*128 + kk*32 + lkhi*16));
                #pragma unroll
                for (int mi = 0; mi < 2; mi++){
                    mma16816(acc[mi][nc][0], a[mi], bh[0], bh[2]);
                    mma16816(acc[mi][nc][1], a[mi], bh[1], bh[3]);
                }
            }
        }
        __syncthreads();
    }

    // spill Zh (bf16) into buf0 as 2 k-panels of 16KB (128 rows x 64 k)
    {
        #pragma unroll
        for (int mi = 0; mi < 2; mi++){
            int row = m0 + mi*16 + g;
            #pragma unroll
            for (int nc = 0; nc < 4; nc++){
                #pragma unroll
                for (int sb = 0; sb < 2; sb++){
                    int col = n0 + nc*16 + sb*8 + cpair;
                    int kp = col >> 6, kc = col & 63;
                    float* cc = acc[mi][nc][sb];
                    *(__nv_bfloat162*)(smem + kp*16384 + swz(row*128 + kc*2)) =
                        __floats2bfloat162_rn(cc[0], cc[1]);
                    *(__nv_bfloat162*)(smem + kp*16384 + swz((row+8)*128 + kc*2)) =
                        __floats2bfloat162_rn(cc[2], cc[3]);
                }
            }
        }
    }
    __syncthreads();

    // second GEMM: gcat_tile = relu(Zh @ W + bias), M=128 N=128 K=128
    {
        float acc2[2][4][2][4];
        #pragma unroll
        for (int mi=0;mi<2;mi++) for (int nc=0;nc<4;nc++) for (int sb=0;sb<2;sb++)
            for (int q=0;q<4;q++) acc2[mi][nc][sb][q] = 0.f;

        #pragma unroll
        for (int s = 0; s < 2; s++){
            unsigned aP = smem_base + s*16384;
            unsigned wP = smem_base + PH_W + s*16384;
            #pragma unroll
            for (int kk = 0; kk < 4; kk++){
                unsigned a[2][4];
                #pragma unroll
                for (int mi = 0; mi < 2; mi++){
                    unsigned row = m0 + mi*16 + lrow + lq8*8;
                    ldsm4(a[mi][0], a[mi][1], a[mi][2], a[mi][3],
                          aP + swz(row*128 + kk*32 + lkhi*16));
                }
                #pragma unroll
                for (int nc = 0; nc < 4; nc++){
                    unsigned row = n0 + nc*16 + lrow + lq8*8;
                    unsigned bh[4];
                    ldsm4(bh[0], bh[1], bh[2], bh[3], wP + swz(row*128 + kk*32 + lkhi*16));
                    #pragma unroll
                    for (int mi = 0; mi < 2; mi++){
                        mma16816(acc2[mi][nc][0], a[mi], bh[0], bh[2]);
                        mma16816(acc2[mi][nc][1], a[mi], bh[1], bh[3]);
                    }
                }
            }
        }
        #pragma unroll
        for (int mi = 0; mi < 2; mi++){
            int row = m0 + mi*16 + g;
            #pragma unroll
            for (int nc = 0; nc < 4; nc++){
                #pragma unroll
                for (int sb = 0; sb < 2; sb++){
                    int col = n0 + nc*16 + sb*8 + cpair;
                    float b0 = bias[col], b1 = bias[col+1];
                    float* cc = acc2[mi][nc][sb];
                    float v00 = fmaxf(cc[0]+b0, 0.f), v01 = fmaxf(cc[1]+b1, 0.f);
                    float v10 = fmaxf(cc[2]+b0, 0.f), v11 = fmaxf(cc[3]+b1, 0.f);
                    *(__nv_bfloat162*)(Gdst + (size_t)row*256 + col) =
                        __floats2bfloat162_rn(v00, v01);
                    *(__nv_bfloat162*)(Gdst + (size_t)(row+8)*256 + col) =
                        __floats2bfloat162_rn(v10, v11);
                }
            }
        }
    }
}

// ================ generic bf16 HMMA GEMM (task table) ================
#define SG_BUFSZ 40960
#define SG_SMEM  (2*SG_BUFSZ)

__global__ void __launch_bounds__(256) sgemm_kernel(int basecfg){
    int which = basecfg + blockIdx.y;
    const __nv_bfloat16 *A, *W;
    int lda, K, N, ldc, act = 0;
    const float* bias;
    float* Cf = nullptr;
    __nv_bfloat16 *Cbf = nullptr;

    switch (which){
    case 2: A=g_gcat; lda=256; K=256; W=g_Wmerge; N=128; bias=g_bias+OFF_MERGE;
            Cf=g_hsf; ldc=128; break;
    case 3: case 4: case 5: {
        int j = which - 3;
        A=g_gcat; lda=256; K=256; W=g_Wmh + (size_t)j*128*256; N=128;
        bias=g_bias2 + j*128; Cbf=g_ghb + j*128; ldc=384; break; }
    default: {
        int j = which - 12;
        A=g_tmp; lda=64; K=64; W=g_Wih + j*192*64; N=192; bias=g_bias+OFF_BIH+j*192;
        Cbf=g_gi_all + j*192; ldc=384; break; }
    }

    extern __shared__ char smem[];
    unsigned smem_base = smem_u32(smem);
    int tid = threadIdx.x;
    int mtile = blockIdx.x;
    int wid = tid >> 5, lane = tid & 31;
    int m0 = (wid >> 1)*32;
    int Nw = N >> 1;
    int n0 = (wid & 1)*Nw;
    int ncCount = Nw >> 4; if (ncCount < 1) ncCount = 1;
    int lrow = lane & 7, lq8 = (lane >> 3) & 1, lkhi = lane >> 4;
    int nstages = K >> 6;

    float acc[2][6][2][4];
    #pragma unroll
    for (int mi = 0; mi < 2; mi++)
        #pragma unroll
        for (int nc = 0; nc < 6; nc++)
            #pragma unroll
            for (int sb = 0; sb < 2; sb++)
                #pragma unroll
                for (int q = 0; q < 4; q++) acc[mi][nc][sb][q] = 0.f;

    int total = 1024 + N*8;
    for (int idx = tid; idx < total; idx += 256){
        const __nv_bfloat16* src; unsigned sec; int row, col;
        if (idx < 1024){ row = idx >> 3; col = idx & 7;
            src = A + ((size_t)mtile*128 + row)*lda + col*8; sec = 0; }
        else { int i2 = idx - 1024; row = i2 >> 3; col = i2 & 7;
            src = W + (size_t)row*K + col*8; sec = 16384; }
        cp16(smem_base + sec + swz(row*128 + col*16), src);
    }
    CP_COMMIT();

    for (int s = 0; s < nstages; s++){
        int buf = s & 1;
        if (s + 1 < nstages){
            int k0 = (s+1)*64;
            unsigned base = smem_base + (buf^1)*SG_BUFSZ;
            for (int idx = tid; idx < total; idx += 256){
                const __nv_bfloat16* src; unsigned sec; int row, col;
                if (idx < 1024){ row = idx >> 3; col = idx & 7;
                    src = A + ((size_t)mtile*128 + row)*lda + k0 + col*8; sec = 0; }
                else { int i2 = idx - 1024; row = i2 >> 3; col = i2 & 7;
                    src = W + (size_t)row*K + k0 + col*8; sec = 16384; }
                cp16(base + sec + swz(row*128 + col*16), src);
            }
            CP_COMMIT();
            asm volatile("cp.async.wait_group 1;" ::: "memory");
        } else {
            CP_WAIT0();
        }
        __syncthreads();

        unsigned ab = smem_base + buf*SG_BUFSZ;
        #pragma unroll
        for (int kk = 0; kk < 4; kk++){
            unsigned a[2][4];
            #pragma unroll
            for (int mi = 0; mi < 2; mi++){
                unsigned row = m0 + mi*16 + lrow + lq8*8;
                unsigned sw = swz(row*128 + kk*32 + lkhi*16);
                ldsm4(a[mi][0], a[mi][1], a[mi][2], a[mi][3], ab + sw);
            }
            for (int nc = 0; nc < ncCount; nc++){
                unsigned row = n0 + nc*16 + lrow + lq8*8;
                unsigned sw = swz(row*128 + kk*32 + lkhi*16);
                unsigned bh[4];
                ldsm4(bh[0], bh[1], bh[2], bh[3], ab + 16384 + sw);
                #pragma unroll
                for (int mi = 0; mi < 2; mi++){
                    mma16816(acc[mi][nc][0], a[mi], bh[0], bh[2]);
                    mma16816(acc[mi][nc][1], a[mi], bh[1], bh[3]);
                }
            }
        }
        __syncthreads();
    }

    int g = lane >> 2, cpair = (lane & 3)*2;
    #pragma unroll
    for (int mi = 0; mi < 2; mi++){
        int row = mtile*128 + m0 + mi*16 + g;
        for (int nc = 0; nc < ncCount; nc++){
            #pragma unroll
            for (int sb = 0; sb < 2; sb++){
                int col = n0 + nc*16 + sb*8 + cpair;
                float b0 = bias[col], b1 = bias[col+1];
                float* cc = acc[mi][nc][sb];
                float v00 = cc[0] + b0, v01 = cc[1] + b1;
                float v10 = cc[2] + b0, v11 = cc[3] + b1;
                if (act){
                    v00 = fmaxf(v00, 0.f); v01 = fmaxf(v01, 0.f);
                    v10 = fmaxf(v10, 0.f); v11 = fmaxf(v11, 0.f);
                }
                if (Cf){
                    *(float2*)(Cf + (size_t)row*ldc + col)     = make_float2(v00, v01);
                    *(float2*)(Cf + (size_t)(row+8)*ldc + col) = make_float2(v10, v11);
                }
                if (Cbf){
                    *(__nv_bfloat162*)(Cbf + (size_t)row*ldc + col)     = __floats2bfloat162_rn(v00, v01);
                    *(__nv_bfloat162*)(Cbf + (size_t)(row+8)*ldc + col) = __floats2bfloat162_rn(v10, v11);
                }
            }
        }
    }
}

// ---------------- fused GRU gates + h transpose + history ----------------
__global__ void gru_tr_kernel(int t){
    __shared__ float tile[32][33];
    int c0 = blockIdx.x*32, f0 = blockIdx.y*32;
    int b = blockIdx.z;
    int tx = threadIdx.x, ty = threadIdx.y;
    #pragma unroll
    for (int r = 0; r < 4; r++){
        int cl = ty + r*8;
        size_t row = (size_t)b*CC + c0 + cl;
        int f = f0 + tx;
        const __nv_bfloat16* gi = g_gi_all + ((size_t)t*ROWS + row)*384;
        const __nv_bfloat16* gh = g_ghb + row*384;
        float ir = __bfloat162float(gi[f]);
        float iz = __bfloat162float(gi[128 + f]);
        float inn = __bfloat162float(gi[256 + f]);
        float hr = __bfloat162float(gh[f]);
        float hz = __bfloat162float(gh[128 + f]);
        float hn = __bfloat162float(gh[256 + f]);
        float rg = 1.f / (1.f + expf(-(ir + hr)));
        float zg = 1.f / (1.f + expf(-(iz + hz)));
        float ng = tanhf(inn + rg*hn);
        float hs = g_hsf[row*HH + f];
        float h = (1.f - zg)*ng + zg*hs;
        tile[cl][tx] = h;
        if (t >= 4) g_hist[((size_t)(t-4)*ROWS + row)*HH + f] = h;
    }
    __syncthreads();
    #pragma unroll
    for (int r = 0; r < 4; r++){
        int fl = ty + r*8;
        int f = f0 + fl, c = c0 + tx;
        g_BH[((size_t)b*HH + f)*CC + c] = __float2bfloat16(tile[tx][fl]);
    }
}

// ---------------- final: pred = hist @ outW + outb, fused mask-scatter ----------------
__global__ void __launch_bounds__(256) predout_kernel(const float* __restrict__ in,
                                                      const float* __restrict__ outW,
                                                      const float* __restrict__ outb,
                                                      float* __restrict__ out){
    __shared__ float Ws[128*32];
    __shared__ float As[64*128];
    int r0 = blockIdx.x*64;
    int tid = threadIdx.x;
    for (int i = tid; i < 128*32; i += 256) Ws[i] = outW[i];
    {
        const float4* src = (const float4*)(g_hist + (size_t)r0*HH);
        float4* dst = (float4*)As;
        for (int i = tid; i < 64*128/4; i += 256) dst[i] = src[i];
    }
    __syncthreads();

    #pragma unroll
    for (int it = 0; it < 2; it++){
        int item = tid + it*256;
        int rl = item >> 3;
        int cg = (item & 7)*4;
        float a0 = outb[cg], a1 = outb[cg+1], a2 = outb[cg+2], a3 = outb[cg+3];
        const float* Ar = As + rl*128;
        #pragma unroll 8
        for (int k = 0; k < 128; k++){
            float av = Ar[k];
            const float* wr = Ws + k*32 + cg;
            a0 += av*wr[0]; a1 += av*wr[1]; a2 += av*wr[2]; a3 += av*wr[3];
        }
        int r = r0 + rl;
        int t = r >> 13;
        int rb = r & 8191;
        int b = rb >> 10, c = rb & 1023;
        float4 v;
        if (g_mask[c])
            v = *(const float4*)(in + (((size_t)(b*TT + t + 5)*CC + c)*160) + cg);
        else
            v = make_float4(a0, a1, a2, a3);
        *(float4*)(out + (((size_t)(b*SS + t)*CC + c)*DST) + cg) = v;
    }
}

// ---------------- host orchestration ----------------
static __nv_bfloat16* symb(const void* s){ void* p = nullptr; cudaGetSymbolAddress(&p, s); return (__nv_bfloat16*)p; }

extern "C" void kernel_launch(void* const* d_in, const int* in_sizes, int n_in,
                              void* d_out, int out_size)
{
    const float* inputs   = (const float*)d_in[0];
    const float* adj      = (const float*)d_in[1];
    const float* init_W   = (const float*)d_in[2];
    const float* init_b   = (const float*)d_in[3];
    const float* fe_fwd_W = (const float*)d_in[4];
    const float* fe_fwd_b = (const float*)d_in[5];
    const float* fe_bwd_W = (const float*)d_in[6];
    const float* fe_bwd_b = (const float*)d_in[7];
    const float* fwd_W    = (const float*)d_in[8];
    const float* fwd_b    = (const float*)d_in[9];
    const float* bwd_W    = (const float*)d_in[10];
    const float* bwd_b    = (const float*)d_in[11];
    const float* merge_W  = (const float*)d_in[12];
    const float* merge_b  = (const float*)d_in[13];
    const float* gru_Wih  = (const float*)d_in[14];
    const float* gru_bih  = (const float*)d_in[15];
    const float* gru_Whh  = (const float*)d_in[16];
    const float* gru_bhh  = (const float*)d_in[17];
    const float* out_W    = (const float*)d_in[18];
    const float* out_b    = (const float*)d_in[19];
    const int*   cells    = (const int*)  d_in[20];
    float* out = (float*)d_out;

    cudaFuncSetAttribute(tmp_prop_kernel, cudaFuncAttributeMaxDynamicSharedMemorySize, TP_SMEM);
    cudaFuncSetAttribute(initprop_kernel, cudaFuncAttributeMaxDynamicSharedMemorySize, IP_SMEM);
    cudaFuncSetAttribute(proph_kernel, cudaFuncAttributeMaxDynamicSharedMemorySize, PH_SMEM);
    cudaFuncSetAttribute(sgemm_kernel, cudaFuncAttributeMaxDynamicSharedMemorySize, SG_SMEM);
    cudaFuncSetAttribute(xw_kernel,    cudaFuncAttributeMaxDynamicSharedMemorySize, 24576);
    cudaFuncSetAttribute(xwinit_kernel,cudaFuncAttributeMaxDynamicSharedMemorySize, 24576);

    // ---- prolog ----
    zero_sums_kernel<<<(TT*CC + 255)/256, 256>>>();
    sums_kernel<<<dim3(16, TT), 256>>>(adj);
    rsqrt_kernel<<<(TT*CC + 255)/256, 256>>>();
    build_L_kernel<<<dim3(CC/64, CC/64, TT), dim3(32, 8)>>>(adj);
    xcf_kernel<<<(int)(((size_t)BB*TT*CC*FIN + 255)/256), 256>>>(inputs);
    mask_init_kernel<<<4, 256>>>();
    int nic = in_sizes[20];
    mask_set_kernel<<<(nic + 255)/256, 256>>>(cells, nic);

    wconv_kernel<<<(128*64 + 255)/256, 256>>>(init_W,  symb(g_Winit), 64, 128);
    wconv_kernel<<<(32*64 + 255)/256, 256>>>(fe_fwd_W, symb(g_Wfe2),         64, 32);
    wconv_kernel<<<(32*64 + 255)/256, 256>>>(fe_bwd_W, symb(g_Wfe2)+32*64,   64, 32);
    wconv_kernel<<<(128*128 + 255)/256, 256>>>(fwd_W,  symb(g_Wfwd),  128, 128);
    wconv_kernel<<<(128*128 + 255)/256, 256>>>(bwd_W,  symb(g_Wbwd),  128, 128);
    wconv_kernel<<<(128*256 + 255)/256, 256>>>(merge_W,symb(g_Wmerge),256, 128);
    wconv_kernel<<<(384*64 + 255)/256, 256>>>(gru_Wih, symb(g_Wih),   64, 384);
    compose_kernel<<<(384*256 + 255)/256, 256>>>(merge_W, gru_Whh, merge_b, gru_bhh);
    bias_copy_kernel<<<2, 256>>>(init_b, fe_fwd_b, fe_bwd_b, fwd_b, bwd_b, merge_b,
                                 gru_bih);

    // ---- x-dependent precompute ----
    xw_kernel<<<dim3(8, BB*NT), 256, 24576>>>();
    xwinit_kernel<<<dim3(16, BB), 256, 24576>>>();
    tmp_prop_kernel<<<dim3(BB, 8, NT*2), 256, TP_SMEM>>>();
    sgemm_kernel<<<dim3(NT*64, 2), 256, SG_SMEM>>>(12);
    initprop_kernel<<<dim3(8, BB), 256, IP_SMEM>>>();
    transpose_h_kernel<<<dim3(CC/32, HH/32, BB), dim3(32, 8)>>>();

    // ---- scan: 3 kernels per step ----
    for (int t = 0; t < NT; t++){
        proph_kernel<<<dim3(BB, 16), 256, PH_SMEM>>>(t);  // gcat = relu((L@BH)@W + b)
        sgemm_kernel<<<dim3(64, 4), 256, SG_SMEM>>>(2);   // hs + gh (one launch)
        gru_tr_kernel<<<dim3(32, 4, BB), dim3(32, 8)>>>(t);
    }

    // ---- output ----
    predout_kernel<<<SS*ROWS/64, 256>>>(inputs, out_W, out_b, out);
}